// round 7
// baseline (speedup 1.0000x reference)
#include <cuda_runtime.h>
#include <cuda_bf16.h>
#include <math.h>

// ---------------------------------------------------------------------------
// IGAB block, B=4, C=128, H=W=256, window 8x8, heads=8, head_dim=16, HIDDEN=512
//   k1: LN1 + QKV + gate + window-attention + proj + residual  (FFMA2, as R6)
//   k2: LN2 + W1 + GELU   -> tensor-core bf16 2-term split (3x mma.m16n8k16)
//   k3: depthwise 3x3 + bias + GELU
//   k4: W2 + bias + residual -> tensor-core bf16 2-term split
// ---------------------------------------------------------------------------

#define HW 65536
#define NPLANE 256

__device__ float g_h1[(size_t)4 * 512 * HW];
__device__ float g_h2[(size_t)4 * 512 * HW];

typedef unsigned long long u64;
typedef unsigned int u32;
typedef __nv_bfloat16 bf16;

__device__ __forceinline__ u64 ffma2(u64 a, u64 b, u64 c) {
    u64 d;
    asm("fma.rn.f32x2 %0, %1, %2, %3;" : "=l"(d) : "l"(a), "l"(b), "l"(c));
    return d;
}
__device__ __forceinline__ u64 pack2(float v) {
    u64 d;
    asm("mov.b64 %0, {%1, %1};" : "=l"(d) : "r"(__float_as_uint(v)));
    return d;
}
__device__ __forceinline__ float2 unpack2(u64 v) {
    unsigned lo, hi;
    asm("mov.b64 {%0, %1}, %2;" : "=r"(lo), "=r"(hi) : "l"(v));
    return make_float2(__uint_as_float(lo), __uint_as_float(hi));
}
__device__ __forceinline__ float gelu_exact(float v) {
    return 0.5f * v * (1.0f + erff(v * 0.70710678118654752f));
}
__device__ __forceinline__ void mma16816(float* c, const u32* a, u32 b0, u32 b1) {
    asm volatile(
        "mma.sync.aligned.m16n8k16.row.col.f32.bf16.bf16.f32 "
        "{%0,%1,%2,%3},{%4,%5,%6,%7},{%8,%9},{%0,%1,%2,%3};"
        : "+f"(c[0]), "+f"(c[1]), "+f"(c[2]), "+f"(c[3])
        : "r"(a[0]), "r"(a[1]), "r"(a[2]), "r"(a[3]), "r"(b0), "r"(b1));
}
__device__ __forceinline__ void split_bf16(float v, bf16& h, bf16& l) {
    h = __float2bfloat16(v);
    l = __float2bfloat16(v - __bfloat162float(h));
}

// ======================= kernel 1 (unchanged, FFMA2) =======================
#define OFF_A   0
#define OFF_B   8704
#define OFF_Q   17408
#define OFF_K   26112
#define OFF_V   34816
#define OFF_W   43520
#define OFF_S   51968
#define OFF_L0  56320
#define OFF_MU  56384
#define OFF_RS  56448
#define OFF_DEN 56512
#define SM1_FLOATS 56576
#define SM1_BYTES (SM1_FLOATS * 4)

__global__ __launch_bounds__(256, 1)
void k1_attn(const float* __restrict__ x, const float* __restrict__ l0,
             const float* __restrict__ n1w, const float* __restrict__ n1b,
             const float* __restrict__ qkvw, const float* __restrict__ gw,
             const float* __restrict__ gb, const float* __restrict__ pw,
             const float* __restrict__ pb, float* __restrict__ outp)
{
    extern __shared__ float sm[];
    const int tid = threadIdx.x;
    const int wi = blockIdx.x;
    const int b  = wi >> 10;
    const int hi = (wi >> 5) & 31;
    const int wj = wi & 31;
    const int base_pix = (hi * 8) * NPLANE + wj * 8;
    const float* xb = x + (size_t)b * 128 * HW;

    #pragma unroll
    for (int it = 0; it < 32; ++it) {
        int idx = tid + it * 256;
        int c = idx >> 6, p = idx & 63;
        sm[OFF_A + c * 68 + p] = xb[c * HW + base_pix + (p >> 3) * NPLANE + (p & 7)];
    }
    if (tid < 64) {
        int p = tid;
        sm[OFF_L0 + p] = l0[(size_t)b * HW + base_pix + (p >> 3) * NPLANE + (p & 7)];
    }
    __syncthreads();

    {
        int p = tid >> 2, part = tid & 3;
        float s = 0.f, sq = 0.f;
        #pragma unroll
        for (int c = part * 32; c < part * 32 + 32; ++c) {
            float v = sm[OFF_A + c * 68 + p];
            s += v; sq += v * v;
        }
        s  += __shfl_xor_sync(0xffffffffu, s, 1);
        sq += __shfl_xor_sync(0xffffffffu, sq, 1);
        s  += __shfl_xor_sync(0xffffffffu, s, 2);
        sq += __shfl_xor_sync(0xffffffffu, sq, 2);
        if (part == 0) {
            float mu = s * (1.f / 128.f);
            float var = sq * (1.f / 128.f) - mu * mu;
            sm[OFF_MU + p] = mu;
            sm[OFF_RS + p] = rsqrtf(var + 1e-6f);
        }
    }
    __syncthreads();
    #pragma unroll
    for (int it = 0; it < 32; ++it) {
        int idx = tid + it * 256;
        int c = idx >> 6, p = idx & 63;
        sm[OFF_B + c * 68 + p] =
            n1w[c] * (sm[OFF_A + c * 68 + p] - sm[OFF_MU + p]) * sm[OFF_RS + p] + n1b[c];
    }
    __syncthreads();

    const int tx = tid & 15, ty = tid >> 4;

    for (int ch = 0; ch < 6; ++ch) {
        #pragma unroll
        for (int it = 0; it < 32; ++it) {
            int idx = tid + it * 256;
            int ol = idx >> 7, c = idx & 127;
            sm[OFF_W + ol * 132 + c] = qkvw[(ch * 64 + ol) * 128 + c];
        }
        __syncthreads();
        u64 acc[2][4];
        #pragma unroll
        for (int i = 0; i < 2; ++i)
            #pragma unroll
            for (int j = 0; j < 4; ++j) acc[i][j] = 0ull;
        #pragma unroll 4
        for (int c = 0; c < 128; ++c) {
            ulonglong2 xv = *(const ulonglong2*)&sm[OFF_B + c * 68 + 4 * tx];
            #pragma unroll
            for (int j = 0; j < 4; ++j) {
                u64 wp = pack2(sm[OFF_W + (4 * ty + j) * 132 + c]);
                acc[0][j] = ffma2(xv.x, wp, acc[0][j]);
                acc[1][j] = ffma2(xv.y, wp, acc[1][j]);
            }
        }
        int dst = (ch < 2) ? OFF_Q : (ch < 4) ? OFF_K : OFF_V;
        int rbase = (ch & 1) * 64;
        if (ch < 2) {
            #pragma unroll
            for (int j = 0; j < 4; ++j) {
                int o = rbase + 4 * ty + j;
                float gwv = gw[o], gbv = gb[o];
                float2 f0 = unpack2(acc[0][j]), f1 = unpack2(acc[1][j]);
                float f[4] = {f0.x, f0.y, f1.x, f1.y};
                float4 st;
                float* pst = &st.x;
                #pragma unroll
                for (int i = 0; i < 4; ++i) {
                    int p = 4 * tx + i;
                    float z = sm[OFF_L0 + p] * gwv + gbv;
                    float g = 1.f / (1.f + __expf(-z));
                    pst[i] = f[i] * g;
                }
                *(float4*)&sm[dst + o * 68 + 4 * tx] = st;
            }
        } else {
            #pragma unroll
            for (int j = 0; j < 4; ++j) {
                int o = rbase + 4 * ty + j;
                float2 f0 = unpack2(acc[0][j]), f1 = unpack2(acc[1][j]);
                float4 st = {f0.x, f0.y, f1.x, f1.y};
                *(float4*)&sm[dst + o * 68 + 4 * tx] = st;
            }
        }
        __syncthreads();
    }

    for (int h = 0; h < 8; ++h) {
        const int cb = h * 16;
        {
            u64 acc[2][4];
            #pragma unroll
            for (int i = 0; i < 2; ++i)
                #pragma unroll
                for (int j = 0; j < 4; ++j) acc[i][j] = 0ull;
            #pragma unroll
            for (int d = 0; d < 16; ++d) {
                ulonglong2 qv = *(const ulonglong2*)&sm[OFF_Q + (cb + d) * 68 + 4 * tx];
                #pragma unroll
                for (int j = 0; j < 4; ++j) {
                    u64 kp = pack2(sm[OFF_K + (cb + d) * 68 + 4 * ty + j]);
                    acc[0][j] = ffma2(qv.x, kp, acc[0][j]);
                    acc[1][j] = ffma2(qv.y, kp, acc[1][j]);
                }
            }
            #pragma unroll
            for (int a = 0; a < 2; ++a)
                #pragma unroll
                for (int j = 0; j < 4; ++j) {
                    float2 f = unpack2(acc[a][j]);
                    sm[OFF_S + (4 * tx + 2 * a) * 68 + 4 * ty + j] = f.x * 0.25f;
                    sm[OFF_S + (4 * tx + 2 * a + 1) * 68 + 4 * ty + j] = f.y * 0.25f;
                }
        }
        __syncthreads();
        {
            int r = tid >> 2, part = tid & 3;
            float m = -1e30f;
            #pragma unroll
            for (int kk = part * 16; kk < part * 16 + 16; ++kk)
                m = fmaxf(m, sm[OFF_S + r * 68 + kk]);
            m = fmaxf(m, __shfl_xor_sync(0xffffffffu, m, 1));
            m = fmaxf(m, __shfl_xor_sync(0xffffffffu, m, 2));
            float s = 0.f;
            #pragma unroll
            for (int kk = part * 16; kk < part * 16 + 16; ++kk) {
                float e = __expf(sm[OFF_S + r * 68 + kk] - m);
                sm[OFF_S + r * 68 + kk] = e;
                s += e;
            }
            s += __shfl_xor_sync(0xffffffffu, s, 1);
            s += __shfl_xor_sync(0xffffffffu, s, 2);
            if (part == 0) sm[OFF_DEN + r] = 1.f / s;
        }
        __syncthreads();
        {
            int pq = tid >> 2, dg = tid & 3;
            const u64* Srow = (const u64*)&sm[OFF_S + pq * 68];
            const u64* V0 = (const u64*)&sm[OFF_V + (cb + 4 * dg + 0) * 68];
            const u64* V1 = (const u64*)&sm[OFF_V + (cb + 4 * dg + 1) * 68];
            const u64* V2 = (const u64*)&sm[OFF_V + (cb + 4 * dg + 2) * 68];
            const u64* V3 = (const u64*)&sm[OFF_V + (cb + 4 * dg + 3) * 68];
            u64 a0 = 0ull, a1 = 0ull, a2 = 0ull, a3 = 0ull;
            #pragma unroll 8
            for (int kk = 0; kk < 32; ++kk) {
                u64 prp = Srow[kk];
                a0 = ffma2(prp, V0[kk], a0);
                a1 = ffma2(prp, V1[kk], a1);
                a2 = ffma2(prp, V2[kk], a2);
                a3 = ffma2(prp, V3[kk], a3);
            }
            float dn = sm[OFF_DEN + pq];
            float2 f0 = unpack2(a0), f1 = unpack2(a1), f2 = unpack2(a2), f3 = unpack2(a3);
            sm[OFF_B + (cb + 4 * dg + 0) * 68 + pq] = (f0.x + f0.y) * dn;
            sm[OFF_B + (cb + 4 * dg + 1) * 68 + pq] = (f1.x + f1.y) * dn;
            sm[OFF_B + (cb + 4 * dg + 2) * 68 + pq] = (f2.x + f2.y) * dn;
            sm[OFF_B + (cb + 4 * dg + 3) * 68 + pq] = (f3.x + f3.y) * dn;
        }
        __syncthreads();
    }

    for (int ch = 0; ch < 2; ++ch) {
        #pragma unroll
        for (int it = 0; it < 32; ++it) {
            int idx = tid + it * 256;
            int ol = idx >> 7, c = idx & 127;
            sm[OFF_W + ol * 132 + c] = pw[(ch * 64 + ol) * 128 + c];
        }
        __syncthreads();
        u64 acc[2][4];
        #pragma unroll
        for (int i = 0; i < 2; ++i)
            #pragma unroll
            for (int j = 0; j < 4; ++j) acc[i][j] = 0ull;
        #pragma unroll 4
        for (int c = 0; c < 128; ++c) {
            ulonglong2 xv = *(const ulonglong2*)&sm[OFF_B + c * 68 + 4 * tx];
            #pragma unroll
            for (int j = 0; j < 4; ++j) {
                u64 wp = pack2(sm[OFF_W + (4 * ty + j) * 132 + c]);
                acc[0][j] = ffma2(xv.x, wp, acc[0][j]);
                acc[1][j] = ffma2(xv.y, wp, acc[1][j]);
            }
        }
        #pragma unroll
        for (int j = 0; j < 4; ++j) {
            float2 f0 = unpack2(acc[0][j]), f1 = unpack2(acc[1][j]);
            float4 st = {f0.x, f0.y, f1.x, f1.y};
            *(float4*)&sm[OFF_S + (4 * ty + j) * 68 + 4 * tx] = st;
        }
        __syncthreads();
        #pragma unroll
        for (int it = 0; it < 16; ++it) {
            int idx = tid + it * 256;
            int ol = idx >> 6, p = idx & 63;
            int o = ch * 64 + ol;
            float v = sm[OFF_S + ol * 68 + p] + pb[o] + sm[OFF_A + o * 68 + p];
            outp[(size_t)(b * 128 + o) * HW + base_pix + (p >> 3) * NPLANE + (p & 7)] = v;
        }
        __syncthreads();
    }
}

// ======================= kernel 2: LN2 + W1 + GELU (tensor) ================
// smem: Xf float[128][130] | Xh bf16[128px][130] | Xl | Wh bf16[128o][130] | Wl
//       Cst (float[128][130]) aliases Wh+Wl ; MU/RS at tail
#define SM2_BYTES (199680 + 1024)

__global__ __launch_bounds__(256, 1)
void k2_ffn1(const float* __restrict__ inp, const float* __restrict__ n2w,
             const float* __restrict__ n2b, const float* __restrict__ w1,
             const float* __restrict__ b1)
{
    extern __shared__ char smc[];
    float* Xf = (float*)smc;                       // 128*130 f32
    bf16* Xh = (bf16*)(smc + 66560);
    bf16* Xl = Xh + 128 * 130;
    bf16* Wh = Xl + 128 * 130;
    bf16* Wl = Wh + 128 * 130;
    float* Cst = (float*)Wh;                       // staging after MMA
    float* MU = (float*)(smc + 199680);
    float* RS = MU + 128;

    const int tid = threadIdx.x;
    const int pg = blockIdx.x * 128;
    const int b = pg >> 16;
    const int pix = pg & 65535;
    const float* ib = inp + (size_t)b * 128 * HW + pix;

    #pragma unroll
    for (int it = 0; it < 64; ++it) {
        int idx = tid + it * 256;
        int c = idx >> 7, p = idx & 127;
        Xf[c * 130 + p] = ib[c * HW + p];
    }
    __syncthreads();
    {
        int p = tid >> 1, part = tid & 1;
        float s = 0.f, sq = 0.f;
        #pragma unroll
        for (int c = part * 64; c < part * 64 + 64; ++c) {
            float v = Xf[c * 130 + p];
            s += v; sq += v * v;
        }
        s  += __shfl_xor_sync(0xffffffffu, s, 1);
        sq += __shfl_xor_sync(0xffffffffu, sq, 1);
        if (part == 0) {
            float mu = s * (1.f / 128.f);
            float var = sq * (1.f / 128.f) - mu * mu;
            MU[p] = mu;
            RS[p] = rsqrtf(var + 1e-6f);
        }
    }
    __syncthreads();
    // normalize + split into transposed bf16 [px][c]
    #pragma unroll
    for (int it = 0; it < 64; ++it) {
        int idx = tid + it * 256;
        int c = idx >> 7, p = idx & 127;
        float xn = n2w[c] * (Xf[c * 130 + p] - MU[p]) * RS[p] + n2b[c];
        bf16 h, l;
        split_bf16(xn, h, l);
        Xh[p * 130 + c] = h;
        Xl[p * 130 + c] = l;
    }

    const int lane = tid & 31;
    const int warp = tid >> 5;
    const int g = lane >> 2, tg = lane & 3;
    const int mbase = (warp >> 1) * 32;    // out rows within chunk
    const int nbase = (warp & 1) * 64;     // px cols

    for (int och = 0; och < 4; ++och) {
        __syncthreads();
        // load W chunk as bf16 split, [o][k]
        #pragma unroll
        for (int it = 0; it < 64; ++it) {
            int idx = tid + it * 256;
            int o = idx >> 7, k = idx & 127;
            float v = w1[(och * 128 + o) * 128 + k];
            bf16 h, l;
            split_bf16(v, h, l);
            Wh[o * 130 + k] = h;
            Wl[o * 130 + k] = l;
        }
        __syncthreads();

        float acc[2][8][4];
        #pragma unroll
        for (int mt = 0; mt < 2; ++mt)
            #pragma unroll
            for (int nt = 0; nt < 8; ++nt)
                #pragma unroll
                for (int q = 0; q < 4; ++q) acc[mt][nt][q] = 0.f;

        #pragma unroll 2
        for (int ks = 0; ks < 8; ++ks) {
            int k0 = ks * 16;
            u32 ah[2][4], al[2][4];
            #pragma unroll
            for (int mt = 0; mt < 2; ++mt) {
                int r = mbase + mt * 16 + g;
                ah[mt][0] = *(const u32*)&Wh[r * 130 + k0 + tg * 2];
                ah[mt][1] = *(const u32*)&Wh[(r + 8) * 130 + k0 + tg * 2];
                ah[mt][2] = *(const u32*)&Wh[r * 130 + k0 + 8 + tg * 2];
                ah[mt][3] = *(const u32*)&Wh[(r + 8) * 130 + k0 + 8 + tg * 2];
                al[mt][0] = *(const u32*)&Wl[r * 130 + k0 + tg * 2];
                al[mt][1] = *(const u32*)&Wl[(r + 8) * 130 + k0 + tg * 2];
                al[mt][2] = *(const u32*)&Wl[r * 130 + k0 + 8 + tg * 2];
                al[mt][3] = *(const u32*)&Wl[(r + 8) * 130 + k0 + 8 + tg * 2];
            }
            #pragma unroll
            for (int nt = 0; nt < 8; ++nt) {
                int cc = nbase + nt * 8 + g;
                u32 bh0 = *(const u32*)&Xh[cc * 130 + k0 + tg * 2];
                u32 bh1 = *(const u32*)&Xh[cc * 130 + k0 + 8 + tg * 2];
                u32 bl0 = *(const u32*)&Xl[cc * 130 + k0 + tg * 2];
                u32 bl1 = *(const u32*)&Xl[cc * 130 + k0 + 8 + tg * 2];
                #pragma unroll
                for (int mt = 0; mt < 2; ++mt) {
                    mma16816(acc[mt][nt], ah[mt], bh0, bh1);
                    mma16816(acc[mt][nt], ah[mt], bl0, bl1);
                    mma16816(acc[mt][nt], al[mt], bh0, bh1);
                }
            }
        }
        __syncthreads();   // all warps done reading W before staging overwrites it
        #pragma unroll
        for (int mt = 0; mt < 2; ++mt) {
            #pragma unroll
            for (int nt = 0; nt < 8; ++nt) {
                int r = mbase + mt * 16 + g;
                int cc = nbase + nt * 8 + tg * 2;
                *(float2*)&Cst[r * 130 + cc] = make_float2(acc[mt][nt][0], acc[mt][nt][1]);
                *(float2*)&Cst[(r + 8) * 130 + cc] = make_float2(acc[mt][nt][2], acc[mt][nt][3]);
            }
        }
        __syncthreads();
        #pragma unroll
        for (int it = 0; it < 64; ++it) {
            int idx = tid + it * 256;
            int o = idx >> 7, p = idx & 127;
            float v = Cst[o * 130 + p] + b1[och * 128 + o];
            g_h1[(size_t)(b * 512 + och * 128 + o) * HW + pix + p] = gelu_exact(v);
        }
    }
}

// ======================= kernel 3 (unchanged) ==============================
__global__ __launch_bounds__(256)
void k3_dw(const float* __restrict__ dw, const float* __restrict__ dwb)
{
    __shared__ float tile[10][34];
    const int plane = blockIdx.z;
    const int ch = plane & 511;
    const float* ip = g_h1 + (size_t)plane * HW;
    float* op = g_h2 + (size_t)plane * HW;
    const int x0 = blockIdx.x * 32, y0 = blockIdx.y * 8;
    const int tid = threadIdx.x;

    for (int idx = tid; idx < 340; idx += 256) {
        int ly = idx / 34, lx = idx % 34;
        int gy = y0 + ly - 1, gx = x0 + lx - 1;
        tile[ly][lx] = (gy >= 0 && gy < 256 && gx >= 0 && gx < 256) ? ip[gy * NPLANE + gx] : 0.f;
    }
    __syncthreads();

    const int tx = tid & 31, ty = tid >> 5;
    float w[9];
    #pragma unroll
    for (int i = 0; i < 9; ++i) w[i] = dw[ch * 9 + i];
    float s = dwb[ch];
    #pragma unroll
    for (int dy = 0; dy < 3; ++dy)
        #pragma unroll
        for (int dx = 0; dx < 3; ++dx)
            s += w[dy * 3 + dx] * tile[ty + dy][tx + dx];
    op[(y0 + ty) * NPLANE + x0 + tx] = gelu_exact(s);
}

// ======================= kernel 4: W2 + residual (tensor) ==================
// smem: Xh bf16[128px][130] | Xl | Wh bf16[128o][130] | Wl ; Cst aliases Xh+Xl
#define SM4_BYTES 133120

__global__ __launch_bounds__(256, 1)
void k4_ffn2(const float* __restrict__ w2, const float* __restrict__ b2,
             float* __restrict__ io)
{
    extern __shared__ char smc[];
    bf16* Xh = (bf16*)smc;
    bf16* Xl = Xh + 128 * 130;
    bf16* Wh = Xl + 128 * 130;
    bf16* Wl = Wh + 128 * 130;
    float* Cst = (float*)smc;

    const int tid = threadIdx.x;
    const int pg = blockIdx.x * 128;
    const int b = pg >> 16;
    const int pix = pg & 65535;
    const float* hb = g_h2 + (size_t)b * 512 * HW + pix;

    const int lane = tid & 31;
    const int warp = tid >> 5;
    const int g = lane >> 2, tg = lane & 3;
    const int mbase = (warp >> 1) * 32;
    const int nbase = (warp & 1) * 64;

    float acc[2][8][4];
    #pragma unroll
    for (int mt = 0; mt < 2; ++mt)
        #pragma unroll
        for (int nt = 0; nt < 8; ++nt)
            #pragma unroll
            for (int q = 0; q < 4; ++q) acc[mt][nt][q] = 0.f;

    for (int kc = 0; kc < 4; ++kc) {
        __syncthreads();
        #pragma unroll
        for (int it = 0; it < 64; ++it) {
            int idx = tid + it * 256;
            int k = idx >> 7, p = idx & 127;
            float v = hb[(size_t)(kc * 128 + k) * HW + p];
            bf16 h, l;
            split_bf16(v, h, l);
            Xh[p * 130 + k] = h;      // transpose: [px][k]
            Xl[p * 130 + k] = l;
        }
        #pragma unroll
        for (int it = 0; it < 64; ++it) {
            int idx = tid + it * 256;
            int o = idx >> 7, k = idx & 127;
            float v = w2[o * 512 + kc * 128 + k];
            bf16 h, l;
            split_bf16(v, h, l);
            Wh[o * 130 + k] = h;
            Wl[o * 130 + k] = l;
        }
        __syncthreads();

        #pragma unroll 2
        for (int ks = 0; ks < 8; ++ks) {
            int k0 = ks * 16;
            u32 ah[2][4], al[2][4];
            #pragma unroll
            for (int mt = 0; mt < 2; ++mt) {
                int r = mbase + mt * 16 + g;
                ah[mt][0] = *(const u32*)&Wh[r * 130 + k0 + tg * 2];
                ah[mt][1] = *(const u32*)&Wh[(r + 8) * 130 + k0 + tg * 2];
                ah[mt][2] = *(const u32*)&Wh[r * 130 + k0 + 8 + tg * 2];
                ah[mt][3] = *(const u32*)&Wh[(r + 8) * 130 + k0 + 8 + tg * 2];
                al[mt][0] = *(const u32*)&Wl[r * 130 + k0 + tg * 2];
                al[mt][1] = *(const u32*)&Wl[(r + 8) * 130 + k0 + tg * 2];
                al[mt][2] = *(const u32*)&Wl[r * 130 + k0 + 8 + tg * 2];
                al[mt][3] = *(const u32*)&Wl[(r + 8) * 130 + k0 + 8 + tg * 2];
            }
            #pragma unroll
            for (int nt = 0; nt < 8; ++nt) {
                int cc = nbase + nt * 8 + g;
                u32 bh0 = *(const u32*)&Xh[cc * 130 + k0 + tg * 2];
                u32 bh1 = *(const u32*)&Xh[cc * 130 + k0 + 8 + tg * 2];
                u32 bl0 = *(const u32*)&Xl[cc * 130 + k0 + tg * 2];
                u32 bl1 = *(const u32*)&Xl[cc * 130 + k0 + 8 + tg * 2];
                #pragma unroll
                for (int mt = 0; mt < 2; ++mt) {
                    mma16816(acc[mt][nt], ah[mt], bh0, bh1);
                    mma16816(acc[mt][nt], ah[mt], bl0, bl1);
                    mma16816(acc[mt][nt], al[mt], bh0, bh1);
                }
            }
        }
    }

    __syncthreads();
    #pragma unroll
    for (int mt = 0; mt < 2; ++mt) {
        #pragma unroll
        for (int nt = 0; nt < 8; ++nt) {
            int r = mbase + mt * 16 + g;
            int cc = nbase + nt * 8 + tg * 2;
            *(float2*)&Cst[r * 130 + cc] = make_float2(acc[mt][nt][0], acc[mt][nt][1]);
            *(float2*)&Cst[(r + 8) * 130 + cc] = make_float2(acc[mt][nt][2], acc[mt][nt][3]);
        }
    }
    __syncthreads();
    #pragma unroll
    for (int it = 0; it < 64; ++it) {
        int idx = tid + it * 256;
        int o = idx >> 7, p = idx & 127;
        size_t ad = (size_t)(b * 128 + o) * HW + pix + p;
        io[ad] = io[ad] + Cst[o * 130 + p] + b2[o];
    }
}

// ---------------------------------------------------------------------------
extern "C" void kernel_launch(void* const* d_in, const int* in_sizes, int n_in,
                              void* d_out, int out_size)
{
    const float* x    = (const float*)d_in[0];
    const float* l0   = (const float*)d_in[1];
    const float* n1w  = (const float*)d_in[2];
    const float* n1b  = (const float*)d_in[3];
    const float* n2w  = (const float*)d_in[4];
    const float* n2b  = (const float*)d_in[5];
    const float* qkvw = (const float*)d_in[6];
    const float* gw   = (const float*)d_in[7];
    const float* gb   = (const float*)d_in[8];
    const float* pw   = (const float*)d_in[9];
    const float* pb   = (const float*)d_in[10];
    const float* w1   = (const float*)d_in[11];
    const float* b1   = (const float*)d_in[12];
    const float* dw   = (const float*)d_in[13];
    const float* dwb  = (const float*)d_in[14];
    const float* w2   = (const float*)d_in[15];
    const float* b2   = (const float*)d_in[16];
    float* out = (float*)d_out;

    cudaFuncSetAttribute(k1_attn, cudaFuncAttributeMaxDynamicSharedMemorySize, SM1_BYTES);
    cudaFuncSetAttribute(k2_ffn1, cudaFuncAttributeMaxDynamicSharedMemorySize, SM2_BYTES);
    cudaFuncSetAttribute(k4_ffn2, cudaFuncAttributeMaxDynamicSharedMemorySize, SM4_BYTES);

    k1_attn<<<4096, 256, SM1_BYTES>>>(x, l0, n1w, n1b, qkvw, gw, gb, pw, pb, out);
    k2_ffn1<<<2048, 256, SM2_BYTES>>>(out, n2w, n2b, w1, b1);
    dim3 g3(8, 32, 2048);
    k3_dw<<<g3, 256>>>(dw, dwb);
    k4_ffn2<<<2048, 256, SM4_BYTES>>>(w2, b2, out);
}

// round 8
// speedup vs baseline: 1.1307x; 1.1307x over previous
#include <cuda_runtime.h>
#include <cuda_bf16.h>
#include <math.h>

// ---------------------------------------------------------------------------
// IGAB block, B=4, C=128, H=W=256, window 8x8, heads=8, head_dim=16, HIDDEN=512
//   k0: pre-split w1/w2 into bf16 hi/lo (once per launch)
//   k1: LN1 + QKV + gate + window-attention + proj + residual  (FFMA2)
//   k2: LN2 + W1 + GELU   -> bf16 2-term split MMA, ldmatrix
//   k3: depthwise 3x3 + bias + GELU -> writes bf16 hi/lo planes
//   k4: W2 + bias + residual -> bf16 2-term split MMA, ldmatrix
// ---------------------------------------------------------------------------

#define HW 65536
#define NPLANE 256

__device__ float g_h1[(size_t)4 * 512 * HW];            // fp32 for k3
__device__ __nv_bfloat16 g_h2h[(size_t)4 * 512 * HW];   // split for k4
__device__ __nv_bfloat16 g_h2l[(size_t)4 * 512 * HW];
__device__ __nv_bfloat16 g_w1h[512 * 128], g_w1l[512 * 128];
__device__ __nv_bfloat16 g_w2h[128 * 512], g_w2l[128 * 512];

typedef unsigned long long u64;
typedef unsigned int u32;
typedef __nv_bfloat16 bf16;

__device__ __forceinline__ u64 ffma2(u64 a, u64 b, u64 c) {
    u64 d;
    asm("fma.rn.f32x2 %0, %1, %2, %3;" : "=l"(d) : "l"(a), "l"(b), "l"(c));
    return d;
}
__device__ __forceinline__ u64 pack2(float v) {
    u64 d;
    asm("mov.b64 %0, {%1, %1};" : "=l"(d) : "r"(__float_as_uint(v)));
    return d;
}
__device__ __forceinline__ float2 unpack2(u64 v) {
    unsigned lo, hi;
    asm("mov.b64 {%0, %1}, %2;" : "=r"(lo), "=r"(hi) : "l"(v));
    return make_float2(__uint_as_float(lo), __uint_as_float(hi));
}
__device__ __forceinline__ float gelu_exact(float v) {
    return 0.5f * v * (1.0f + erff(v * 0.70710678118654752f));
}
__device__ __forceinline__ void mma16816(float* c, const u32* a, u32 b0, u32 b1) {
    asm volatile(
        "mma.sync.aligned.m16n8k16.row.col.f32.bf16.bf16.f32 "
        "{%0,%1,%2,%3},{%4,%5,%6,%7},{%8,%9},{%0,%1,%2,%3};"
        : "+f"(c[0]), "+f"(c[1]), "+f"(c[2]), "+f"(c[3])
        : "r"(a[0]), "r"(a[1]), "r"(a[2]), "r"(a[3]), "r"(b0), "r"(b1));
}
__device__ __forceinline__ void ldsm4(u32& d0, u32& d1, u32& d2, u32& d3, u32 a) {
    asm volatile("ldmatrix.sync.aligned.m8n8.x4.shared.b16 {%0,%1,%2,%3},[%4];"
                 : "=r"(d0), "=r"(d1), "=r"(d2), "=r"(d3) : "r"(a));
}
__device__ __forceinline__ void ldsm4t(u32& d0, u32& d1, u32& d2, u32& d3, u32 a) {
    asm volatile("ldmatrix.sync.aligned.m8n8.x4.trans.shared.b16 {%0,%1,%2,%3},[%4];"
                 : "=r"(d0), "=r"(d1), "=r"(d2), "=r"(d3) : "r"(a));
}
__device__ __forceinline__ void split_bf16(float v, bf16& h, bf16& l) {
    h = __float2bfloat16(v);
    l = __float2bfloat16(v - __bfloat162float(h));
}

// ======================= kernel 0: weight pre-split ========================
__global__ __launch_bounds__(256)
void k0_prep(const float* __restrict__ w1, const float* __restrict__ w2)
{
    int i = blockIdx.x * 256 + threadIdx.x;      // 131072 total
    if (i < 65536) {
        bf16 h, l;
        split_bf16(w1[i], h, l);
        g_w1h[i] = h; g_w1l[i] = l;
    } else {
        int j = i - 65536;
        bf16 h, l;
        split_bf16(w2[j], h, l);
        g_w2h[j] = h; g_w2l[j] = l;
    }
}

// ======================= kernel 1 (unchanged, FFMA2) =======================
#define OFF_A   0
#define OFF_B   8704
#define OFF_Q   17408
#define OFF_K   26112
#define OFF_V   34816
#define OFF_W   43520
#define OFF_S   51968
#define OFF_L0  56320
#define OFF_MU  56384
#define OFF_RS  56448
#define OFF_DEN 56512
#define SM1_FLOATS 56576
#define SM1_BYTES (SM1_FLOATS * 4)

__global__ __launch_bounds__(256, 1)
void k1_attn(const float* __restrict__ x, const float* __restrict__ l0,
             const float* __restrict__ n1w, const float* __restrict__ n1b,
             const float* __restrict__ qkvw, const float* __restrict__ gw,
             const float* __restrict__ gb, const float* __restrict__ pw,
             const float* __restrict__ pb, float* __restrict__ outp)
{
    extern __shared__ float sm[];
    const int tid = threadIdx.x;
    const int wi = blockIdx.x;
    const int b  = wi >> 10;
    const int hi = (wi >> 5) & 31;
    const int wj = wi & 31;
    const int base_pix = (hi * 8) * NPLANE + wj * 8;
    const float* xb = x + (size_t)b * 128 * HW;

    #pragma unroll
    for (int it = 0; it < 32; ++it) {
        int idx = tid + it * 256;
        int c = idx >> 6, p = idx & 63;
        sm[OFF_A + c * 68 + p] = xb[c * HW + base_pix + (p >> 3) * NPLANE + (p & 7)];
    }
    if (tid < 64) {
        int p = tid;
        sm[OFF_L0 + p] = l0[(size_t)b * HW + base_pix + (p >> 3) * NPLANE + (p & 7)];
    }
    __syncthreads();

    {
        int p = tid >> 2, part = tid & 3;
        float s = 0.f, sq = 0.f;
        #pragma unroll
        for (int c = part * 32; c < part * 32 + 32; ++c) {
            float v = sm[OFF_A + c * 68 + p];
            s += v; sq += v * v;
        }
        s  += __shfl_xor_sync(0xffffffffu, s, 1);
        sq += __shfl_xor_sync(0xffffffffu, sq, 1);
        s  += __shfl_xor_sync(0xffffffffu, s, 2);
        sq += __shfl_xor_sync(0xffffffffu, sq, 2);
        if (part == 0) {
            float mu = s * (1.f / 128.f);
            float var = sq * (1.f / 128.f) - mu * mu;
            sm[OFF_MU + p] = mu;
            sm[OFF_RS + p] = rsqrtf(var + 1e-6f);
        }
    }
    __syncthreads();
    #pragma unroll
    for (int it = 0; it < 32; ++it) {
        int idx = tid + it * 256;
        int c = idx >> 6, p = idx & 63;
        sm[OFF_B + c * 68 + p] =
            n1w[c] * (sm[OFF_A + c * 68 + p] - sm[OFF_MU + p]) * sm[OFF_RS + p] + n1b[c];
    }
    __syncthreads();

    const int tx = tid & 15, ty = tid >> 4;

    for (int ch = 0; ch < 6; ++ch) {
        #pragma unroll
        for (int it = 0; it < 32; ++it) {
            int idx = tid + it * 256;
            int ol = idx >> 7, c = idx & 127;
            sm[OFF_W + ol * 132 + c] = qkvw[(ch * 64 + ol) * 128 + c];
        }
        __syncthreads();
        u64 acc[2][4];
        #pragma unroll
        for (int i = 0; i < 2; ++i)
            #pragma unroll
            for (int j = 0; j < 4; ++j) acc[i][j] = 0ull;
        #pragma unroll 4
        for (int c = 0; c < 128; ++c) {
            ulonglong2 xv = *(const ulonglong2*)&sm[OFF_B + c * 68 + 4 * tx];
            #pragma unroll
            for (int j = 0; j < 4; ++j) {
                u64 wp = pack2(sm[OFF_W + (4 * ty + j) * 132 + c]);
                acc[0][j] = ffma2(xv.x, wp, acc[0][j]);
                acc[1][j] = ffma2(xv.y, wp, acc[1][j]);
            }
        }
        int dst = (ch < 2) ? OFF_Q : (ch < 4) ? OFF_K : OFF_V;
        int rbase = (ch & 1) * 64;
        if (ch < 2) {
            #pragma unroll
            for (int j = 0; j < 4; ++j) {
                int o = rbase + 4 * ty + j;
                float gwv = gw[o], gbv = gb[o];
                float2 f0 = unpack2(acc[0][j]), f1 = unpack2(acc[1][j]);
                float f[4] = {f0.x, f0.y, f1.x, f1.y};
                float4 st;
                float* pst = &st.x;
                #pragma unroll
                for (int i = 0; i < 4; ++i) {
                    int p = 4 * tx + i;
                    float z = sm[OFF_L0 + p] * gwv + gbv;
                    float g = 1.f / (1.f + __expf(-z));
                    pst[i] = f[i] * g;
                }
                *(float4*)&sm[dst + o * 68 + 4 * tx] = st;
            }
        } else {
            #pragma unroll
            for (int j = 0; j < 4; ++j) {
                int o = rbase + 4 * ty + j;
                float2 f0 = unpack2(acc[0][j]), f1 = unpack2(acc[1][j]);
                float4 st = {f0.x, f0.y, f1.x, f1.y};
                *(float4*)&sm[dst + o * 68 + 4 * tx] = st;
            }
        }
        __syncthreads();
    }

    for (int h = 0; h < 8; ++h) {
        const int cb = h * 16;
        {
            u64 acc[2][4];
            #pragma unroll
            for (int i = 0; i < 2; ++i)
                #pragma unroll
                for (int j = 0; j < 4; ++j) acc[i][j] = 0ull;
            #pragma unroll
            for (int d = 0; d < 16; ++d) {
                ulonglong2 qv = *(const ulonglong2*)&sm[OFF_Q + (cb + d) * 68 + 4 * tx];
                #pragma unroll
                for (int j = 0; j < 4; ++j) {
                    u64 kp = pack2(sm[OFF_K + (cb + d) * 68 + 4 * ty + j]);
                    acc[0][j] = ffma2(qv.x, kp, acc[0][j]);
                    acc[1][j] = ffma2(qv.y, kp, acc[1][j]);
                }
            }
            #pragma unroll
            for (int a = 0; a < 2; ++a)
                #pragma unroll
                for (int j = 0; j < 4; ++j) {
                    float2 f = unpack2(acc[a][j]);
                    sm[OFF_S + (4 * tx + 2 * a) * 68 + 4 * ty + j] = f.x * 0.25f;
                    sm[OFF_S + (4 * tx + 2 * a + 1) * 68 + 4 * ty + j] = f.y * 0.25f;
                }
        }
        __syncthreads();
        {
            int r = tid >> 2, part = tid & 3;
            float m = -1e30f;
            #pragma unroll
            for (int kk = part * 16; kk < part * 16 + 16; ++kk)
                m = fmaxf(m, sm[OFF_S + r * 68 + kk]);
            m = fmaxf(m, __shfl_xor_sync(0xffffffffu, m, 1));
            m = fmaxf(m, __shfl_xor_sync(0xffffffffu, m, 2));
            float s = 0.f;
            #pragma unroll
            for (int kk = part * 16; kk < part * 16 + 16; ++kk) {
                float e = __expf(sm[OFF_S + r * 68 + kk] - m);
                sm[OFF_S + r * 68 + kk] = e;
                s += e;
            }
            s += __shfl_xor_sync(0xffffffffu, s, 1);
            s += __shfl_xor_sync(0xffffffffu, s, 2);
            if (part == 0) sm[OFF_DEN + r] = 1.f / s;
        }
        __syncthreads();
        {
            int pq = tid >> 2, dg = tid & 3;
            const u64* Srow = (const u64*)&sm[OFF_S + pq * 68];
            const u64* V0 = (const u64*)&sm[OFF_V + (cb + 4 * dg + 0) * 68];
            const u64* V1 = (const u64*)&sm[OFF_V + (cb + 4 * dg + 1) * 68];
            const u64* V2 = (const u64*)&sm[OFF_V + (cb + 4 * dg + 2) * 68];
            const u64* V3 = (const u64*)&sm[OFF_V + (cb + 4 * dg + 3) * 68];
            u64 a0 = 0ull, a1 = 0ull, a2 = 0ull, a3 = 0ull;
            #pragma unroll 8
            for (int kk = 0; kk < 32; ++kk) {
                u64 prp = Srow[kk];
                a0 = ffma2(prp, V0[kk], a0);
                a1 = ffma2(prp, V1[kk], a1);
                a2 = ffma2(prp, V2[kk], a2);
                a3 = ffma2(prp, V3[kk], a3);
            }
            float dn = sm[OFF_DEN + pq];
            float2 f0 = unpack2(a0), f1 = unpack2(a1), f2 = unpack2(a2), f3 = unpack2(a3);
            sm[OFF_B + (cb + 4 * dg + 0) * 68 + pq] = (f0.x + f0.y) * dn;
            sm[OFF_B + (cb + 4 * dg + 1) * 68 + pq] = (f1.x + f1.y) * dn;
            sm[OFF_B + (cb + 4 * dg + 2) * 68 + pq] = (f2.x + f2.y) * dn;
            sm[OFF_B + (cb + 4 * dg + 3) * 68 + pq] = (f3.x + f3.y) * dn;
        }
        __syncthreads();
    }

    for (int ch = 0; ch < 2; ++ch) {
        #pragma unroll
        for (int it = 0; it < 32; ++it) {
            int idx = tid + it * 256;
            int ol = idx >> 7, c = idx & 127;
            sm[OFF_W + ol * 132 + c] = pw[(ch * 64 + ol) * 128 + c];
        }
        __syncthreads();
        u64 acc[2][4];
        #pragma unroll
        for (int i = 0; i < 2; ++i)
            #pragma unroll
            for (int j = 0; j < 4; ++j) acc[i][j] = 0ull;
        #pragma unroll 4
        for (int c = 0; c < 128; ++c) {
            ulonglong2 xv = *(const ulonglong2*)&sm[OFF_B + c * 68 + 4 * tx];
            #pragma unroll
            for (int j = 0; j < 4; ++j) {
                u64 wp = pack2(sm[OFF_W + (4 * ty + j) * 132 + c]);
                acc[0][j] = ffma2(xv.x, wp, acc[0][j]);
                acc[1][j] = ffma2(xv.y, wp, acc[1][j]);
            }
        }
        #pragma unroll
        for (int j = 0; j < 4; ++j) {
            float2 f0 = unpack2(acc[0][j]), f1 = unpack2(acc[1][j]);
            float4 st = {f0.x, f0.y, f1.x, f1.y};
            *(float4*)&sm[OFF_S + (4 * ty + j) * 68 + 4 * tx] = st;
        }
        __syncthreads();
        #pragma unroll
        for (int it = 0; it < 16; ++it) {
            int idx = tid + it * 256;
            int ol = idx >> 6, p = idx & 63;
            int o = ch * 64 + ol;
            float v = sm[OFF_S + ol * 68 + p] + pb[o] + sm[OFF_A + o * 68 + p];
            outp[(size_t)(b * 128 + o) * HW + base_pix + (p >> 3) * NPLANE + (p & 7)] = v;
        }
        __syncthreads();
    }
}

// ======================= kernel 2: LN2 + W1 + GELU (tensor) ================
// smem bytes:
//   Xf  f32 [128][132]  @ 0        (67584)
//   Xh  bf16[128c][136] @ 67584    (34816)   (k-major: rows=c, cols=px)
//   Xl               @ 102400
//   Wh  bf16[128o][136] @ 137216
//   Wl               @ 172032
//   MU @ 206848, RS @ 207360; Cst f32[128][132] aliases Wh/Wl
#define SM2_BYTES 207872

__global__ __launch_bounds__(256, 1)
void k2_ffn1(const float* __restrict__ inp, const float* __restrict__ n2w,
             const float* __restrict__ n2b, const float* __restrict__ b1)
{
    extern __shared__ char smc[];
    float* Xf = (float*)smc;
    bf16* Xh = (bf16*)(smc + 67584);
    bf16* Xl = (bf16*)(smc + 102400);
    bf16* Wh = (bf16*)(smc + 137216);
    bf16* Wl = (bf16*)(smc + 172032);
    float* Cst = (float*)(smc + 137216);
    float* MU = (float*)(smc + 206848);
    float* RS = (float*)(smc + 207360);

    const int tid = threadIdx.x;
    const int pg = blockIdx.x * 128;
    const int b = pg >> 16;
    const int pix = pg & 65535;
    const float* ib = inp + (size_t)b * 128 * HW + pix;

    #pragma unroll
    for (int it = 0; it < 64; ++it) {
        int idx = tid + it * 256;
        int c = idx >> 7, p = idx & 127;
        Xf[c * 132 + p] = ib[c * HW + p];
    }
    __syncthreads();
    {
        int p = tid >> 1, part = tid & 1;
        float s = 0.f, sq = 0.f;
        #pragma unroll
        for (int c = part * 64; c < part * 64 + 64; ++c) {
            float v = Xf[c * 132 + p];
            s += v; sq += v * v;
        }
        s  += __shfl_xor_sync(0xffffffffu, s, 1);
        sq += __shfl_xor_sync(0xffffffffu, sq, 1);
        if (part == 0) {
            float mu = s * (1.f / 128.f);
            float var = sq * (1.f / 128.f) - mu * mu;
            MU[p] = mu;
            RS[p] = rsqrtf(var + 1e-6f);
        }
    }
    __syncthreads();
    // normalize + split, natural [c][p] layout (ldmatrix.trans handles transpose)
    #pragma unroll
    for (int it = 0; it < 64; ++it) {
        int idx = tid + it * 256;
        int c = idx >> 7, p = idx & 127;
        float xn = n2w[c] * (Xf[c * 132 + p] - MU[p]) * RS[p] + n2b[c];
        bf16 h, l;
        split_bf16(xn, h, l);
        Xh[c * 136 + p] = h;
        Xl[c * 136 + p] = l;
    }

    const int lane = tid & 31;
    const int warp = tid >> 5;
    const int g = lane >> 2, tg = lane & 3;
    const int mbase = (warp >> 1) * 32;
    const int nbase = (warp & 1) * 64;
    const int laneoff = (lane & 15) * 272 + ((lane >> 4) << 4);

    const u32 smXh = (u32)__cvta_generic_to_shared(Xh);
    const u32 smXl = (u32)__cvta_generic_to_shared(Xl);
    const u32 smWh = (u32)__cvta_generic_to_shared(Wh);
    const u32 smWl = (u32)__cvta_generic_to_shared(Wl);

    for (int och = 0; och < 4; ++och) {
        __syncthreads();
        // copy pre-split W chunk (u32 copies, no conversion)
        {
            const u32* wh = (const u32*)&g_w1h[(och * 128) * 128];
            const u32* wl = (const u32*)&g_w1l[(och * 128) * 128];
            u32* dWh = (u32*)Wh;
            u32* dWl = (u32*)Wl;
            #pragma unroll
            for (int it = 0; it < 32; ++it) {
                int idx = tid + it * 256;
                int o = idx >> 5, kk = idx & 31;   // 64 u32 per row? 128k = 64 u32
                // each row has 64 u32; process as o = idx>>6, kk = idx&63 over 8192 u32
                (void)o; (void)kk;
            }
            #pragma unroll
            for (int it = 0; it < 32; ++it) {
                int idx = tid + it * 256;
                int o = idx >> 6, kk = idx & 63;
                dWh[o * 68 + kk] = wh[o * 64 + kk];
                dWl[o * 68 + kk] = wl[o * 64 + kk];
            }
        }
        __syncthreads();

        float acc[2][8][4];
        #pragma unroll
        for (int mt = 0; mt < 2; ++mt)
            #pragma unroll
            for (int nt = 0; nt < 8; ++nt)
                #pragma unroll
                for (int q = 0; q < 4; ++q) acc[mt][nt][q] = 0.f;

        #pragma unroll
        for (int ks = 0; ks < 8; ++ks) {
            u32 ah[2][4], al[2][4];
            ldsm4(ah[0][0], ah[0][1], ah[0][2], ah[0][3],
                  smWh + laneoff + mbase * 272 + ks * 32);
            ldsm4(ah[1][0], ah[1][1], ah[1][2], ah[1][3],
                  smWh + laneoff + (mbase + 16) * 272 + ks * 32);
            ldsm4(al[0][0], al[0][1], al[0][2], al[0][3],
                  smWl + laneoff + mbase * 272 + ks * 32);
            ldsm4(al[1][0], al[1][1], al[1][2], al[1][3],
                  smWl + laneoff + (mbase + 16) * 272 + ks * 32);
            #pragma unroll
            for (int ntp = 0; ntp < 4; ++ntp) {
                int n0 = nbase + ntp * 16;
                u32 bh[4], bl[4];
                ldsm4t(bh[0], bh[1], bh[2], bh[3],
                       smXh + laneoff + ks * 16 * 272 + n0 * 2);
                ldsm4t(bl[0], bl[1], bl[2], bl[3],
                       smXl + laneoff + ks * 16 * 272 + n0 * 2);
                #pragma unroll
                for (int mt = 0; mt < 2; ++mt) {
                    mma16816(acc[mt][2 * ntp],     ah[mt], bh[0], bh[1]);
                    mma16816(acc[mt][2 * ntp + 1], ah[mt], bh[2], bh[3]);
                    mma16816(acc[mt][2 * ntp],     ah[mt], bl[0], bl[1]);
                    mma16816(acc[mt][2 * ntp + 1], ah[mt], bl[2], bl[3]);
                    mma16816(acc[mt][2 * ntp],     al[mt], bh[0], bh[1]);
                    mma16816(acc[mt][2 * ntp + 1], al[mt], bh[2], bh[3]);
                }
            }
        }
        __syncthreads();     // done reading W before Cst overwrites it
        #pragma unroll
        for (int mt = 0; mt < 2; ++mt) {
            #pragma unroll
            for (int nt = 0; nt < 8; ++nt) {
                int r = mbase + mt * 16 + g;
                int cc = nbase + nt * 8 + tg * 2;
                *(float2*)&Cst[r * 132 + cc] = make_float2(acc[mt][nt][0], acc[mt][nt][1]);
                *(float2*)&Cst[(r + 8) * 132 + cc] = make_float2(acc[mt][nt][2], acc[mt][nt][3]);
            }
        }
        __syncthreads();
        #pragma unroll
        for (int it = 0; it < 64; ++it) {
            int idx = tid + it * 256;
            int o = idx >> 7, p = idx & 127;
            float v = Cst[o * 132 + p] + b1[och * 128 + o];
            g_h1[(size_t)(b * 512 + och * 128 + o) * HW + pix + p] = gelu_exact(v);
        }
    }
}

// ======================= kernel 3: dw3x3 + GELU, split output ==============
__global__ __launch_bounds__(256)
void k3_dw(const float* __restrict__ dw, const float* __restrict__ dwb)
{
    __shared__ float tile[10][34];
    const int plane = blockIdx.z;
    const int ch = plane & 511;
    const float* ip = g_h1 + (size_t)plane * HW;
    const int x0 = blockIdx.x * 32, y0 = blockIdx.y * 8;
    const int tid = threadIdx.x;

    for (int idx = tid; idx < 340; idx += 256) {
        int ly = idx / 34, lx = idx % 34;
        int gy = y0 + ly - 1, gx = x0 + lx - 1;
        tile[ly][lx] = (gy >= 0 && gy < 256 && gx >= 0 && gx < 256) ? ip[gy * NPLANE + gx] : 0.f;
    }
    __syncthreads();

    const int tx = tid & 31, ty = tid >> 5;
    float w[9];
    #pragma unroll
    for (int i = 0; i < 9; ++i) w[i] = dw[ch * 9 + i];
    float s = dwb[ch];
    #pragma unroll
    for (int dy = 0; dy < 3; ++dy)
        #pragma unroll
        for (int dx = 0; dx < 3; ++dx)
            s += w[dy * 3 + dx] * tile[ty + dy][tx + dx];
    float r = gelu_exact(s);
    bf16 h, l;
    split_bf16(r, h, l);
    size_t off = (size_t)plane * HW + (y0 + ty) * NPLANE + x0 + tx;
    g_h2h[off] = h;
    g_h2l[off] = l;
}

// ======================= kernel 4: W2 + residual (tensor) ==================
// smem bytes:
//   Xh bf16[128k][136] @ 0       (34816)
//   Xl              @ 34816
//   Wh bf16[128o][136] @ 69632
//   Wl              @ 104448
//   Cst f32[128][132] aliases @ 0
#define SM4_BYTES 139264

__global__ __launch_bounds__(256, 1)
void k4_ffn2(const float* __restrict__ b2, float* __restrict__ io)
{
    extern __shared__ char smc[];
    bf16* Xh = (bf16*)smc;
    bf16* Xl = (bf16*)(smc + 34816);
    bf16* Wh = (bf16*)(smc + 69632);
    bf16* Wl = (bf16*)(smc + 104448);
    float* Cst = (float*)smc;

    const int tid = threadIdx.x;
    const int pg = blockIdx.x * 128;
    const int b = pg >> 16;
    const int pix = pg & 65535;

    const int lane = tid & 31;
    const int warp = tid >> 5;
    const int g = lane >> 2, tg = lane & 3;
    const int mbase = (warp >> 1) * 32;
    const int nbase = (warp & 1) * 64;
    const int laneoff = (lane & 15) * 272 + ((lane >> 4) << 4);

    const u32 smXh = (u32)__cvta_generic_to_shared(Xh);
    const u32 smXl = (u32)__cvta_generic_to_shared(Xl);
    const u32 smWh = (u32)__cvta_generic_to_shared(Wh);
    const u32 smWl = (u32)__cvta_generic_to_shared(Wl);

    float acc[2][8][4];
    #pragma unroll
    for (int mt = 0; mt < 2; ++mt)
        #pragma unroll
        for (int nt = 0; nt < 8; ++nt)
            #pragma unroll
            for (int q = 0; q < 4; ++q) acc[mt][nt][q] = 0.f;

    for (int kc = 0; kc < 4; ++kc) {
        __syncthreads();
        {   // X: coalesced u32 copies, natural [k][p] layout
            const u32* xh = (const u32*)&g_h2h[((size_t)(b * 512 + kc * 128)) * HW + pix];
            const u32* xl = (const u32*)&g_h2l[((size_t)(b * 512 + kc * 128)) * HW + pix];
            u32* dXh = (u32*)Xh;
            u32* dXl = (u32*)Xl;
            #pragma unroll
            for (int it = 0; it < 32; ++it) {
                int idx = tid + it * 256;
                int k = idx >> 6, pp = idx & 63;
                dXh[k * 68 + pp] = xh[(size_t)k * (HW / 2) + pp];
                dXl[k * 68 + pp] = xl[(size_t)k * (HW / 2) + pp];
            }
            // W: pre-split copies
            const u32* wh = (const u32*)&g_w2h[kc * 128];
            const u32* wl = (const u32*)&g_w2l[kc * 128];
            u32* dWh = (u32*)Wh;
            u32* dWl = (u32*)Wl;
            #pragma unroll
            for (int it = 0; it < 32; ++it) {
                int idx = tid + it * 256;
                int o = idx >> 6, kk = idx & 63;
                dWh[o * 68 + kk] = wh[o * 256 + kk];   // w2 row stride 512 bf16 = 256 u32
                dWl[o * 68 + kk] = wl[o * 256 + kk];
            }
        }
        __syncthreads();

        #pragma unroll
        for (int ks = 0; ks < 8; ++ks) {
            u32 ah[2][4], al[2][4];
            ldsm4(ah[0][0], ah[0][1], ah[0][2], ah[0][3],
                  smWh + laneoff + mbase * 272 + ks * 32);
            ldsm4(ah[1][0], ah[1][1], ah[1][2], ah[1][3],
                  smWh + laneoff + (mbase + 16) * 272 + ks * 32);
            ldsm4(al[0][0], al[0][1], al[0][2], al[0][3],
                  smWl + laneoff + mbase * 272 + ks * 32);
            ldsm4(al[1][0], al[1][1], al[1][2], al[1][3],
                  smWl + laneoff + (mbase + 16) * 272 + ks * 32);
            #pragma unroll
            for (int ntp = 0; ntp < 4; ++ntp) {
                int n0 = nbase + ntp * 16;
                u32 bh[4], bl[4];
                ldsm4t(bh[0], bh[1], bh[2], bh[3],
                       smXh + laneoff + ks * 16 * 272 + n0 * 2);
                ldsm4t(bl[0], bl[1], bl[2], bl[3],
                       smXl + laneoff + ks * 16 * 272 + n0 * 2);
                #pragma unroll
                for (int mt = 0; mt < 2; ++mt) {
                    mma16816(acc[mt][2 * ntp],     ah[mt], bh[0], bh[1]);
                    mma16816(acc[mt][2 * ntp + 1], ah[mt], bh[2], bh[3]);
                    mma16816(acc[mt][2 * ntp],     ah[mt], bl[0], bl[1]);
                    mma16816(acc[mt][2 * ntp + 1], ah[mt], bl[2], bl[3]);
                    mma16816(acc[mt][2 * ntp],     al[mt], bh[0], bh[1]);
                    mma16816(acc[mt][2 * ntp + 1], al[mt], bh[2], bh[3]);
                }
            }
        }
    }

    __syncthreads();
    #pragma unroll
    for (int mt = 0; mt < 2; ++mt) {
        #pragma unroll
        for (int nt = 0; nt < 8; ++nt) {
            int r = mbase + mt * 16 + g;
            int cc = nbase + nt * 8 + tg * 2;
            *(float2*)&Cst[r * 132 + cc] = make_float2(acc[mt][nt][0], acc[mt][nt][1]);
            *(float2*)&Cst[(r + 8) * 132 + cc] = make_float2(acc[mt][nt][2], acc[mt][nt][3]);
        }
    }
    __syncthreads();
    #pragma unroll
    for (int it = 0; it < 64; ++it) {
        int idx = tid + it * 256;
        int o = idx >> 7, p = idx & 127;
        size_t ad = (size_t)(b * 128 + o) * HW + pix + p;
        io[ad] = io[ad] + Cst[o * 132 + p] + b2[o];
    }
}

// ---------------------------------------------------------------------------
extern "C" void kernel_launch(void* const* d_in, const int* in_sizes, int n_in,
                              void* d_out, int out_size)
{
    const float* x    = (const float*)d_in[0];
    const float* l0   = (const float*)d_in[1];
    const float* n1w  = (const float*)d_in[2];
    const float* n1b  = (const float*)d_in[3];
    const float* n2w  = (const float*)d_in[4];
    const float* n2b  = (const float*)d_in[5];
    const float* qkvw = (const float*)d_in[6];
    const float* gw   = (const float*)d_in[7];
    const float* gb   = (const float*)d_in[8];
    const float* pw   = (const float*)d_in[9];
    const float* pb   = (const float*)d_in[10];
    const float* w1   = (const float*)d_in[11];
    const float* b1   = (const float*)d_in[12];
    const float* dw   = (const float*)d_in[13];
    const float* dwb  = (const float*)d_in[14];
    const float* w2   = (const float*)d_in[15];
    const float* b2   = (const float*)d_in[16];
    float* out = (float*)d_out;

    cudaFuncSetAttribute(k1_attn, cudaFuncAttributeMaxDynamicSharedMemorySize, SM1_BYTES);
    cudaFuncSetAttribute(k2_ffn1, cudaFuncAttributeMaxDynamicSharedMemorySize, SM2_BYTES);
    cudaFuncSetAttribute(k4_ffn2, cudaFuncAttributeMaxDynamicSharedMemorySize, SM4_BYTES);

    k0_prep<<<512, 256>>>(w1, w2);
    k1_attn<<<4096, 256, SM1_BYTES>>>(x, l0, n1w, n1b, qkvw, gw, gb, pw, pb, out);
    k2_ffn1<<<2048, 256, SM2_BYTES>>>(out, n2w, n2b, b1);
    dim3 g3(8, 32, 2048);
    k3_dw<<<g3, 256>>>(dw, dwb);
    k4_ffn2<<<2048, 256, SM4_BYTES>>>(b2, out);
}

// round 9
// speedup vs baseline: 1.2625x; 1.1165x over previous
#include <cuda_runtime.h>
#include <cuda_bf16.h>
#include <math.h>

// ---------------------------------------------------------------------------
// IGAB block, B=4, C=128, H=W=256, window 8x8, heads=8, head_dim=16, HIDDEN=512
//   k0: pre-split w1/w2 into bf16 hi/lo (once per launch)
//   k1: LN1 + QKV + gate + window-attention + proj + residual  (FFMA2)
//   k2: LN2 + W1 + GELU   -> bf16 2-term split MMA, ldmatrix
//   k3: depthwise 3x3 + bias + GELU -> 4px/thread, no smem, writes bf16 hi/lo
//   k4: W2 + bias + residual -> bf16 2-term split MMA, ldmatrix
// ---------------------------------------------------------------------------

#define HW 65536
#define NPLANE 256

__device__ float g_h1[(size_t)4 * 512 * HW];            // fp32 for k3
__device__ __nv_bfloat16 g_h2h[(size_t)4 * 512 * HW];   // split for k4
__device__ __nv_bfloat16 g_h2l[(size_t)4 * 512 * HW];
__device__ __nv_bfloat16 g_w1h[512 * 128], g_w1l[512 * 128];
__device__ __nv_bfloat16 g_w2h[128 * 512], g_w2l[128 * 512];

typedef unsigned long long u64;
typedef unsigned int u32;
typedef __nv_bfloat16 bf16;

__device__ __forceinline__ u64 ffma2(u64 a, u64 b, u64 c) {
    u64 d;
    asm("fma.rn.f32x2 %0, %1, %2, %3;" : "=l"(d) : "l"(a), "l"(b), "l"(c));
    return d;
}
__device__ __forceinline__ u64 pack2(float v) {
    u64 d;
    asm("mov.b64 %0, {%1, %1};" : "=l"(d) : "r"(__float_as_uint(v)));
    return d;
}
__device__ __forceinline__ float2 unpack2(u64 v) {
    unsigned lo, hi;
    asm("mov.b64 {%0, %1}, %2;" : "=r"(lo), "=r"(hi) : "l"(v));
    return make_float2(__uint_as_float(lo), __uint_as_float(hi));
}
__device__ __forceinline__ float gelu_exact(float v) {
    return 0.5f * v * (1.0f + erff(v * 0.70710678118654752f));
}
__device__ __forceinline__ void mma16816(float* c, const u32* a, u32 b0, u32 b1) {
    asm volatile(
        "mma.sync.aligned.m16n8k16.row.col.f32.bf16.bf16.f32 "
        "{%0,%1,%2,%3},{%4,%5,%6,%7},{%8,%9},{%0,%1,%2,%3};"
        : "+f"(c[0]), "+f"(c[1]), "+f"(c[2]), "+f"(c[3])
        : "r"(a[0]), "r"(a[1]), "r"(a[2]), "r"(a[3]), "r"(b0), "r"(b1));
}
__device__ __forceinline__ void ldsm4(u32& d0, u32& d1, u32& d2, u32& d3, u32 a) {
    asm volatile("ldmatrix.sync.aligned.m8n8.x4.shared.b16 {%0,%1,%2,%3},[%4];"
                 : "=r"(d0), "=r"(d1), "=r"(d2), "=r"(d3) : "r"(a));
}
__device__ __forceinline__ void ldsm4t(u32& d0, u32& d1, u32& d2, u32& d3, u32 a) {
    asm volatile("ldmatrix.sync.aligned.m8n8.x4.trans.shared.b16 {%0,%1,%2,%3},[%4];"
                 : "=r"(d0), "=r"(d1), "=r"(d2), "=r"(d3) : "r"(a));
}
__device__ __forceinline__ void split_bf16(float v, bf16& h, bf16& l) {
    h = __float2bfloat16(v);
    l = __float2bfloat16(v - __bfloat162float(h));
}

// ======================= kernel 0: weight pre-split ========================
__global__ __launch_bounds__(256)
void k0_prep(const float* __restrict__ w1, const float* __restrict__ w2)
{
    int i = blockIdx.x * 256 + threadIdx.x;      // 131072 total
    if (i < 65536) {
        bf16 h, l;
        split_bf16(w1[i], h, l);
        g_w1h[i] = h; g_w1l[i] = l;
    } else {
        int j = i - 65536;
        bf16 h, l;
        split_bf16(w2[j], h, l);
        g_w2h[j] = h; g_w2l[j] = l;
    }
}

// ======================= kernel 1 (unchanged, FFMA2) =======================
#define OFF_A   0
#define OFF_B   8704
#define OFF_Q   17408
#define OFF_K   26112
#define OFF_V   34816
#define OFF_W   43520
#define OFF_S   51968
#define OFF_L0  56320
#define OFF_MU  56384
#define OFF_RS  56448
#define OFF_DEN 56512
#define SM1_FLOATS 56576
#define SM1_BYTES (SM1_FLOATS * 4)

__global__ __launch_bounds__(256, 1)
void k1_attn(const float* __restrict__ x, const float* __restrict__ l0,
             const float* __restrict__ n1w, const float* __restrict__ n1b,
             const float* __restrict__ qkvw, const float* __restrict__ gw,
             const float* __restrict__ gb, const float* __restrict__ pw,
             const float* __restrict__ pb, float* __restrict__ outp)
{
    extern __shared__ float sm[];
    const int tid = threadIdx.x;
    const int wi = blockIdx.x;
    const int b  = wi >> 10;
    const int hi = (wi >> 5) & 31;
    const int wj = wi & 31;
    const int base_pix = (hi * 8) * NPLANE + wj * 8;
    const float* xb = x + (size_t)b * 128 * HW;

    #pragma unroll
    for (int it = 0; it < 32; ++it) {
        int idx = tid + it * 256;
        int c = idx >> 6, p = idx & 63;
        sm[OFF_A + c * 68 + p] = xb[c * HW + base_pix + (p >> 3) * NPLANE + (p & 7)];
    }
    if (tid < 64) {
        int p = tid;
        sm[OFF_L0 + p] = l0[(size_t)b * HW + base_pix + (p >> 3) * NPLANE + (p & 7)];
    }
    __syncthreads();

    {
        int p = tid >> 2, part = tid & 3;
        float s = 0.f, sq = 0.f;
        #pragma unroll
        for (int c = part * 32; c < part * 32 + 32; ++c) {
            float v = sm[OFF_A + c * 68 + p];
            s += v; sq += v * v;
        }
        s  += __shfl_xor_sync(0xffffffffu, s, 1);
        sq += __shfl_xor_sync(0xffffffffu, sq, 1);
        s  += __shfl_xor_sync(0xffffffffu, s, 2);
        sq += __shfl_xor_sync(0xffffffffu, sq, 2);
        if (part == 0) {
            float mu = s * (1.f / 128.f);
            float var = sq * (1.f / 128.f) - mu * mu;
            sm[OFF_MU + p] = mu;
            sm[OFF_RS + p] = rsqrtf(var + 1e-6f);
        }
    }
    __syncthreads();
    #pragma unroll
    for (int it = 0; it < 32; ++it) {
        int idx = tid + it * 256;
        int c = idx >> 6, p = idx & 63;
        sm[OFF_B + c * 68 + p] =
            n1w[c] * (sm[OFF_A + c * 68 + p] - sm[OFF_MU + p]) * sm[OFF_RS + p] + n1b[c];
    }
    __syncthreads();

    const int tx = tid & 15, ty = tid >> 4;

    for (int ch = 0; ch < 6; ++ch) {
        #pragma unroll
        for (int it = 0; it < 32; ++it) {
            int idx = tid + it * 256;
            int ol = idx >> 7, c = idx & 127;
            sm[OFF_W + ol * 132 + c] = qkvw[(ch * 64 + ol) * 128 + c];
        }
        __syncthreads();
        u64 acc[2][4];
        #pragma unroll
        for (int i = 0; i < 2; ++i)
            #pragma unroll
            for (int j = 0; j < 4; ++j) acc[i][j] = 0ull;
        #pragma unroll 4
        for (int c = 0; c < 128; ++c) {
            ulonglong2 xv = *(const ulonglong2*)&sm[OFF_B + c * 68 + 4 * tx];
            #pragma unroll
            for (int j = 0; j < 4; ++j) {
                u64 wp = pack2(sm[OFF_W + (4 * ty + j) * 132 + c]);
                acc[0][j] = ffma2(xv.x, wp, acc[0][j]);
                acc[1][j] = ffma2(xv.y, wp, acc[1][j]);
            }
        }
        int dst = (ch < 2) ? OFF_Q : (ch < 4) ? OFF_K : OFF_V;
        int rbase = (ch & 1) * 64;
        if (ch < 2) {
            #pragma unroll
            for (int j = 0; j < 4; ++j) {
                int o = rbase + 4 * ty + j;
                float gwv = gw[o], gbv = gb[o];
                float2 f0 = unpack2(acc[0][j]), f1 = unpack2(acc[1][j]);
                float f[4] = {f0.x, f0.y, f1.x, f1.y};
                float4 st;
                float* pst = &st.x;
                #pragma unroll
                for (int i = 0; i < 4; ++i) {
                    int p = 4 * tx + i;
                    float z = sm[OFF_L0 + p] * gwv + gbv;
                    float g = 1.f / (1.f + __expf(-z));
                    pst[i] = f[i] * g;
                }
                *(float4*)&sm[dst + o * 68 + 4 * tx] = st;
            }
        } else {
            #pragma unroll
            for (int j = 0; j < 4; ++j) {
                int o = rbase + 4 * ty + j;
                float2 f0 = unpack2(acc[0][j]), f1 = unpack2(acc[1][j]);
                float4 st = {f0.x, f0.y, f1.x, f1.y};
                *(float4*)&sm[dst + o * 68 + 4 * tx] = st;
            }
        }
        __syncthreads();
    }

    for (int h = 0; h < 8; ++h) {
        const int cb = h * 16;
        {
            u64 acc[2][4];
            #pragma unroll
            for (int i = 0; i < 2; ++i)
                #pragma unroll
                for (int j = 0; j < 4; ++j) acc[i][j] = 0ull;
            #pragma unroll
            for (int d = 0; d < 16; ++d) {
                ulonglong2 qv = *(const ulonglong2*)&sm[OFF_Q + (cb + d) * 68 + 4 * tx];
                #pragma unroll
                for (int j = 0; j < 4; ++j) {
                    u64 kp = pack2(sm[OFF_K + (cb + d) * 68 + 4 * ty + j]);
                    acc[0][j] = ffma2(qv.x, kp, acc[0][j]);
                    acc[1][j] = ffma2(qv.y, kp, acc[1][j]);
                }
            }
            #pragma unroll
            for (int a = 0; a < 2; ++a)
                #pragma unroll
                for (int j = 0; j < 4; ++j) {
                    float2 f = unpack2(acc[a][j]);
                    sm[OFF_S + (4 * tx + 2 * a) * 68 + 4 * ty + j] = f.x * 0.25f;
                    sm[OFF_S + (4 * tx + 2 * a + 1) * 68 + 4 * ty + j] = f.y * 0.25f;
                }
        }
        __syncthreads();
        {
            int r = tid >> 2, part = tid & 3;
            float m = -1e30f;
            #pragma unroll
            for (int kk = part * 16; kk < part * 16 + 16; ++kk)
                m = fmaxf(m, sm[OFF_S + r * 68 + kk]);
            m = fmaxf(m, __shfl_xor_sync(0xffffffffu, m, 1));
            m = fmaxf(m, __shfl_xor_sync(0xffffffffu, m, 2));
            float s = 0.f;
            #pragma unroll
            for (int kk = part * 16; kk < part * 16 + 16; ++kk) {
                float e = __expf(sm[OFF_S + r * 68 + kk] - m);
                sm[OFF_S + r * 68 + kk] = e;
                s += e;
            }
            s += __shfl_xor_sync(0xffffffffu, s, 1);
            s += __shfl_xor_sync(0xffffffffu, s, 2);
            if (part == 0) sm[OFF_DEN + r] = 1.f / s;
        }
        __syncthreads();
        {
            int pq = tid >> 2, dg = tid & 3;
            const u64* Srow = (const u64*)&sm[OFF_S + pq * 68];
            const u64* V0 = (const u64*)&sm[OFF_V + (cb + 4 * dg + 0) * 68];
            const u64* V1 = (const u64*)&sm[OFF_V + (cb + 4 * dg + 1) * 68];
            const u64* V2 = (const u64*)&sm[OFF_V + (cb + 4 * dg + 2) * 68];
            const u64* V3 = (const u64*)&sm[OFF_V + (cb + 4 * dg + 3) * 68];
            u64 a0 = 0ull, a1 = 0ull, a2 = 0ull, a3 = 0ull;
            #pragma unroll 8
            for (int kk = 0; kk < 32; ++kk) {
                u64 prp = Srow[kk];
                a0 = ffma2(prp, V0[kk], a0);
                a1 = ffma2(prp, V1[kk], a1);
                a2 = ffma2(prp, V2[kk], a2);
                a3 = ffma2(prp, V3[kk], a3);
            }
            float dn = sm[OFF_DEN + pq];
            float2 f0 = unpack2(a0), f1 = unpack2(a1), f2 = unpack2(a2), f3 = unpack2(a3);
            sm[OFF_B + (cb + 4 * dg + 0) * 68 + pq] = (f0.x + f0.y) * dn;
            sm[OFF_B + (cb + 4 * dg + 1) * 68 + pq] = (f1.x + f1.y) * dn;
            sm[OFF_B + (cb + 4 * dg + 2) * 68 + pq] = (f2.x + f2.y) * dn;
            sm[OFF_B + (cb + 4 * dg + 3) * 68 + pq] = (f3.x + f3.y) * dn;
        }
        __syncthreads();
    }

    for (int ch = 0; ch < 2; ++ch) {
        #pragma unroll
        for (int it = 0; it < 32; ++it) {
            int idx = tid + it * 256;
            int ol = idx >> 7, c = idx & 127;
            sm[OFF_W + ol * 132 + c] = pw[(ch * 64 + ol) * 128 + c];
        }
        __syncthreads();
        u64 acc[2][4];
        #pragma unroll
        for (int i = 0; i < 2; ++i)
            #pragma unroll
            for (int j = 0; j < 4; ++j) acc[i][j] = 0ull;
        #pragma unroll 4
        for (int c = 0; c < 128; ++c) {
            ulonglong2 xv = *(const ulonglong2*)&sm[OFF_B + c * 68 + 4 * tx];
            #pragma unroll
            for (int j = 0; j < 4; ++j) {
                u64 wp = pack2(sm[OFF_W + (4 * ty + j) * 132 + c]);
                acc[0][j] = ffma2(xv.x, wp, acc[0][j]);
                acc[1][j] = ffma2(xv.y, wp, acc[1][j]);
            }
        }
        #pragma unroll
        for (int j = 0; j < 4; ++j) {
            float2 f0 = unpack2(acc[0][j]), f1 = unpack2(acc[1][j]);
            float4 st = {f0.x, f0.y, f1.x, f1.y};
            *(float4*)&sm[OFF_S + (4 * ty + j) * 68 + 4 * tx] = st;
        }
        __syncthreads();
        #pragma unroll
        for (int it = 0; it < 16; ++it) {
            int idx = tid + it * 256;
            int ol = idx >> 6, p = idx & 63;
            int o = ch * 64 + ol;
            float v = sm[OFF_S + ol * 68 + p] + pb[o] + sm[OFF_A + o * 68 + p];
            outp[(size_t)(b * 128 + o) * HW + base_pix + (p >> 3) * NPLANE + (p & 7)] = v;
        }
        __syncthreads();
    }
}

// ======================= kernel 2: LN2 + W1 + GELU (tensor) ================
#define SM2_BYTES 207872

__global__ __launch_bounds__(256, 1)
void k2_ffn1(const float* __restrict__ inp, const float* __restrict__ n2w,
             const float* __restrict__ n2b, const float* __restrict__ b1)
{
    extern __shared__ char smc[];
    float* Xf = (float*)smc;
    bf16* Xh = (bf16*)(smc + 67584);
    bf16* Xl = (bf16*)(smc + 102400);
    bf16* Wh = (bf16*)(smc + 137216);
    bf16* Wl = (bf16*)(smc + 172032);
    float* Cst = (float*)(smc + 137216);
    float* MU = (float*)(smc + 206848);
    float* RS = (float*)(smc + 207360);

    const int tid = threadIdx.x;
    const int pg = blockIdx.x * 128;
    const int b = pg >> 16;
    const int pix = pg & 65535;
    const float* ib = inp + (size_t)b * 128 * HW + pix;

    #pragma unroll
    for (int it = 0; it < 64; ++it) {
        int idx = tid + it * 256;
        int c = idx >> 7, p = idx & 127;
        Xf[c * 132 + p] = ib[c * HW + p];
    }
    __syncthreads();
    {
        int p = tid >> 1, part = tid & 1;
        float s = 0.f, sq = 0.f;
        #pragma unroll
        for (int c = part * 64; c < part * 64 + 64; ++c) {
            float v = Xf[c * 132 + p];
            s += v; sq += v * v;
        }
        s  += __shfl_xor_sync(0xffffffffu, s, 1);
        sq += __shfl_xor_sync(0xffffffffu, sq, 1);
        if (part == 0) {
            float mu = s * (1.f / 128.f);
            float var = sq * (1.f / 128.f) - mu * mu;
            MU[p] = mu;
            RS[p] = rsqrtf(var + 1e-6f);
        }
    }
    __syncthreads();
    #pragma unroll
    for (int it = 0; it < 64; ++it) {
        int idx = tid + it * 256;
        int c = idx >> 7, p = idx & 127;
        float xn = n2w[c] * (Xf[c * 132 + p] - MU[p]) * RS[p] + n2b[c];
        bf16 h, l;
        split_bf16(xn, h, l);
        Xh[c * 136 + p] = h;
        Xl[c * 136 + p] = l;
    }

    const int lane = tid & 31;
    const int warp = tid >> 5;
    const int g = lane >> 2, tg = lane & 3;
    const int mbase = (warp >> 1) * 32;
    const int nbase = (warp & 1) * 64;
    const int laneoff = (lane & 15) * 272 + ((lane >> 4) << 4);

    const u32 smXh = (u32)__cvta_generic_to_shared(Xh);
    const u32 smXl = (u32)__cvta_generic_to_shared(Xl);
    const u32 smWh = (u32)__cvta_generic_to_shared(Wh);
    const u32 smWl = (u32)__cvta_generic_to_shared(Wl);

    for (int och = 0; och < 4; ++och) {
        __syncthreads();
        {
            const u32* wh = (const u32*)&g_w1h[(och * 128) * 128];
            const u32* wl = (const u32*)&g_w1l[(och * 128) * 128];
            u32* dWh = (u32*)Wh;
            u32* dWl = (u32*)Wl;
            #pragma unroll
            for (int it = 0; it < 32; ++it) {
                int idx = tid + it * 256;
                int o = idx >> 6, kk = idx & 63;
                dWh[o * 68 + kk] = wh[o * 64 + kk];
                dWl[o * 68 + kk] = wl[o * 64 + kk];
            }
        }
        __syncthreads();

        float acc[2][8][4];
        #pragma unroll
        for (int mt = 0; mt < 2; ++mt)
            #pragma unroll
            for (int nt = 0; nt < 8; ++nt)
                #pragma unroll
                for (int q = 0; q < 4; ++q) acc[mt][nt][q] = 0.f;

        #pragma unroll
        for (int ks = 0; ks < 8; ++ks) {
            u32 ah[2][4], al[2][4];
            ldsm4(ah[0][0], ah[0][1], ah[0][2], ah[0][3],
                  smWh + laneoff + mbase * 272 + ks * 32);
            ldsm4(ah[1][0], ah[1][1], ah[1][2], ah[1][3],
                  smWh + laneoff + (mbase + 16) * 272 + ks * 32);
            ldsm4(al[0][0], al[0][1], al[0][2], al[0][3],
                  smWl + laneoff + mbase * 272 + ks * 32);
            ldsm4(al[1][0], al[1][1], al[1][2], al[1][3],
                  smWl + laneoff + (mbase + 16) * 272 + ks * 32);
            #pragma unroll
            for (int ntp = 0; ntp < 4; ++ntp) {
                int n0 = nbase + ntp * 16;
                u32 bh[4], bl[4];
                ldsm4t(bh[0], bh[1], bh[2], bh[3],
                       smXh + laneoff + ks * 16 * 272 + n0 * 2);
                ldsm4t(bl[0], bl[1], bl[2], bl[3],
                       smXl + laneoff + ks * 16 * 272 + n0 * 2);
                #pragma unroll
                for (int mt = 0; mt < 2; ++mt) {
                    mma16816(acc[mt][2 * ntp],     ah[mt], bh[0], bh[1]);
                    mma16816(acc[mt][2 * ntp + 1], ah[mt], bh[2], bh[3]);
                    mma16816(acc[mt][2 * ntp],     ah[mt], bl[0], bl[1]);
                    mma16816(acc[mt][2 * ntp + 1], ah[mt], bl[2], bl[3]);
                    mma16816(acc[mt][2 * ntp],     al[mt], bh[0], bh[1]);
                    mma16816(acc[mt][2 * ntp + 1], al[mt], bh[2], bh[3]);
                }
            }
        }
        __syncthreads();
        #pragma unroll
        for (int mt = 0; mt < 2; ++mt) {
            #pragma unroll
            for (int nt = 0; nt < 8; ++nt) {
                int r = mbase + mt * 16 + g;
                int cc = nbase + nt * 8 + tg * 2;
                *(float2*)&Cst[r * 132 + cc] = make_float2(acc[mt][nt][0], acc[mt][nt][1]);
                *(float2*)&Cst[(r + 8) * 132 + cc] = make_float2(acc[mt][nt][2], acc[mt][nt][3]);
            }
        }
        __syncthreads();
        #pragma unroll
        for (int it = 0; it < 64; ++it) {
            int idx = tid + it * 256;
            int o = idx >> 7, p = idx & 127;
            float v = Cst[o * 132 + p] + b1[och * 128 + o];
            g_h1[(size_t)(b * 512 + och * 128 + o) * HW + pix + p] = gelu_exact(v);
        }
    }
}

// ======================= kernel 3: dw3x3 + GELU, 4px/thread, no smem =======
// block: 4 rows x 256 cols of one plane; thread: 4 consecutive px in one row
__global__ __launch_bounds__(256)
void k3_dw(const float* __restrict__ dw, const float* __restrict__ dwb)
{
    const int blk = blockIdx.x;          // plane*64 + rowgroup
    const int plane = blk >> 6;
    const int ch = plane & 511;
    const int rg = blk & 63;
    const int tid = threadIdx.x;
    const int y = rg * 4 + (tid >> 6);
    const int xc = (tid & 63) * 4;
    const float* ip = g_h1 + (size_t)plane * HW;

    float w[9];
    #pragma unroll
    for (int i = 0; i < 9; ++i) w[i] = dw[ch * 9 + i];
    const float bias = dwb[ch];

    float v[3][6];
    #pragma unroll
    for (int dy = 0; dy < 3; ++dy) {
        int yy = y + dy - 1;
        if (yy >= 0 && yy < 256) {
            const float* row = ip + yy * NPLANE + xc;
            float4 m = *(const float4*)row;
            v[dy][1] = m.x; v[dy][2] = m.y; v[dy][3] = m.z; v[dy][4] = m.w;
            v[dy][0] = (xc > 0) ? row[-1] : 0.f;
            v[dy][5] = (xc < 252) ? row[4] : 0.f;
        } else {
            #pragma unroll
            for (int i = 0; i < 6; ++i) v[dy][i] = 0.f;
        }
    }

    bf16 hh[4], ll[4];
    #pragma unroll
    for (int p = 0; p < 4; ++p) {
        float s = bias;
        #pragma unroll
        for (int dy = 0; dy < 3; ++dy)
            s += w[dy * 3 + 0] * v[dy][p] + w[dy * 3 + 1] * v[dy][p + 1]
               + w[dy * 3 + 2] * v[dy][p + 2];
        float r = gelu_exact(s);
        split_bf16(r, hh[p], ll[p]);
    }

    uint2 ph, pl;
    ph.x = (u32)__bfloat16_as_ushort(hh[0]) | ((u32)__bfloat16_as_ushort(hh[1]) << 16);
    ph.y = (u32)__bfloat16_as_ushort(hh[2]) | ((u32)__bfloat16_as_ushort(hh[3]) << 16);
    pl.x = (u32)__bfloat16_as_ushort(ll[0]) | ((u32)__bfloat16_as_ushort(ll[1]) << 16);
    pl.y = (u32)__bfloat16_as_ushort(ll[2]) | ((u32)__bfloat16_as_ushort(ll[3]) << 16);
    size_t off = (size_t)plane * HW + y * NPLANE + xc;
    *(uint2*)&g_h2h[off] = ph;
    *(uint2*)&g_h2l[off] = pl;
}

// ======================= kernel 4: W2 + residual (tensor) ==================
#define SM4_BYTES 139264

__global__ __launch_bounds__(256, 1)
void k4_ffn2(const float* __restrict__ b2, float* __restrict__ io)
{
    extern __shared__ char smc[];
    bf16* Xh = (bf16*)smc;
    bf16* Xl = (bf16*)(smc + 34816);
    bf16* Wh = (bf16*)(smc + 69632);
    bf16* Wl = (bf16*)(smc + 104448);
    float* Cst = (float*)smc;

    const int tid = threadIdx.x;
    const int pg = blockIdx.x * 128;
    const int b = pg >> 16;
    const int pix = pg & 65535;

    const int lane = tid & 31;
    const int warp = tid >> 5;
    const int g = lane >> 2, tg = lane & 3;
    const int mbase = (warp >> 1) * 32;
    const int nbase = (warp & 1) * 64;
    const int laneoff = (lane & 15) * 272 + ((lane >> 4) << 4);

    const u32 smXh = (u32)__cvta_generic_to_shared(Xh);
    const u32 smXl = (u32)__cvta_generic_to_shared(Xl);
    const u32 smWh = (u32)__cvta_generic_to_shared(Wh);
    const u32 smWl = (u32)__cvta_generic_to_shared(Wl);

    float acc[2][8][4];
    #pragma unroll
    for (int mt = 0; mt < 2; ++mt)
        #pragma unroll
        for (int nt = 0; nt < 8; ++nt)
            #pragma unroll
            for (int q = 0; q < 4; ++q) acc[mt][nt][q] = 0.f;

    for (int kc = 0; kc < 4; ++kc) {
        __syncthreads();
        {
            const u32* xh = (const u32*)&g_h2h[((size_t)(b * 512 + kc * 128)) * HW + pix];
            const u32* xl = (const u32*)&g_h2l[((size_t)(b * 512 + kc * 128)) * HW + pix];
            u32* dXh = (u32*)Xh;
            u32* dXl = (u32*)Xl;
            #pragma unroll
            for (int it = 0; it < 32; ++it) {
                int idx = tid + it * 256;
                int k = idx >> 6, pp = idx & 63;
                dXh[k * 68 + pp] = xh[(size_t)k * (HW / 2) + pp];
                dXl[k * 68 + pp] = xl[(size_t)k * (HW / 2) + pp];
            }
            const u32* wh = (const u32*)&g_w2h[kc * 128];
            const u32* wl = (const u32*)&g_w2l[kc * 128];
            u32* dWh = (u32*)Wh;
            u32* dWl = (u32*)Wl;
            #pragma unroll
            for (int it = 0; it < 32; ++it) {
                int idx = tid + it * 256;
                int o = idx >> 6, kk = idx & 63;
                dWh[o * 68 + kk] = wh[o * 256 + kk];
                dWl[o * 68 + kk] = wl[o * 256 + kk];
            }
        }
        __syncthreads();

        #pragma unroll
        for (int ks = 0; ks < 8; ++ks) {
            u32 ah[2][4], al[2][4];
            ldsm4(ah[0][0], ah[0][1], ah[0][2], ah[0][3],
                  smWh + laneoff + mbase * 272 + ks * 32);
            ldsm4(ah[1][0], ah[1][1], ah[1][2], ah[1][3],
                  smWh + laneoff + (mbase + 16) * 272 + ks * 32);
            ldsm4(al[0][0], al[0][1], al[0][2], al[0][3],
                  smWl + laneoff + mbase * 272 + ks * 32);
            ldsm4(al[1][0], al[1][1], al[1][2], al[1][3],
                  smWl + laneoff + (mbase + 16) * 272 + ks * 32);
            #pragma unroll
            for (int ntp = 0; ntp < 4; ++ntp) {
                int n0 = nbase + ntp * 16;
                u32 bh[4], bl[4];
                ldsm4t(bh[0], bh[1], bh[2], bh[3],
                       smXh + laneoff + ks * 16 * 272 + n0 * 2);
                ldsm4t(bl[0], bl[1], bl[2], bl[3],
                       smXl + laneoff + ks * 16 * 272 + n0 * 2);
                #pragma unroll
                for (int mt = 0; mt < 2; ++mt) {
                    mma16816(acc[mt][2 * ntp],     ah[mt], bh[0], bh[1]);
                    mma16816(acc[mt][2 * ntp + 1], ah[mt], bh[2], bh[3]);
                    mma16816(acc[mt][2 * ntp],     ah[mt], bl[0], bl[1]);
                    mma16816(acc[mt][2 * ntp + 1], ah[mt], bl[2], bl[3]);
                    mma16816(acc[mt][2 * ntp],     al[mt], bh[0], bh[1]);
                    mma16816(acc[mt][2 * ntp + 1], al[mt], bh[2], bh[3]);
                }
            }
        }
    }

    __syncthreads();
    #pragma unroll
    for (int mt = 0; mt < 2; ++mt) {
        #pragma unroll
        for (int nt = 0; nt < 8; ++nt) {
            int r = mbase + mt * 16 + g;
            int cc = nbase + nt * 8 + tg * 2;
            *(float2*)&Cst[r * 132 + cc] = make_float2(acc[mt][nt][0], acc[mt][nt][1]);
            *(float2*)&Cst[(r + 8) * 132 + cc] = make_float2(acc[mt][nt][2], acc[mt][nt][3]);
        }
    }
    __syncthreads();
    #pragma unroll
    for (int it = 0; it < 64; ++it) {
        int idx = tid + it * 256;
        int o = idx >> 7, p = idx & 127;
        size_t ad = (size_t)(b * 128 + o) * HW + pix + p;
        io[ad] = io[ad] + Cst[o * 132 + p] + b2[o];
    }
}

// ---------------------------------------------------------------------------
extern "C" void kernel_launch(void* const* d_in, const int* in_sizes, int n_in,
                              void* d_out, int out_size)
{
    const float* x    = (const float*)d_in[0];
    const float* l0   = (const float*)d_in[1];
    const float* n1w  = (const float*)d_in[2];
    const float* n1b  = (const float*)d_in[3];
    const float* n2w  = (const float*)d_in[4];
    const float* n2b  = (const float*)d_in[5];
    const float* qkvw = (const float*)d_in[6];
    const float* gw   = (const float*)d_in[7];
    const float* gb   = (const float*)d_in[8];
    const float* pw   = (const float*)d_in[9];
    const float* pb   = (const float*)d_in[10];
    const float* w1   = (const float*)d_in[11];
    const float* b1   = (const float*)d_in[12];
    const float* dw   = (const float*)d_in[13];
    const float* dwb  = (const float*)d_in[14];
    const float* w2   = (const float*)d_in[15];
    const float* b2   = (const float*)d_in[16];
    float* out = (float*)d_out;

    cudaFuncSetAttribute(k1_attn, cudaFuncAttributeMaxDynamicSharedMemorySize, SM1_BYTES);
    cudaFuncSetAttribute(k2_ffn1, cudaFuncAttributeMaxDynamicSharedMemorySize, SM2_BYTES);
    cudaFuncSetAttribute(k4_ffn2, cudaFuncAttributeMaxDynamicSharedMemorySize, SM4_BYTES);

    k0_prep<<<512, 256>>>(w1, w2);
    k1_attn<<<4096, 256, SM1_BYTES>>>(x, l0, n1w, n1b, qkvw, gw, gb, pw, pb, out);
    k2_ffn1<<<2048, 256, SM2_BYTES>>>(out, n2w, n2b, b1);
    k3_dw<<<131072, 256>>>(dw, dwb);
    k4_ffn2<<<2048, 256, SM4_BYTES>>>(b2, out);
}

// round 10
// speedup vs baseline: 1.4947x; 1.1839x over previous
#include <cuda_runtime.h>
#include <cuda_bf16.h>
#include <math.h>

// ---------------------------------------------------------------------------
// IGAB block, B=4, C=128, H=W=256, window 8x8, heads=8, head_dim=16, HIDDEN=512
//   k0: pre-split qkvw/pw/w1/w2 into bf16 hi/lo (once per launch)
//   k1: LN1 + QKV(MMA) + gate + window-attention(FFMA2) + proj(MMA) + residual
//   k2: LN2 + W1 + GELU   -> bf16 2-term split MMA, ldmatrix
//   k3: depthwise 3x3 + bias + GELU -> 4px/thread, no smem, writes bf16 hi/lo
//   k4: W2 + bias + residual -> bf16 2-term split MMA, ldmatrix
// ---------------------------------------------------------------------------

#define HW 65536
#define NPLANE 256

__device__ float g_h1[(size_t)4 * 512 * HW];            // fp32 for k3
__device__ __nv_bfloat16 g_h2h[(size_t)4 * 512 * HW];   // split for k4
__device__ __nv_bfloat16 g_h2l[(size_t)4 * 512 * HW];
__device__ __nv_bfloat16 g_w1h[512 * 128], g_w1l[512 * 128];
__device__ __nv_bfloat16 g_w2h[128 * 512], g_w2l[128 * 512];
__device__ __nv_bfloat16 g_qkvh[384 * 128], g_qkvl[384 * 128];
__device__ __nv_bfloat16 g_pwh[128 * 128], g_pwl[128 * 128];

typedef unsigned long long u64;
typedef unsigned int u32;
typedef __nv_bfloat16 bf16;

__device__ __forceinline__ u64 ffma2(u64 a, u64 b, u64 c) {
    u64 d;
    asm("fma.rn.f32x2 %0, %1, %2, %3;" : "=l"(d) : "l"(a), "l"(b), "l"(c));
    return d;
}
__device__ __forceinline__ float2 unpack2(u64 v) {
    unsigned lo, hi;
    asm("mov.b64 {%0, %1}, %2;" : "=r"(lo), "=r"(hi) : "l"(v));
    return make_float2(__uint_as_float(lo), __uint_as_float(hi));
}
__device__ __forceinline__ float gelu_exact(float v) {
    return 0.5f * v * (1.0f + erff(v * 0.70710678118654752f));
}
__device__ __forceinline__ void mma16816(float* c, const u32* a, u32 b0, u32 b1) {
    asm volatile(
        "mma.sync.aligned.m16n8k16.row.col.f32.bf16.bf16.f32 "
        "{%0,%1,%2,%3},{%4,%5,%6,%7},{%8,%9},{%0,%1,%2,%3};"
        : "+f"(c[0]), "+f"(c[1]), "+f"(c[2]), "+f"(c[3])
        : "r"(a[0]), "r"(a[1]), "r"(a[2]), "r"(a[3]), "r"(b0), "r"(b1));
}
__device__ __forceinline__ void ldsm4(u32& d0, u32& d1, u32& d2, u32& d3, u32 a) {
    asm volatile("ldmatrix.sync.aligned.m8n8.x4.shared.b16 {%0,%1,%2,%3},[%4];"
                 : "=r"(d0), "=r"(d1), "=r"(d2), "=r"(d3) : "r"(a));
}
__device__ __forceinline__ void ldsm4t(u32& d0, u32& d1, u32& d2, u32& d3, u32 a) {
    asm volatile("ldmatrix.sync.aligned.m8n8.x4.trans.shared.b16 {%0,%1,%2,%3},[%4];"
                 : "=r"(d0), "=r"(d1), "=r"(d2), "=r"(d3) : "r"(a));
}
__device__ __forceinline__ void split_bf16(float v, bf16& h, bf16& l) {
    h = __float2bfloat16(v);
    l = __float2bfloat16(v - __bfloat162float(h));
}

// ======================= kernel 0: weight pre-split ========================
__global__ __launch_bounds__(256)
void k0_prep(const float* __restrict__ w1, const float* __restrict__ w2,
             const float* __restrict__ qkvw, const float* __restrict__ pw)
{
    int i = blockIdx.x * 256 + threadIdx.x;      // 196608 total
    bf16 h, l;
    if (i < 65536) {
        split_bf16(w1[i], h, l);
        g_w1h[i] = h; g_w1l[i] = l;
    } else if (i < 131072) {
        int j = i - 65536;
        split_bf16(w2[j], h, l);
        g_w2h[j] = h; g_w2l[j] = l;
    } else if (i < 180224) {
        int j = i - 131072;
        split_bf16(qkvw[j], h, l);
        g_qkvh[j] = h; g_qkvl[j] = l;
    } else {
        int j = i - 180224;
        split_bf16(pw[j], h, l);
        g_pwh[j] = h; g_pwl[j] = l;
    }
}

// ======================= kernel 1: attention block (MMA GEMMs) =============
// smem byte layout (total 211968):
//   Af   f32 [128][68]   @ 0        (raw x, residual)
//   Xh   bf16[128][72]   @ 34816    (LN out; later attn out)
//   Xl                @ 53248
//   Wh   bf16[64][136]   @ 71680    (aliases Sf)
//   Wl                @ 89088
//   Qf   f32 [128][68]   @ 106496   (aliases Cst for proj staging)
//   Kf   f32 [128][68]   @ 141312
//   Vf   f32 [128][68]   @ 176128
//   Sf   f32 [64][68]    @ 71680
//   L0 @ 210944, MU @ 211200, RS @ 211456, DEN @ 211712
#define SM1_BYTES 211968

__global__ __launch_bounds__(256, 1)
void k1_attn(const float* __restrict__ x, const float* __restrict__ l0,
             const float* __restrict__ n1w, const float* __restrict__ n1b,
             const float* __restrict__ gw, const float* __restrict__ gb,
             const float* __restrict__ pb, float* __restrict__ outp)
{
    extern __shared__ float sm[];
    char* smcc = (char*)sm;
    float* Af = sm;
    bf16* Xh = (bf16*)(smcc + 34816);
    bf16* Xl = (bf16*)(smcc + 53248);
    bf16* Wh = (bf16*)(smcc + 71680);
    bf16* Wl = (bf16*)(smcc + 89088);
    float* Qf = sm + 26624;
    float* Kf = sm + 35328;
    float* Vf = sm + 44032;
    float* Sf = sm + 17920;
    float* Cst = Qf;
    float* L0v = sm + 52736;
    float* MUv = sm + 52800;
    float* RSv = sm + 52864;
    float* DENv = sm + 52928;

    const int tid = threadIdx.x;
    const int wi = blockIdx.x;
    const int b  = wi >> 10;
    const int hi = (wi >> 5) & 31;
    const int wj = wi & 31;
    const int base_pix = (hi * 8) * NPLANE + wj * 8;
    const float* xb = x + (size_t)b * 128 * HW;

    // load raw x tile [128 ch][64 px]
    #pragma unroll
    for (int it = 0; it < 32; ++it) {
        int idx = tid + it * 256;
        int c = idx >> 6, p = idx & 63;
        Af[c * 68 + p] = xb[c * HW + base_pix + (p >> 3) * NPLANE + (p & 7)];
    }
    if (tid < 64) {
        int p = tid;
        L0v[p] = l0[(size_t)b * HW + base_pix + (p >> 3) * NPLANE + (p & 7)];
    }
    __syncthreads();

    {   // LN1 stats
        int p = tid >> 2, part = tid & 3;
        float s = 0.f, sq = 0.f;
        #pragma unroll
        for (int c = part * 32; c < part * 32 + 32; ++c) {
            float v = Af[c * 68 + p];
            s += v; sq += v * v;
        }
        s  += __shfl_xor_sync(0xffffffffu, s, 1);
        sq += __shfl_xor_sync(0xffffffffu, sq, 1);
        s  += __shfl_xor_sync(0xffffffffu, s, 2);
        sq += __shfl_xor_sync(0xffffffffu, sq, 2);
        if (part == 0) {
            float mu = s * (1.f / 128.f);
            float var = sq * (1.f / 128.f) - mu * mu;
            MUv[p] = mu;
            RSv[p] = rsqrtf(var + 1e-6f);
        }
    }
    __syncthreads();
    // LN normalize + bf16 split into [c][72]
    #pragma unroll
    for (int it = 0; it < 32; ++it) {
        int idx = tid + it * 256;
        int c = idx >> 6, p = idx & 63;
        float xn = n1w[c] * (Af[c * 68 + p] - MUv[p]) * RSv[p] + n1b[c];
        bf16 h, l;
        split_bf16(xn, h, l);
        Xh[c * 72 + p] = h;
        Xl[c * 72 + p] = l;
    }

    const int lane = tid & 31;
    const int warp = tid >> 5;
    const int g = lane >> 2, tg = lane & 3;
    const int mwarp = warp >> 1;        // 0..3 -> 16 rows each
    const int nwarp = warp & 1;         // 0..1 -> 32 px cols each
    const int laneW = (lane & 15) * 272 + ((lane >> 4) << 4);
    const int laneX = (lane & 15) * 144 + ((lane >> 4) << 4);

    const u32 smXh = (u32)__cvta_generic_to_shared(Xh);
    const u32 smXl = (u32)__cvta_generic_to_shared(Xl);
    const u32 smWh = (u32)__cvta_generic_to_shared(Wh);
    const u32 smWl = (u32)__cvta_generic_to_shared(Wl);

    // ---- QKV: 6 chunks of 64 outs, tensor-core MMA ----
    for (int ch = 0; ch < 6; ++ch) {
        __syncthreads();
        {   // copy pre-split W chunk [64][128] -> [64][136]
            const u32* wh = (const u32*)&g_qkvh[ch * 64 * 128];
            const u32* wl = (const u32*)&g_qkvl[ch * 64 * 128];
            u32* dWh = (u32*)Wh;
            u32* dWl = (u32*)Wl;
            #pragma unroll
            for (int it = 0; it < 16; ++it) {
                int idx = tid + it * 256;
                int o = idx >> 6, kk = idx & 63;
                dWh[o * 68 + kk] = wh[o * 64 + kk];
                dWl[o * 68 + kk] = wl[o * 64 + kk];
            }
        }
        __syncthreads();

        float acc[4][4];
        #pragma unroll
        for (int nt = 0; nt < 4; ++nt)
            #pragma unroll
            for (int q = 0; q < 4; ++q) acc[nt][q] = 0.f;

        #pragma unroll
        for (int ks = 0; ks < 8; ++ks) {
            u32 ah[4], al[4];
            ldsm4(ah[0], ah[1], ah[2], ah[3], smWh + laneW + mwarp * 16 * 272 + ks * 32);
            ldsm4(al[0], al[1], al[2], al[3], smWl + laneW + mwarp * 16 * 272 + ks * 32);
            #pragma unroll
            for (int ntp = 0; ntp < 2; ++ntp) {
                int n0 = nwarp * 32 + ntp * 16;
                u32 bh[4], bl[4];
                ldsm4t(bh[0], bh[1], bh[2], bh[3], smXh + laneX + ks * 16 * 144 + n0 * 2);
                ldsm4t(bl[0], bl[1], bl[2], bl[3], smXl + laneX + ks * 16 * 144 + n0 * 2);
                mma16816(acc[2 * ntp],     ah, bh[0], bh[1]);
                mma16816(acc[2 * ntp + 1], ah, bh[2], bh[3]);
                mma16816(acc[2 * ntp],     ah, bl[0], bl[1]);
                mma16816(acc[2 * ntp + 1], ah, bl[2], bl[3]);
                mma16816(acc[2 * ntp],     al, bh[0], bh[1]);
                mma16816(acc[2 * ntp + 1], al, bh[2], bh[3]);
            }
        }

        // epilogue -> Q/K/V f32 smem
        float* dst = (ch < 2) ? Qf : (ch < 4) ? Kf : Vf;
        int rloc = (ch & 1) * 64 + mwarp * 16;      // row within 128
        int r0 = rloc + g, r1 = rloc + g + 8;
        if (ch < 2) {
            float gw0 = gw[r0], gb0 = gb[r0];
            float gw1 = gw[r1], gb1 = gb[r1];
            #pragma unroll
            for (int nt = 0; nt < 4; ++nt) {
                int col = nwarp * 32 + nt * 8 + tg * 2;
                float la = L0v[col], lb = L0v[col + 1];
                float s00 = 1.f / (1.f + __expf(-(la * gw0 + gb0)));
                float s01 = 1.f / (1.f + __expf(-(lb * gw0 + gb0)));
                float s10 = 1.f / (1.f + __expf(-(la * gw1 + gb1)));
                float s11 = 1.f / (1.f + __expf(-(lb * gw1 + gb1)));
                *(float2*)&dst[r0 * 68 + col] = make_float2(acc[nt][0] * s00, acc[nt][1] * s01);
                *(float2*)&dst[r1 * 68 + col] = make_float2(acc[nt][2] * s10, acc[nt][3] * s11);
            }
        } else {
            #pragma unroll
            for (int nt = 0; nt < 4; ++nt) {
                int col = nwarp * 32 + nt * 8 + tg * 2;
                *(float2*)&dst[r0 * 68 + col] = make_float2(acc[nt][0], acc[nt][1]);
                *(float2*)&dst[r1 * 68 + col] = make_float2(acc[nt][2], acc[nt][3]);
            }
        }
    }
    __syncthreads();

    // ---- window attention (FFMA2), output -> bf16 split in Xh/Xl ----
    for (int h = 0; h < 8; ++h) {
        const int cb = h * 16;
        {   // S = scale * Q K^T
            const int tx = tid & 15, ty = tid >> 4;
            u64 acc2[2][4];
            #pragma unroll
            for (int i = 0; i < 2; ++i)
                #pragma unroll
                for (int j = 0; j < 4; ++j) acc2[i][j] = 0ull;
            #pragma unroll
            for (int d = 0; d < 16; ++d) {
                ulonglong2 qv = *(const ulonglong2*)&Qf[(cb + d) * 68 + 4 * tx];
                #pragma unroll
                for (int j = 0; j < 4; ++j) {
                    float kvs = Kf[(cb + d) * 68 + 4 * ty + j];
                    u64 kp;
                    asm("mov.b64 %0, {%1, %1};" : "=l"(kp) : "r"(__float_as_uint(kvs)));
                    acc2[0][j] = ffma2(qv.x, kp, acc2[0][j]);
                    acc2[1][j] = ffma2(qv.y, kp, acc2[1][j]);
                }
            }
            #pragma unroll
            for (int a = 0; a < 2; ++a)
                #pragma unroll
                for (int j = 0; j < 4; ++j) {
                    float2 f = unpack2(acc2[a][j]);
                    Sf[(4 * tx + 2 * a) * 68 + 4 * ty + j] = f.x * 0.25f;
                    Sf[(4 * tx + 2 * a + 1) * 68 + 4 * ty + j] = f.y * 0.25f;
                }
        }
        __syncthreads();
        {   // softmax rows
            int r = tid >> 2, part = tid & 3;
            float m = -1e30f;
            #pragma unroll
            for (int kk = part * 16; kk < part * 16 + 16; ++kk)
                m = fmaxf(m, Sf[r * 68 + kk]);
            m = fmaxf(m, __shfl_xor_sync(0xffffffffu, m, 1));
            m = fmaxf(m, __shfl_xor_sync(0xffffffffu, m, 2));
            float s = 0.f;
            #pragma unroll
            for (int kk = part * 16; kk < part * 16 + 16; ++kk) {
                float e = __expf(Sf[r * 68 + kk] - m);
                Sf[r * 68 + kk] = e;
                s += e;
            }
            s += __shfl_xor_sync(0xffffffffu, s, 1);
            s += __shfl_xor_sync(0xffffffffu, s, 2);
            if (part == 0) DENv[r] = 1.f / s;
        }
        __syncthreads();
        {   // O = P V -> bf16 split [c][72]
            int pq = tid >> 2, dg = tid & 3;
            const u64* Srow = (const u64*)&Sf[pq * 68];
            const u64* V0 = (const u64*)&Vf[(cb + 4 * dg + 0) * 68];
            const u64* V1 = (const u64*)&Vf[(cb + 4 * dg + 1) * 68];
            const u64* V2 = (const u64*)&Vf[(cb + 4 * dg + 2) * 68];
            const u64* V3 = (const u64*)&Vf[(cb + 4 * dg + 3) * 68];
            u64 a0 = 0ull, a1 = 0ull, a2 = 0ull, a3 = 0ull;
            #pragma unroll 8
            for (int kk = 0; kk < 32; ++kk) {
                u64 prp = Srow[kk];
                a0 = ffma2(prp, V0[kk], a0);
                a1 = ffma2(prp, V1[kk], a1);
                a2 = ffma2(prp, V2[kk], a2);
                a3 = ffma2(prp, V3[kk], a3);
            }
            float dn = DENv[pq];
            float2 f0 = unpack2(a0), f1 = unpack2(a1), f2 = unpack2(a2), f3 = unpack2(a3);
            bf16 h_, l_;
            split_bf16((f0.x + f0.y) * dn, h_, l_);
            Xh[(cb + 4 * dg + 0) * 72 + pq] = h_; Xl[(cb + 4 * dg + 0) * 72 + pq] = l_;
            split_bf16((f1.x + f1.y) * dn, h_, l_);
            Xh[(cb + 4 * dg + 1) * 72 + pq] = h_; Xl[(cb + 4 * dg + 1) * 72 + pq] = l_;
            split_bf16((f2.x + f2.y) * dn, h_, l_);
            Xh[(cb + 4 * dg + 2) * 72 + pq] = h_; Xl[(cb + 4 * dg + 2) * 72 + pq] = l_;
            split_bf16((f3.x + f3.y) * dn, h_, l_);
            Xh[(cb + 4 * dg + 3) * 72 + pq] = h_; Xl[(cb + 4 * dg + 3) * 72 + pq] = l_;
        }
        __syncthreads();
    }

    // ---- proj (MMA) + bias + residual ----
    for (int ch = 0; ch < 2; ++ch) {
        __syncthreads();
        {
            const u32* wh = (const u32*)&g_pwh[ch * 64 * 128];
            const u32* wl = (const u32*)&g_pwl[ch * 64 * 128];
            u32* dWh = (u32*)Wh;
            u32* dWl = (u32*)Wl;
            #pragma unroll
            for (int it = 0; it < 16; ++it) {
                int idx = tid + it * 256;
                int o = idx >> 6, kk = idx & 63;
                dWh[o * 68 + kk] = wh[o * 64 + kk];
                dWl[o * 68 + kk] = wl[o * 64 + kk];
            }
        }
        __syncthreads();

        float acc[4][4];
        #pragma unroll
        for (int nt = 0; nt < 4; ++nt)
            #pragma unroll
            for (int q = 0; q < 4; ++q) acc[nt][q] = 0.f;

        #pragma unroll
        for (int ks = 0; ks < 8; ++ks) {
            u32 ah[4], al[4];
            ldsm4(ah[0], ah[1], ah[2], ah[3], smWh + laneW + mwarp * 16 * 272 + ks * 32);
            ldsm4(al[0], al[1], al[2], al[3], smWl + laneW + mwarp * 16 * 272 + ks * 32);
            #pragma unroll
            for (int ntp = 0; ntp < 2; ++ntp) {
                int n0 = nwarp * 32 + ntp * 16;
                u32 bh[4], bl[4];
                ldsm4t(bh[0], bh[1], bh[2], bh[3], smXh + laneX + ks * 16 * 144 + n0 * 2);
                ldsm4t(bl[0], bl[1], bl[2], bl[3], smXl + laneX + ks * 16 * 144 + n0 * 2);
                mma16816(acc[2 * ntp],     ah, bh[0], bh[1]);
                mma16816(acc[2 * ntp + 1], ah, bh[2], bh[3]);
                mma16816(acc[2 * ntp],     ah, bl[0], bl[1]);
                mma16816(acc[2 * ntp + 1], ah, bl[2], bl[3]);
                mma16816(acc[2 * ntp],     al, bh[0], bh[1]);
                mma16816(acc[2 * ntp + 1], al, bh[2], bh[3]);
            }
        }

        // stage into Cst (=Qf region, free after attention)
        int r0 = mwarp * 16 + g, r1 = r0 + 8;
        #pragma unroll
        for (int nt = 0; nt < 4; ++nt) {
            int col = nwarp * 32 + nt * 8 + tg * 2;
            *(float2*)&Cst[r0 * 68 + col] = make_float2(acc[nt][0], acc[nt][1]);
            *(float2*)&Cst[r1 * 68 + col] = make_float2(acc[nt][2], acc[nt][3]);
        }
        __syncthreads();
        #pragma unroll
        for (int it = 0; it < 16; ++it) {
            int idx = tid + it * 256;
            int ol = idx >> 6, p = idx & 63;
            int o = ch * 64 + ol;
            float v = Cst[ol * 68 + p] + pb[o] + Af[o * 68 + p];
            outp[(size_t)(b * 128 + o) * HW + base_pix + (p >> 3) * NPLANE + (p & 7)] = v;
        }
    }
}

// ======================= kernel 2: LN2 + W1 + GELU (tensor) ================
#define SM2_BYTES 207872

__global__ __launch_bounds__(256, 1)
void k2_ffn1(const float* __restrict__ inp, const float* __restrict__ n2w,
             const float* __restrict__ n2b, const float* __restrict__ b1)
{
    extern __shared__ char smc[];
    float* Xf = (float*)smc;
    bf16* Xh = (bf16*)(smc + 67584);
    bf16* Xl = (bf16*)(smc + 102400);
    bf16* Wh = (bf16*)(smc + 137216);
    bf16* Wl = (bf16*)(smc + 172032);
    float* Cst = (float*)(smc + 137216);
    float* MU = (float*)(smc + 206848);
    float* RS = (float*)(smc + 207360);

    const int tid = threadIdx.x;
    const int pg = blockIdx.x * 128;
    const int b = pg >> 16;
    const int pix = pg & 65535;
    const float* ib = inp + (size_t)b * 128 * HW + pix;

    #pragma unroll
    for (int it = 0; it < 64; ++it) {
        int idx = tid + it * 256;
        int c = idx >> 7, p = idx & 127;
        Xf[c * 132 + p] = ib[c * HW + p];
    }
    __syncthreads();
    {
        int p = tid >> 1, part = tid & 1;
        float s = 0.f, sq = 0.f;
        #pragma unroll
        for (int c = part * 64; c < part * 64 + 64; ++c) {
            float v = Xf[c * 132 + p];
            s += v; sq += v * v;
        }
        s  += __shfl_xor_sync(0xffffffffu, s, 1);
        sq += __shfl_xor_sync(0xffffffffu, sq, 1);
        if (part == 0) {
            float mu = s * (1.f / 128.f);
            float var = sq * (1.f / 128.f) - mu * mu;
            MU[p] = mu;
            RS[p] = rsqrtf(var + 1e-6f);
        }
    }
    __syncthreads();
    #pragma unroll
    for (int it = 0; it < 64; ++it) {
        int idx = tid + it * 256;
        int c = idx >> 7, p = idx & 127;
        float xn = n2w[c] * (Xf[c * 132 + p] - MU[p]) * RS[p] + n2b[c];
        bf16 h, l;
        split_bf16(xn, h, l);
        Xh[c * 136 + p] = h;
        Xl[c * 136 + p] = l;
    }

    const int lane = tid & 31;
    const int warp = tid >> 5;
    const int g = lane >> 2, tg = lane & 3;
    const int mbase = (warp >> 1) * 32;
    const int nbase = (warp & 1) * 64;
    const int laneoff = (lane & 15) * 272 + ((lane >> 4) << 4);

    const u32 smXh = (u32)__cvta_generic_to_shared(Xh);
    const u32 smXl = (u32)__cvta_generic_to_shared(Xl);
    const u32 smWh = (u32)__cvta_generic_to_shared(Wh);
    const u32 smWl = (u32)__cvta_generic_to_shared(Wl);

    for (int och = 0; och < 4; ++och) {
        __syncthreads();
        {
            const u32* wh = (const u32*)&g_w1h[(och * 128) * 128];
            const u32* wl = (const u32*)&g_w1l[(och * 128) * 128];
            u32* dWh = (u32*)Wh;
            u32* dWl = (u32*)Wl;
            #pragma unroll
            for (int it = 0; it < 32; ++it) {
                int idx = tid + it * 256;
                int o = idx >> 6, kk = idx & 63;
                dWh[o * 68 + kk] = wh[o * 64 + kk];
                dWl[o * 68 + kk] = wl[o * 64 + kk];
            }
        }
        __syncthreads();

        float acc[2][8][4];
        #pragma unroll
        for (int mt = 0; mt < 2; ++mt)
            #pragma unroll
            for (int nt = 0; nt < 8; ++nt)
                #pragma unroll
                for (int q = 0; q < 4; ++q) acc[mt][nt][q] = 0.f;

        #pragma unroll
        for (int ks = 0; ks < 8; ++ks) {
            u32 ah[2][4], al[2][4];
            ldsm4(ah[0][0], ah[0][1], ah[0][2], ah[0][3],
                  smWh + laneoff + mbase * 272 + ks * 32);
            ldsm4(ah[1][0], ah[1][1], ah[1][2], ah[1][3],
                  smWh + laneoff + (mbase + 16) * 272 + ks * 32);
            ldsm4(al[0][0], al[0][1], al[0][2], al[0][3],
                  smWl + laneoff + mbase * 272 + ks * 32);
            ldsm4(al[1][0], al[1][1], al[1][2], al[1][3],
                  smWl + laneoff + (mbase + 16) * 272 + ks * 32);
            #pragma unroll
            for (int ntp = 0; ntp < 4; ++ntp) {
                int n0 = nbase + ntp * 16;
                u32 bh[4], bl[4];
                ldsm4t(bh[0], bh[1], bh[2], bh[3],
                       smXh + laneoff + ks * 16 * 272 + n0 * 2);
                ldsm4t(bl[0], bl[1], bl[2], bl[3],
                       smXl + laneoff + ks * 16 * 272 + n0 * 2);
                #pragma unroll
                for (int mt = 0; mt < 2; ++mt) {
                    mma16816(acc[mt][2 * ntp],     ah[mt], bh[0], bh[1]);
                    mma16816(acc[mt][2 * ntp + 1], ah[mt], bh[2], bh[3]);
                    mma16816(acc[mt][2 * ntp],     ah[mt], bl[0], bl[1]);
                    mma16816(acc[mt][2 * ntp + 1], ah[mt], bl[2], bl[3]);
                    mma16816(acc[mt][2 * ntp],     al[mt], bh[0], bh[1]);
                    mma16816(acc[mt][2 * ntp + 1], al[mt], bh[2], bh[3]);
                }
            }
        }
        __syncthreads();
        #pragma unroll
        for (int mt = 0; mt < 2; ++mt) {
            #pragma unroll
            for (int nt = 0; nt < 8; ++nt) {
                int r = mbase + mt * 16 + g;
                int cc = nbase + nt * 8 + tg * 2;
                *(float2*)&Cst[r * 132 + cc] = make_float2(acc[mt][nt][0], acc[mt][nt][1]);
                *(float2*)&Cst[(r + 8) * 132 + cc] = make_float2(acc[mt][nt][2], acc[mt][nt][3]);
            }
        }
        __syncthreads();
        #pragma unroll
        for (int it = 0; it < 64; ++it) {
            int idx = tid + it * 256;
            int o = idx >> 7, p = idx & 127;
            float v = Cst[o * 132 + p] + b1[och * 128 + o];
            g_h1[(size_t)(b * 512 + och * 128 + o) * HW + pix + p] = gelu_exact(v);
        }
    }
}

// ======================= kernel 3: dw3x3 + GELU, 4px/thread ================
__global__ __launch_bounds__(256)
void k3_dw(const float* __restrict__ dw, const float* __restrict__ dwb)
{
    const int blk = blockIdx.x;
    const int plane = blk >> 6;
    const int ch = plane & 511;
    const int rg = blk & 63;
    const int tid = threadIdx.x;
    const int y = rg * 4 + (tid >> 6);
    const int xc = (tid & 63) * 4;
    const float* ip = g_h1 + (size_t)plane * HW;

    float w[9];
    #pragma unroll
    for (int i = 0; i < 9; ++i) w[i] = dw[ch * 9 + i];
    const float bias = dwb[ch];

    float v[3][6];
    #pragma unroll
    for (int dy = 0; dy < 3; ++dy) {
        int yy = y + dy - 1;
        if (yy >= 0 && yy < 256) {
            const float* row = ip + yy * NPLANE + xc;
            float4 m = *(const float4*)row;
            v[dy][1] = m.x; v[dy][2] = m.y; v[dy][3] = m.z; v[dy][4] = m.w;
            v[dy][0] = (xc > 0) ? row[-1] : 0.f;
            v[dy][5] = (xc < 252) ? row[4] : 0.f;
        } else {
            #pragma unroll
            for (int i = 0; i < 6; ++i) v[dy][i] = 0.f;
        }
    }

    bf16 hh[4], ll[4];
    #pragma unroll
    for (int p = 0; p < 4; ++p) {
        float s = bias;
        #pragma unroll
        for (int dy = 0; dy < 3; ++dy)
            s += w[dy * 3 + 0] * v[dy][p] + w[dy * 3 + 1] * v[dy][p + 1]
               + w[dy * 3 + 2] * v[dy][p + 2];
        float r = gelu_exact(s);
        split_bf16(r, hh[p], ll[p]);
    }

    uint2 ph, pl;
    ph.x = (u32)__bfloat16_as_ushort(hh[0]) | ((u32)__bfloat16_as_ushort(hh[1]) << 16);
    ph.y = (u32)__bfloat16_as_ushort(hh[2]) | ((u32)__bfloat16_as_ushort(hh[3]) << 16);
    pl.x = (u32)__bfloat16_as_ushort(ll[0]) | ((u32)__bfloat16_as_ushort(ll[1]) << 16);
    pl.y = (u32)__bfloat16_as_ushort(ll[2]) | ((u32)__bfloat16_as_ushort(ll[3]) << 16);
    size_t off = (size_t)plane * HW + y * NPLANE + xc;
    *(uint2*)&g_h2h[off] = ph;
    *(uint2*)&g_h2l[off] = pl;
}

// ======================= kernel 4: W2 + residual (tensor) ==================
#define SM4_BYTES 139264

__global__ __launch_bounds__(256, 1)
void k4_ffn2(const float* __restrict__ b2, float* __restrict__ io)
{
    extern __shared__ char smc[];
    bf16* Xh = (bf16*)smc;
    bf16* Xl = (bf16*)(smc + 34816);
    bf16* Wh = (bf16*)(smc + 69632);
    bf16* Wl = (bf16*)(smc + 104448);
    float* Cst = (float*)smc;

    const int tid = threadIdx.x;
    const int pg = blockIdx.x * 128;
    const int b = pg >> 16;
    const int pix = pg & 65535;

    const int lane = tid & 31;
    const int warp = tid >> 5;
    const int g = lane >> 2, tg = lane & 3;
    const int mbase = (warp >> 1) * 32;
    const int nbase = (warp & 1) * 64;
    const int laneoff = (lane & 15) * 272 + ((lane >> 4) << 4);

    const u32 smXh = (u32)__cvta_generic_to_shared(Xh);
    const u32 smXl = (u32)__cvta_generic_to_shared(Xl);
    const u32 smWh = (u32)__cvta_generic_to_shared(Wh);
    const u32 smWl = (u32)__cvta_generic_to_shared(Wl);

    float acc[2][8][4];
    #pragma unroll
    for (int mt = 0; mt < 2; ++mt)
        #pragma unroll
        for (int nt = 0; nt < 8; ++nt)
            #pragma unroll
            for (int q = 0; q < 4; ++q) acc[mt][nt][q] = 0.f;

    for (int kc = 0; kc < 4; ++kc) {
        __syncthreads();
        {
            const u32* xh = (const u32*)&g_h2h[((size_t)(b * 512 + kc * 128)) * HW + pix];
            const u32* xl = (const u32*)&g_h2l[((size_t)(b * 512 + kc * 128)) * HW + pix];
            u32* dXh = (u32*)Xh;
            u32* dXl = (u32*)Xl;
            #pragma unroll
            for (int it = 0; it < 32; ++it) {
                int idx = tid + it * 256;
                int k = idx >> 6, pp = idx & 63;
                dXh[k * 68 + pp] = xh[(size_t)k * (HW / 2) + pp];
                dXl[k * 68 + pp] = xl[(size_t)k * (HW / 2) + pp];
            }
            const u32* wh = (const u32*)&g_w2h[kc * 128];
            const u32* wl = (const u32*)&g_w2l[kc * 128];
            u32* dWh = (u32*)Wh;
            u32* dWl = (u32*)Wl;
            #pragma unroll
            for (int it = 0; it < 32; ++it) {
                int idx = tid + it * 256;
                int o = idx >> 6, kk = idx & 63;
                dWh[o * 68 + kk] = wh[o * 256 + kk];
                dWl[o * 68 + kk] = wl[o * 256 + kk];
            }
        }
        __syncthreads();

        #pragma unroll
        for (int ks = 0; ks < 8; ++ks) {
            u32 ah[2][4], al[2][4];
            ldsm4(ah[0][0], ah[0][1], ah[0][2], ah[0][3],
                  smWh + laneoff + mbase * 272 + ks * 32);
            ldsm4(ah[1][0], ah[1][1], ah[1][2], ah[1][3],
                  smWh + laneoff + (mbase + 16) * 272 + ks * 32);
            ldsm4(al[0][0], al[0][1], al[0][2], al[0][3],
                  smWl + laneoff + mbase * 272 + ks * 32);
            ldsm4(al[1][0], al[1][1], al[1][2], al[1][3],
                  smWl + laneoff + (mbase + 16) * 272 + ks * 32);
            #pragma unroll
            for (int ntp = 0; ntp < 4; ++ntp) {
                int n0 = nbase + ntp * 16;
                u32 bh[4], bl[4];
                ldsm4t(bh[0], bh[1], bh[2], bh[3],
                       smXh + laneoff + ks * 16 * 272 + n0 * 2);
                ldsm4t(bl[0], bl[1], bl[2], bl[3],
                       smXl + laneoff + ks * 16 * 272 + n0 * 2);
                #pragma unroll
                for (int mt = 0; mt < 2; ++mt) {
                    mma16816(acc[mt][2 * ntp],     ah[mt], bh[0], bh[1]);
                    mma16816(acc[mt][2 * ntp + 1], ah[mt], bh[2], bh[3]);
                    mma16816(acc[mt][2 * ntp],     ah[mt], bl[0], bl[1]);
                    mma16816(acc[mt][2 * ntp + 1], ah[mt], bl[2], bl[3]);
                    mma16816(acc[mt][2 * ntp],     al[mt], bh[0], bh[1]);
                    mma16816(acc[mt][2 * ntp + 1], al[mt], bh[2], bh[3]);
                }
            }
        }
    }

    __syncthreads();
    #pragma unroll
    for (int mt = 0; mt < 2; ++mt) {
        #pragma unroll
        for (int nt = 0; nt < 8; ++nt) {
            int r = mbase + mt * 16 + g;
            int cc = nbase + nt * 8 + tg * 2;
            *(float2*)&Cst[r * 132 + cc] = make_float2(acc[mt][nt][0], acc[mt][nt][1]);
            *(float2*)&Cst[(r + 8) * 132 + cc] = make_float2(acc[mt][nt][2], acc[mt][nt][3]);
        }
    }
    __syncthreads();
    #pragma unroll
    for (int it = 0; it < 64; ++it) {
        int idx = tid + it * 256;
        int o = idx >> 7, p = idx & 127;
        size_t ad = (size_t)(b * 128 + o) * HW + pix + p;
        io[ad] = io[ad] + Cst[o * 132 + p] + b2[o];
    }
}

// ---------------------------------------------------------------------------
extern "C" void kernel_launch(void* const* d_in, const int* in_sizes, int n_in,
                              void* d_out, int out_size)
{
    const float* x    = (const float*)d_in[0];
    const float* l0   = (const float*)d_in[1];
    const float* n1w  = (const float*)d_in[2];
    const float* n1b  = (const float*)d_in[3];
    const float* n2w  = (const float*)d_in[4];
    const float* n2b  = (const float*)d_in[5];
    const float* qkvw = (const float*)d_in[6];
    const float* gw   = (const float*)d_in[7];
    const float* gb   = (const float*)d_in[8];
    const float* pw   = (const float*)d_in[9];
    const float* pb   = (const float*)d_in[10];
    const float* w1   = (const float*)d_in[11];
    const float* b1   = (const float*)d_in[12];
    const float* dw   = (const float*)d_in[13];
    const float* dwb  = (const float*)d_in[14];
    const float* w2   = (const float*)d_in[15];
    const float* b2   = (const float*)d_in[16];
    float* out = (float*)d_out;

    cudaFuncSetAttribute(k1_attn, cudaFuncAttributeMaxDynamicSharedMemorySize, SM1_BYTES);
    cudaFuncSetAttribute(k2_ffn1, cudaFuncAttributeMaxDynamicSharedMemorySize, SM2_BYTES);
    cudaFuncSetAttribute(k4_ffn2, cudaFuncAttributeMaxDynamicSharedMemorySize, SM4_BYTES);

    k0_prep<<<768, 256>>>(w1, w2, qkvw, pw);
    k1_attn<<<4096, 256, SM1_BYTES>>>(x, l0, n1w, n1b, gw, gb, pb, out);
    k2_ffn1<<<2048, 256, SM2_BYTES>>>(out, n2w, n2b, b1);
    k3_dw<<<131072, 256>>>(dw, dwb);
    k4_ffn2<<<2048, 256, SM4_BYTES>>>(b2, out);
}

// round 12
// speedup vs baseline: 1.7967x; 1.2021x over previous
#include <cuda_runtime.h>
#include <cuda_bf16.h>
#include <math.h>

// ---------------------------------------------------------------------------
// IGAB block, B=4, C=128, H=W=256, window 8x8, heads=8, head_dim=16, HIDDEN=512
//   k0: pre-split qkvw/pw/w1/w2 into bf16 hi/lo (once per launch)
//   k1: LN1 + QKV(MMA, reg-prefetch W) + gate + attention(FFMA2) + proj(MMA)
//   k2: LN2 + W1 + GELU  -> MMA, cp.async double-buffered W, direct store
//   k3: depthwise 3x3 + bias + GELU -> 4px/thread, writes bf16 hi/lo
//   k4: W2 + bias + residual -> MMA, cp.async double-buffered X, direct store
// ---------------------------------------------------------------------------

#define HW 65536
#define NPLANE 256

__device__ float g_h1[(size_t)4 * 512 * HW];
__device__ __nv_bfloat16 g_h2h[(size_t)4 * 512 * HW];
__device__ __nv_bfloat16 g_h2l[(size_t)4 * 512 * HW];
__device__ __nv_bfloat16 g_w1h[512 * 128], g_w1l[512 * 128];
__device__ __nv_bfloat16 g_w2h[128 * 512], g_w2l[128 * 512];
__device__ __nv_bfloat16 g_qkvh[384 * 128], g_qkvl[384 * 128];
__device__ __nv_bfloat16 g_pwh[128 * 128], g_pwl[128 * 128];

typedef unsigned long long u64;
typedef unsigned int u32;
typedef __nv_bfloat16 bf16;

__device__ __forceinline__ u64 ffma2(u64 a, u64 b, u64 c) {
    u64 d;
    asm("fma.rn.f32x2 %0, %1, %2, %3;" : "=l"(d) : "l"(a), "l"(b), "l"(c));
    return d;
}
__device__ __forceinline__ float2 unpack2(u64 v) {
    unsigned lo, hi;
    asm("mov.b64 {%0, %1}, %2;" : "=r"(lo), "=r"(hi) : "l"(v));
    return make_float2(__uint_as_float(lo), __uint_as_float(hi));
}
__device__ __forceinline__ float gelu_exact(float v) {
    return 0.5f * v * (1.0f + erff(v * 0.70710678118654752f));
}
__device__ __forceinline__ void mma16816(float* c, const u32* a, u32 b0, u32 b1) {
    asm volatile(
        "mma.sync.aligned.m16n8k16.row.col.f32.bf16.bf16.f32 "
        "{%0,%1,%2,%3},{%4,%5,%6,%7},{%8,%9},{%0,%1,%2,%3};"
        : "+f"(c[0]), "+f"(c[1]), "+f"(c[2]), "+f"(c[3])
        : "r"(a[0]), "r"(a[1]), "r"(a[2]), "r"(a[3]), "r"(b0), "r"(b1));
}
__device__ __forceinline__ void ldsm4(u32& d0, u32& d1, u32& d2, u32& d3, u32 a) {
    asm volatile("ldmatrix.sync.aligned.m8n8.x4.shared.b16 {%0,%1,%2,%3},[%4];"
                 : "=r"(d0), "=r"(d1), "=r"(d2), "=r"(d3) : "r"(a));
}
__device__ __forceinline__ void ldsm4t(u32& d0, u32& d1, u32& d2, u32& d3, u32 a) {
    asm volatile("ldmatrix.sync.aligned.m8n8.x4.trans.shared.b16 {%0,%1,%2,%3},[%4];"
                 : "=r"(d0), "=r"(d1), "=r"(d2), "=r"(d3) : "r"(a));
}
__device__ __forceinline__ void split_bf16(float v, bf16& h, bf16& l) {
    h = __float2bfloat16(v);
    l = __float2bfloat16(v - __bfloat162float(h));
}
__device__ __forceinline__ void cpasync16(u32 smem_addr, const void* gptr) {
    asm volatile("cp.async.ca.shared.global [%0], [%1], 16;"
                 :: "r"(smem_addr), "l"(gptr) : "memory");
}
#define CP_COMMIT() asm volatile("cp.async.commit_group;" ::: "memory")
#define CP_WAIT0()  asm volatile("cp.async.wait_group 0;" ::: "memory")

// ======================= kernel 0: weight pre-split ========================
__global__ __launch_bounds__(256)
void k0_prep(const float* __restrict__ w1, const float* __restrict__ w2,
             const float* __restrict__ qkvw, const float* __restrict__ pw)
{
    int i = blockIdx.x * 256 + threadIdx.x;      // 196608 total
    bf16 h, l;
    if (i < 65536) {
        split_bf16(w1[i], h, l);
        g_w1h[i] = h; g_w1l[i] = l;
    } else if (i < 131072) {
        int j = i - 65536;
        split_bf16(w2[j], h, l);
        g_w2h[j] = h; g_w2l[j] = l;
    } else if (i < 180224) {
        int j = i - 131072;
        split_bf16(qkvw[j], h, l);
        g_qkvh[j] = h; g_qkvl[j] = l;
    } else {
        int j = i - 180224;
        split_bf16(pw[j], h, l);
        g_pwh[j] = h; g_pwl[j] = l;
    }
}

// ======================= kernel 1: attention block =========================
// smem byte layout (211968 total):
//   Af f32[128][68] @0 | Xh bf16[128][72] @34816 | Xl @53248
//   Wh bf16[64][136] @71680 (aliases Sf) | Wl @89088
//   Qf f32[128][68] @106496 | Kf @141312 | Vf @176128
//   Sf f32[64][68] @71680 | L0 @210944 | MU @211200 | RS @211456 | DEN @211712
#define SM1_BYTES 211968

__global__ __launch_bounds__(256, 1)
void k1_attn(const float* __restrict__ x, const float* __restrict__ l0,
             const float* __restrict__ n1w, const float* __restrict__ n1b,
             const float* __restrict__ gw, const float* __restrict__ gb,
             const float* __restrict__ pb, float* __restrict__ outp)
{
    extern __shared__ float sm[];
    char* smcc = (char*)sm;
    float* Af = sm;
    bf16* Xh = (bf16*)(smcc + 34816);
    bf16* Xl = (bf16*)(smcc + 53248);
    bf16* Wh = (bf16*)(smcc + 71680);
    bf16* Wl = (bf16*)(smcc + 89088);
    float* Qf = sm + 26624;
    float* Kf = sm + 35328;
    float* Vf = sm + 44032;
    float* Sf = sm + 17920;
    float* L0v = sm + 52736;
    float* MUv = sm + 52800;
    float* RSv = sm + 52864;
    float* DENv = sm + 52928;

    const int tid = threadIdx.x;
    const int wi = blockIdx.x;
    const int b  = wi >> 10;
    const int hi = (wi >> 5) & 31;
    const int wj = wi & 31;
    const int base_pix = (hi * 8) * NPLANE + wj * 8;
    const float* xb = x + (size_t)b * 128 * HW;

    #pragma unroll
    for (int it = 0; it < 32; ++it) {
        int idx = tid + it * 256;
        int c = idx >> 6, p = idx & 63;
        Af[c * 68 + p] = xb[c * HW + base_pix + (p >> 3) * NPLANE + (p & 7)];
    }
    if (tid < 64) {
        int p = tid;
        L0v[p] = l0[(size_t)b * HW + base_pix + (p >> 3) * NPLANE + (p & 7)];
    }
    __syncthreads();

    {   // LN1 stats
        int p = tid >> 2, part = tid & 3;
        float s = 0.f, sq = 0.f;
        #pragma unroll
        for (int c = part * 32; c < part * 32 + 32; ++c) {
            float v = Af[c * 68 + p];
            s += v; sq += v * v;
        }
        s  += __shfl_xor_sync(0xffffffffu, s, 1);
        sq += __shfl_xor_sync(0xffffffffu, sq, 1);
        s  += __shfl_xor_sync(0xffffffffu, s, 2);
        sq += __shfl_xor_sync(0xffffffffu, sq, 2);
        if (part == 0) {
            float mu = s * (1.f / 128.f);
            float var = sq * (1.f / 128.f) - mu * mu;
            MUv[p] = mu;
            RSv[p] = rsqrtf(var + 1e-6f);
        }
    }
    __syncthreads();
    #pragma unroll
    for (int it = 0; it < 32; ++it) {
        int idx = tid + it * 256;
        int c = idx >> 6, p = idx & 63;
        float xn = n1w[c] * (Af[c * 68 + p] - MUv[p]) * RSv[p] + n1b[c];
        bf16 h, l;
        split_bf16(xn, h, l);
        Xh[c * 72 + p] = h;
        Xl[c * 72 + p] = l;
    }

    const int lane = tid & 31;
    const int warp = tid >> 5;
    const int g = lane >> 2, tg = lane & 3;
    const int mwarp = warp >> 1;
    const int nwarp = warp & 1;
    const int laneW = (lane & 15) * 272 + ((lane >> 4) << 4);
    const int laneX = (lane & 15) * 144 + ((lane >> 4) << 4);

    const u32 smXh = (u32)__cvta_generic_to_shared(Xh);
    const u32 smXl = (u32)__cvta_generic_to_shared(Xl);
    const u32 smWh = (u32)__cvta_generic_to_shared(Wh);
    const u32 smWl = (u32)__cvta_generic_to_shared(Wl);

    // ---- QKV: 6 chunks, register-prefetched weights ----
    u32 wph[16], wpl[16];
    {
        const u32* wh = (const u32*)g_qkvh;        // chunk 0
        const u32* wl = (const u32*)g_qkvl;
        #pragma unroll
        for (int it = 0; it < 16; ++it) {
            wph[it] = wh[tid + it * 256];
            wpl[it] = wl[tid + it * 256];
        }
    }

    for (int ch = 0; ch < 6; ++ch) {
        __syncthreads();      // split visible (ch=0) / prior ldsm done
        {
            u32* dWh = (u32*)Wh;
            u32* dWl = (u32*)Wl;
            #pragma unroll
            for (int it = 0; it < 16; ++it) {
                int idx = tid + it * 256;
                int o = idx >> 6, kk = idx & 63;
                dWh[o * 68 + kk] = wph[it];
                dWl[o * 68 + kk] = wpl[it];
            }
        }
        __syncthreads();
        if (ch < 5) {
            const u32* wh = (const u32*)g_qkvh + (ch + 1) * 4096;
            const u32* wl = (const u32*)g_qkvl + (ch + 1) * 4096;
            #pragma unroll
            for (int it = 0; it < 16; ++it) {
                wph[it] = wh[tid + it * 256];
                wpl[it] = wl[tid + it * 256];
            }
        }

        float acc[4][4];
        #pragma unroll
        for (int nt = 0; nt < 4; ++nt)
            #pragma unroll
            for (int q = 0; q < 4; ++q) acc[nt][q] = 0.f;

        #pragma unroll
        for (int ks = 0; ks < 8; ++ks) {
            u32 ah[4], al[4];
            ldsm4(ah[0], ah[1], ah[2], ah[3], smWh + laneW + mwarp * 16 * 272 + ks * 32);
            ldsm4(al[0], al[1], al[2], al[3], smWl + laneW + mwarp * 16 * 272 + ks * 32);
            #pragma unroll
            for (int ntp = 0; ntp < 2; ++ntp) {
                int n0 = nwarp * 32 + ntp * 16;
                u32 bh[4], bl[4];
                ldsm4t(bh[0], bh[1], bh[2], bh[3], smXh + laneX + ks * 16 * 144 + n0 * 2);
                ldsm4t(bl[0], bl[1], bl[2], bl[3], smXl + laneX + ks * 16 * 144 + n0 * 2);
                mma16816(acc[2 * ntp],     ah, bh[0], bh[1]);
                mma16816(acc[2 * ntp + 1], ah, bh[2], bh[3]);
                mma16816(acc[2 * ntp],     ah, bl[0], bl[1]);
                mma16816(acc[2 * ntp + 1], ah, bl[2], bl[3]);
                mma16816(acc[2 * ntp],     al, bh[0], bh[1]);
                mma16816(acc[2 * ntp + 1], al, bh[2], bh[3]);
            }
        }

        float* dst = (ch < 2) ? Qf : (ch < 4) ? Kf : Vf;
        int rloc = (ch & 1) * 64 + mwarp * 16;
        int r0 = rloc + g, r1 = rloc + g + 8;
        if (ch < 2) {
            float gw0 = gw[r0], gb0 = gb[r0];
            float gw1 = gw[r1], gb1 = gb[r1];
            #pragma unroll
            for (int nt = 0; nt < 4; ++nt) {
                int col = nwarp * 32 + nt * 8 + tg * 2;
                float la = L0v[col], lb = L0v[col + 1];
                float s00 = 1.f / (1.f + __expf(-(la * gw0 + gb0)));
                float s01 = 1.f / (1.f + __expf(-(lb * gw0 + gb0)));
                float s10 = 1.f / (1.f + __expf(-(la * gw1 + gb1)));
                float s11 = 1.f / (1.f + __expf(-(lb * gw1 + gb1)));
                *(float2*)&dst[r0 * 68 + col] = make_float2(acc[nt][0] * s00, acc[nt][1] * s01);
                *(float2*)&dst[r1 * 68 + col] = make_float2(acc[nt][2] * s10, acc[nt][3] * s11);
            }
        } else {
            #pragma unroll
            for (int nt = 0; nt < 4; ++nt) {
                int col = nwarp * 32 + nt * 8 + tg * 2;
                *(float2*)&dst[r0 * 68 + col] = make_float2(acc[nt][0], acc[nt][1]);
                *(float2*)&dst[r1 * 68 + col] = make_float2(acc[nt][2], acc[nt][3]);
            }
        }
    }
    __syncthreads();

    // ---- window attention (FFMA2) -> bf16 split Xh/Xl ----
    for (int h = 0; h < 8; ++h) {
        const int cb = h * 16;
        {
            const int tx = tid & 15, ty = tid >> 4;
            u64 acc2[2][4];
            #pragma unroll
            for (int i = 0; i < 2; ++i)
                #pragma unroll
                for (int j = 0; j < 4; ++j) acc2[i][j] = 0ull;
            #pragma unroll
            for (int d = 0; d < 16; ++d) {
                ulonglong2 qv = *(const ulonglong2*)&Qf[(cb + d) * 68 + 4 * tx];
                #pragma unroll
                for (int j = 0; j < 4; ++j) {
                    float kvs = Kf[(cb + d) * 68 + 4 * ty + j];
                    u64 kp;
                    asm("mov.b64 %0, {%1, %1};" : "=l"(kp) : "r"(__float_as_uint(kvs)));
                    acc2[0][j] = ffma2(qv.x, kp, acc2[0][j]);
                    acc2[1][j] = ffma2(qv.y, kp, acc2[1][j]);
                }
            }
            #pragma unroll
            for (int a = 0; a < 2; ++a)
                #pragma unroll
                for (int j = 0; j < 4; ++j) {
                    float2 f = unpack2(acc2[a][j]);
                    Sf[(4 * tx + 2 * a) * 68 + 4 * ty + j] = f.x * 0.25f;
                    Sf[(4 * tx + 2 * a + 1) * 68 + 4 * ty + j] = f.y * 0.25f;
                }
        }
        __syncthreads();
        {
            int r = tid >> 2, part = tid & 3;
            float m = -1e30f;
            #pragma unroll
            for (int kk = part * 16; kk < part * 16 + 16; ++kk)
                m = fmaxf(m, Sf[r * 68 + kk]);
            m = fmaxf(m, __shfl_xor_sync(0xffffffffu, m, 1));
            m = fmaxf(m, __shfl_xor_sync(0xffffffffu, m, 2));
            float s = 0.f;
            #pragma unroll
            for (int kk = part * 16; kk < part * 16 + 16; ++kk) {
                float e = __expf(Sf[r * 68 + kk] - m);
                Sf[r * 68 + kk] = e;
                s += e;
            }
            s += __shfl_xor_sync(0xffffffffu, s, 1);
            s += __shfl_xor_sync(0xffffffffu, s, 2);
            if (part == 0) DENv[r] = 1.f / s;
        }
        __syncthreads();
        {
            int pq = tid >> 2, dg = tid & 3;
            const u64* Srow = (const u64*)&Sf[pq * 68];
            const u64* V0 = (const u64*)&Vf[(cb + 4 * dg + 0) * 68];
            const u64* V1 = (const u64*)&Vf[(cb + 4 * dg + 1) * 68];
            const u64* V2 = (const u64*)&Vf[(cb + 4 * dg + 2) * 68];
            const u64* V3 = (const u64*)&Vf[(cb + 4 * dg + 3) * 68];
            u64 a0 = 0ull, a1 = 0ull, a2 = 0ull, a3 = 0ull;
            #pragma unroll 8
            for (int kk = 0; kk < 32; ++kk) {
                u64 prp = Srow[kk];
                a0 = ffma2(prp, V0[kk], a0);
                a1 = ffma2(prp, V1[kk], a1);
                a2 = ffma2(prp, V2[kk], a2);
                a3 = ffma2(prp, V3[kk], a3);
            }
            float dn = DENv[pq];
            float2 f0 = unpack2(a0), f1 = unpack2(a1), f2 = unpack2(a2), f3 = unpack2(a3);
            bf16 h_, l_;
            split_bf16((f0.x + f0.y) * dn, h_, l_);
            Xh[(cb + 4 * dg + 0) * 72 + pq] = h_; Xl[(cb + 4 * dg + 0) * 72 + pq] = l_;
            split_bf16((f1.x + f1.y) * dn, h_, l_);
            Xh[(cb + 4 * dg + 1) * 72 + pq] = h_; Xl[(cb + 4 * dg + 1) * 72 + pq] = l_;
            split_bf16((f2.x + f2.y) * dn, h_, l_);
            Xh[(cb + 4 * dg + 2) * 72 + pq] = h_; Xl[(cb + 4 * dg + 2) * 72 + pq] = l_;
            split_bf16((f3.x + f3.y) * dn, h_, l_);
            Xh[(cb + 4 * dg + 3) * 72 + pq] = h_; Xl[(cb + 4 * dg + 3) * 72 + pq] = l_;
        }
        __syncthreads();
    }

    // ---- proj (MMA) + bias + residual, direct store ----
    {
        const u32* wh = (const u32*)g_pwh;
        const u32* wl = (const u32*)g_pwl;
        #pragma unroll
        for (int it = 0; it < 16; ++it) {
            wph[it] = wh[tid + it * 256];
            wpl[it] = wl[tid + it * 256];
        }
    }
    for (int ch = 0; ch < 2; ++ch) {
        __syncthreads();      // attention Sf readers done / prior ldsm done
        {
            u32* dWh = (u32*)Wh;
            u32* dWl = (u32*)Wl;
            #pragma unroll
            for (int it = 0; it < 16; ++it) {
                int idx = tid + it * 256;
                int o = idx >> 6, kk = idx & 63;
                dWh[o * 68 + kk] = wph[it];
                dWl[o * 68 + kk] = wpl[it];
            }
        }
        __syncthreads();
        if (ch == 0) {
            const u32* wh = (const u32*)g_pwh + 4096;
            const u32* wl = (const u32*)g_pwl + 4096;
            #pragma unroll
            for (int it = 0; it < 16; ++it) {
                wph[it] = wh[tid + it * 256];
                wpl[it] = wl[tid + it * 256];
            }
        }

        float acc[4][4];
        #pragma unroll
        for (int nt = 0; nt < 4; ++nt)
            #pragma unroll
            for (int q = 0; q < 4; ++q) acc[nt][q] = 0.f;

        #pragma unroll
        for (int ks = 0; ks < 8; ++ks) {
            u32 ah[4], al[4];
            ldsm4(ah[0], ah[1], ah[2], ah[3], smWh + laneW + mwarp * 16 * 272 + ks * 32);
            ldsm4(al[0], al[1], al[2], al[3], smWl + laneW + mwarp * 16 * 272 + ks * 32);
            #pragma unroll
            for (int ntp = 0; ntp < 2; ++ntp) {
                int n0 = nwarp * 32 + ntp * 16;
                u32 bh[4], bl[4];
                ldsm4t(bh[0], bh[1], bh[2], bh[3], smXh + laneX + ks * 16 * 144 + n0 * 2);
                ldsm4t(bl[0], bl[1], bl[2], bl[3], smXl + laneX + ks * 16 * 144 + n0 * 2);
                mma16816(acc[2 * ntp],     ah, bh[0], bh[1]);
                mma16816(acc[2 * ntp + 1], ah, bh[2], bh[3]);
                mma16816(acc[2 * ntp],     ah, bl[0], bl[1]);
                mma16816(acc[2 * ntp + 1], ah, bl[2], bl[3]);
                mma16816(acc[2 * ntp],     al, bh[0], bh[1]);
                mma16816(acc[2 * ntp + 1], al, bh[2], bh[3]);
            }
        }

        // direct store: + bias + residual(Af)
        int r0 = mwarp * 16 + g, r1 = r0 + 8;
        int o0 = ch * 64 + r0, o1 = ch * 64 + r1;
        float pb0 = pb[o0], pb1 = pb[o1];
        float* op0 = outp + (size_t)(b * 128 + o0) * HW + base_pix;
        float* op1 = outp + (size_t)(b * 128 + o1) * HW + base_pix;
        #pragma unroll
        for (int nt = 0; nt < 4; ++nt) {
            int col = nwarp * 32 + nt * 8 + tg * 2;
            int goff = ((col >> 3) * NPLANE) + (col & 7);
            float2 v0 = make_float2(acc[nt][0] + pb0 + Af[o0 * 68 + col],
                                    acc[nt][1] + pb0 + Af[o0 * 68 + col + 1]);
            float2 v1 = make_float2(acc[nt][2] + pb1 + Af[o1 * 68 + col],
                                    acc[nt][3] + pb1 + Af[o1 * 68 + col + 1]);
            *(float2*)&op0[goff] = v0;
            *(float2*)&op1[goff] = v1;
        }
    }
}

// ======================= kernel 2: LN2 + W1 + GELU =========================
// smem: Xh@0 Xl@34816 | W0h@69632 W0l@104448 | W1h@139264 W1l@174080
//       Xf f32[128][132] aliases @69632 ; MU@208896 RS@209408
#define SM2_BYTES 209920

__global__ __launch_bounds__(256, 1)
void k2_ffn1(const float* __restrict__ inp, const float* __restrict__ n2w,
             const float* __restrict__ n2b, const float* __restrict__ b1)
{
    extern __shared__ char smc[];
    bf16* Xh = (bf16*)smc;
    bf16* Xl = (bf16*)(smc + 34816);
    float* Xf = (float*)(smc + 69632);
    float* MU = (float*)(smc + 208896);
    float* RS = (float*)(smc + 209408);
    const u32 smbase = (u32)__cvta_generic_to_shared(smc);
    const u32 smW[2] = {smbase + 69632, smbase + 139264};   // h; l at +34816

    const int tid = threadIdx.x;
    const int pg = blockIdx.x * 128;
    const int b = pg >> 16;
    const int pix = pg & 65535;
    const float* ib = inp + (size_t)b * 128 * HW + pix;

    #pragma unroll
    for (int it = 0; it < 64; ++it) {
        int idx = tid + it * 256;
        int c = idx >> 7, p = idx & 127;
        Xf[c * 132 + p] = ib[c * HW + p];
    }
    __syncthreads();
    {
        int p = tid >> 1, part = tid & 1;
        float s = 0.f, sq = 0.f;
        #pragma unroll
        for (int c = part * 64; c < part * 64 + 64; ++c) {
            float v = Xf[c * 132 + p];
            s += v; sq += v * v;
        }
        s  += __shfl_xor_sync(0xffffffffu, s, 1);
        sq += __shfl_xor_sync(0xffffffffu, sq, 1);
        if (part == 0) {
            float mu = s * (1.f / 128.f);
            float var = sq * (1.f / 128.f) - mu * mu;
            MU[p] = mu;
            RS[p] = rsqrtf(var + 1e-6f);
        }
    }
    __syncthreads();
    #pragma unroll
    for (int it = 0; it < 64; ++it) {
        int idx = tid + it * 256;
        int c = idx >> 7, p = idx & 127;
        float xn = n2w[c] * (Xf[c * 132 + p] - MU[p]) * RS[p] + n2b[c];
        bf16 h, l;
        split_bf16(xn, h, l);
        Xh[c * 136 + p] = h;
        Xl[c * 136 + p] = l;
    }
    __syncthreads();     // all Xf reads done before W0 cp.async overwrites it

    // cp.async W chunk loader
    const int c16 = tid & 15;
    const int orow = tid >> 4;           // 0..15, step 16 per it
    // prefetch chunk 0 into buffer 0
    {
        const char* srcH = (const char*)g_w1h;
        const char* srcL = (const char*)g_w1l;
        #pragma unroll
        for (int it = 0; it < 8; ++it) {
            int o = orow + it * 16;
            cpasync16(smW[0] + o * 272 + c16 * 16, srcH + o * 256 + c16 * 16);
            cpasync16(smW[0] + 34816 + o * 272 + c16 * 16, srcL + o * 256 + c16 * 16);
        }
        CP_COMMIT();
    }

    const int lane = tid & 31;
    const int warp = tid >> 5;
    const int g = lane >> 2, tg = lane & 3;
    const int mbase = (warp >> 1) * 32;
    const int nbase = (warp & 1) * 64;
    const int laneoff = (lane & 15) * 272 + ((lane >> 4) << 4);
    const u32 smXh = smbase;
    const u32 smXl = smbase + 34816;

    for (int och = 0; och < 4; ++och) {
        CP_WAIT0();
        __syncthreads();
        if (och < 3) {
            const char* srcH = (const char*)g_w1h + (size_t)(och + 1) * 128 * 256;
            const char* srcL = (const char*)g_w1l + (size_t)(och + 1) * 128 * 256;
            u32 dstW = smW[(och + 1) & 1];
            #pragma unroll
            for (int it = 0; it < 8; ++it) {
                int o = orow + it * 16;
                cpasync16(dstW + o * 272 + c16 * 16, srcH + o * 256 + c16 * 16);
                cpasync16(dstW + 34816 + o * 272 + c16 * 16, srcL + o * 256 + c16 * 16);
            }
            CP_COMMIT();
        }
        const u32 smWh = smW[och & 1];
        const u32 smWl = smWh + 34816;

        float acc[2][8][4];
        #pragma unroll
        for (int mt = 0; mt < 2; ++mt)
            #pragma unroll
            for (int nt = 0; nt < 8; ++nt)
                #pragma unroll
                for (int q = 0; q < 4; ++q) acc[mt][nt][q] = 0.f;

        #pragma unroll
        for (int ks = 0; ks < 8; ++ks) {
            u32 ah[2][4], al[2][4];
            ldsm4(ah[0][0], ah[0][1], ah[0][2], ah[0][3],
                  smWh + laneoff + mbase * 272 + ks * 32);
            ldsm4(ah[1][0], ah[1][1], ah[1][2], ah[1][3],
                  smWh + laneoff + (mbase + 16) * 272 + ks * 32);
            ldsm4(al[0][0], al[0][1], al[0][2], al[0][3],
                  smWl + laneoff + mbase * 272 + ks * 32);
            ldsm4(al[1][0], al[1][1], al[1][2], al[1][3],
                  smWl + laneoff + (mbase + 16) * 272 + ks * 32);
            #pragma unroll
            for (int ntp = 0; ntp < 4; ++ntp) {
                int n0 = nbase + ntp * 16;
                u32 bh[4], bl[4];
                ldsm4t(bh[0], bh[1], bh[2], bh[3],
                       smXh + laneoff + ks * 16 * 272 + n0 * 2);
                ldsm4t(bl[0], bl[1], bl[2], bl[3],
                       smXl + laneoff + ks * 16 * 272 + n0 * 2);
                #pragma unroll
                for (int mt = 0; mt < 2; ++mt) {
                    mma16816(acc[mt][2 * ntp],     ah[mt], bh[0], bh[1]);
                    mma16816(acc[mt][2 * ntp + 1], ah[mt], bh[2], bh[3]);
                    mma16816(acc[mt][2 * ntp],     ah[mt], bl[0], bl[1]);
                    mma16816(acc[mt][2 * ntp + 1], ah[mt], bl[2], bl[3]);
                    mma16816(acc[mt][2 * ntp],     al[mt], bh[0], bh[1]);
                    mma16816(acc[mt][2 * ntp + 1], al[mt], bh[2], bh[3]);
                }
            }
        }

        // direct store with bias + GELU
        #pragma unroll
        for (int mt = 0; mt < 2; ++mt) {
            int r = mbase + mt * 16 + g;
            int o0 = och * 128 + r, o1 = o0 + 8;
            float bv0 = b1[o0], bv1 = b1[o1];
            float* p0 = &g_h1[(size_t)(b * 512 + o0) * HW + pix];
            float* p1 = &g_h1[(size_t)(b * 512 + o1) * HW + pix];
            #pragma unroll
            for (int nt = 0; nt < 8; ++nt) {
                int col = nbase + nt * 8 + tg * 2;
                float2 v0 = make_float2(gelu_exact(acc[mt][nt][0] + bv0),
                                        gelu_exact(acc[mt][nt][1] + bv0));
                float2 v1 = make_float2(gelu_exact(acc[mt][nt][2] + bv1),
                                        gelu_exact(acc[mt][nt][3] + bv1));
                *(float2*)&p0[col] = v0;
                *(float2*)&p1[col] = v1;
            }
        }
    }
}

// ======================= kernel 3: dw3x3 + GELU ============================
__global__ __launch_bounds__(256)
void k3_dw(const float* __restrict__ dw, const float* __restrict__ dwb)
{
    const int blk = blockIdx.x;
    const int plane = blk >> 6;
    const int ch = plane & 511;
    const int rg = blk & 63;
    const int tid = threadIdx.x;
    const int y = rg * 4 + (tid >> 6);
    const int xc = (tid & 63) * 4;
    const float* ip = g_h1 + (size_t)plane * HW;

    float w[9];
    #pragma unroll
    for (int i = 0; i < 9; ++i) w[i] = dw[ch * 9 + i];
    const float bias = dwb[ch];

    float v[3][6];
    #pragma unroll
    for (int dy = 0; dy < 3; ++dy) {
        int yy = y + dy - 1;
        if (yy >= 0 && yy < 256) {
            const float* row = ip + yy * NPLANE + xc;
            float4 m = *(const float4*)row;
            v[dy][1] = m.x; v[dy][2] = m.y; v[dy][3] = m.z; v[dy][4] = m.w;
            v[dy][0] = (xc > 0) ? row[-1] : 0.f;
            v[dy][5] = (xc < 252) ? row[4] : 0.f;
        } else {
            #pragma unroll
            for (int i = 0; i < 6; ++i) v[dy][i] = 0.f;
        }
    }

    bf16 hh[4], ll[4];
    #pragma unroll
    for (int p = 0; p < 4; ++p) {
        float s = bias;
        #pragma unroll
        for (int dy = 0; dy < 3; ++dy)
            s += w[dy * 3 + 0] * v[dy][p] + w[dy * 3 + 1] * v[dy][p + 1]
               + w[dy * 3 + 2] * v[dy][p + 2];
        float r = gelu_exact(s);
        split_bf16(r, hh[p], ll[p]);
    }

    uint2 ph, pl;
    ph.x = (u32)__bfloat16_as_ushort(hh[0]) | ((u32)__bfloat16_as_ushort(hh[1]) << 16);
    ph.y = (u32)__bfloat16_as_ushort(hh[2]) | ((u32)__bfloat16_as_ushort(hh[3]) << 16);
    pl.x = (u32)__bfloat16_as_ushort(ll[0]) | ((u32)__bfloat16_as_ushort(ll[1]) << 16);
    pl.y = (u32)__bfloat16_as_ushort(ll[2]) | ((u32)__bfloat16_as_ushort(ll[3]) << 16);
    size_t off = (size_t)plane * HW + y * NPLANE + xc;
    *(uint2*)&g_h2h[off] = ph;
    *(uint2*)&g_h2l[off] = pl;
}

// ======================= kernel 4: W2 + residual ===========================
// smem: X0h@0 X0l@34816 | X1h@69632 X1l@104448 | Wh@139264 Wl@174080
#define SM4_BYTES 208896

__global__ __launch_bounds__(256, 1)
void k4_ffn2(const float* __restrict__ b2, float* __restrict__ io)
{
    extern __shared__ char smc[];
    const u32 smbase = (u32)__cvta_generic_to_shared(smc);
    const u32 smX[2] = {smbase, smbase + 69632};
    const u32 smWh = smbase + 139264;
    const u32 smWl = smbase + 174080;

    const int tid = threadIdx.x;
    const int pg = blockIdx.x * 128;
    const int b = pg >> 16;
    const int pix = pg & 65535;

    const int c16 = tid & 15;
    const int xrow = tid >> 4;          // 0..15, step 16

    // cp.async X chunk kc into buffer sel
    auto copyX = [&](int kc, int sel) {
        const char* srcH = (const char*)g_h2h +
            ((size_t)(b * 512 + kc * 128)) * (HW * 2) + (size_t)pix * 2;
        const char* srcL = (const char*)g_h2l +
            ((size_t)(b * 512 + kc * 128)) * (HW * 2) + (size_t)pix * 2;
        u32 dst = smX[sel];
        #pragma unroll
        for (int it = 0; it < 8; ++it) {
            int k = xrow + it * 16;
            cpasync16(dst + k * 272 + c16 * 16,
                      srcH + (size_t)k * (HW * 2) + c16 * 16);
            cpasync16(dst + 34816 + k * 272 + c16 * 16,
                      srcL + (size_t)k * (HW * 2) + c16 * 16);
        }
        CP_COMMIT();
    };

    copyX(0, 0);

    const int lane = tid & 31;
    const int warp = tid >> 5;
    const int g = lane >> 2, tg = lane & 3;
    const int mbase = (warp >> 1) * 32;
    const int nbase = (warp & 1) * 64;
    const int laneoff = (lane & 15) * 272 + ((lane >> 4) << 4);

    float acc[2][8][4];
    #pragma unroll
    for (int mt = 0; mt < 2; ++mt)
        #pragma unroll
        for (int nt = 0; nt < 8; ++nt)
            #pragma unroll
            for (int q = 0; q < 4; ++q) acc[mt][nt][q] = 0.f;

    for (int kc = 0; kc < 4; ++kc) {
        CP_WAIT0();
        __syncthreads();
        if (kc < 3) copyX(kc + 1, (kc + 1) & 1);
        {   // W synchronous (L2-resident)
            const u32* wh = (const u32*)&g_w2h[kc * 128];
            const u32* wl = (const u32*)&g_w2l[kc * 128];
            bf16* Wh = (bf16*)(smc + 139264);
            bf16* Wl = (bf16*)(smc + 174080);
            u32* dWh = (u32*)Wh;
            u32* dWl = (u32*)Wl;
            #pragma unroll
            for (int it = 0; it < 32; ++it) {
                int idx = tid + it * 256;
                int o = idx >> 6, kk = idx & 63;
                dWh[o * 68 + kk] = wh[o * 256 + kk];
                dWl[o * 68 + kk] = wl[o * 256 + kk];
            }
        }
        __syncthreads();

        const u32 smXh = smX[kc & 1];
        const u32 smXl = smXh + 34816;

        #pragma unroll
        for (int ks = 0; ks < 8; ++ks) {
            u32 ah[2][4], al[2][4];
            ldsm4(ah[0][0], ah[0][1], ah[0][2], ah[0][3],
                  smWh + laneoff + mbase * 272 + ks * 32);
            ldsm4(ah[1][0], ah[1][1], ah[1][2], ah[1][3],
                  smWh + laneoff + (mbase + 16) * 272 + ks * 32);
            ldsm4(al[0][0], al[0][1], al[0][2], al[0][3],
                  smWl + laneoff + mbase * 272 + ks * 32);
            ldsm4(al[1][0], al[1][1], al[1][2], al[1][3],
                  smWl + laneoff + (mbase + 16) * 272 + ks * 32);
            #pragma unroll
            for (int ntp = 0; ntp < 4; ++ntp) {
                int n0 = nbase + ntp * 16;
                u32 bh[4], bl[4];
                ldsm4t(bh[0], bh[1], bh[2], bh[3],
                       smXh + laneoff + ks * 16 * 272 + n0 * 2);
                ldsm4t(bl[0], bl[1], bl[2], bl[3],
                       smXl + laneoff + ks * 16 * 272 + n0 * 2);
                #pragma unroll
                for (int mt = 0; mt < 2; ++mt) {
                    mma16816(acc[mt][2 * ntp],     ah[mt], bh[0], bh[1]);
                    mma16816(acc[mt][2 * ntp + 1], ah[mt], bh[2], bh[3]);
                    mma16816(acc[mt][2 * ntp],     ah[mt], bl[0], bl[1]);
                    mma16816(acc[mt][2 * ntp + 1], ah[mt], bl[2], bl[3]);
                    mma16816(acc[mt][2 * ntp],     al[mt], bh[0], bh[1]);
                    mma16816(acc[mt][2 * ntp + 1], al[mt], bh[2], bh[3]);
                }
            }
        }
    }

    // direct epilogue: residual RMW + bias
    #pragma unroll
    for (int mt = 0; mt < 2; ++mt) {
        int r = mbase + mt * 16 + g;
        int o0 = r, o1 = r + 8;
        float bv0 = b2[o0], bv1 = b2[o1];
        float* p0 = &io[(size_t)(b * 128 + o0) * HW + pix];
        float* p1 = &io[(size_t)(b * 128 + o1) * HW + pix];
        #pragma unroll
        for (int nt = 0; nt < 8; ++nt) {
            int col = nbase + nt * 8 + tg * 2;
            float2 v0 = *(float2*)&p0[col];
            float2 v1 = *(float2*)&p1[col];
            v0.x += acc[mt][nt][0] + bv0;
            v0.y += acc[mt][nt][1] + bv0;
            v1.x += acc[mt][nt][2] + bv1;
            v1.y += acc[mt][nt][3] + bv1;
            *(float2*)&p0[col] = v0;
            *(float2*)&p1[col] = v1;
        }
    }
}

// ---------------------------------------------------------------------------
extern "C" void kernel_launch(void* const* d_in, const int* in_sizes, int n_in,
                              void* d_out, int out_size)
{
    const float* x    = (const float*)d_in[0];
    const float* l0   = (const float*)d_in[1];
    const float* n1w  = (const float*)d_in[2];
    const float* n1b  = (const float*)d_in[3];
    const float* n2w  = (const float*)d_in[4];
    const float* n2b  = (const float*)d_in[5];
    const float* qkvw = (const float*)d_in[6];
    const float* gw   = (const float*)d_in[7];
    const float* gb   = (const float*)d_in[8];
    const float* pw   = (const float*)d_in[9];
    const float* pb   = (const float*)d_in[10];
    const float* w1   = (const float*)d_in[11];
    const float* b1   = (const float*)d_in[12];
    const float* dw   = (const float*)d_in[13];
    const float* dwb  = (const float*)d_in[14];
    const float* w2   = (const float*)d_in[15];
    const float* b2   = (const float*)d_in[16];
    float* out = (float*)d_out;

    cudaFuncSetAttribute(k1_attn, cudaFuncAttributeMaxDynamicSharedMemorySize, SM1_BYTES);
    cudaFuncSetAttribute(k2_ffn1, cudaFuncAttributeMaxDynamicSharedMemorySize, SM2_BYTES);
    cudaFuncSetAttribute(k4_ffn2, cudaFuncAttributeMaxDynamicSharedMemorySize, SM4_BYTES);

    k0_prep<<<768, 256>>>(w1, w2, qkvw, pw);
    k1_attn<<<4096, 256, SM1_BYTES>>>(x, l0, n1w, n1b, gw, gb, pb, out);
    k2_ffn1<<<2048, 256, SM2_BYTES>>>(out, n2w, n2b, b1);
    k3_dw<<<131072, 256>>>(dw, dwb);
    k4_ffn2<<<2048, 256, SM4_BYTES>>>(b2, out);
}

// round 14
// speedup vs baseline: 1.8385x; 1.0233x over previous
#include <cuda_runtime.h>
#include <cuda_bf16.h>
#include <math.h>

// ---------------------------------------------------------------------------
// IGAB block, B=4, C=128, H=W=256, window 8x8, heads=8, head_dim=16, HIDDEN=512
//   k0: pre-split qkvw/pw/w1/w2 into bf16 hi/lo
//   k1: 512 thr: LN1 + QKV(MMA) + gate + attention(FFMA2, 2 heads par) + proj
//   k2: 512 thr: LN2 + W1 + GELU, cp.async W, direct store
//   k3: depthwise 3x3 + bias + GELU (4px/thread)
//   k4: 512 thr: W2 + bias + residual, cp.async X, direct store
// ---------------------------------------------------------------------------

#define HW 65536
#define NPLANE 256

__device__ float g_h1[(size_t)4 * 512 * HW];
__device__ __nv_bfloat16 g_h2h[(size_t)4 * 512 * HW];
__device__ __nv_bfloat16 g_h2l[(size_t)4 * 512 * HW];
__device__ __nv_bfloat16 g_w1h[512 * 128], g_w1l[512 * 128];
__device__ __nv_bfloat16 g_w2h[128 * 512], g_w2l[128 * 512];
__device__ __nv_bfloat16 g_qkvh[384 * 128], g_qkvl[384 * 128];
__device__ __nv_bfloat16 g_pwh[128 * 128], g_pwl[128 * 128];

typedef unsigned long long u64;
typedef unsigned int u32;
typedef __nv_bfloat16 bf16;

__device__ __forceinline__ u64 ffma2(u64 a, u64 b, u64 c) {
    u64 d;
    asm("fma.rn.f32x2 %0, %1, %2, %3;" : "=l"(d) : "l"(a), "l"(b), "l"(c));
    return d;
}
__device__ __forceinline__ float2 unpack2(u64 v) {
    unsigned lo, hi;
    asm("mov.b64 {%0, %1}, %2;" : "=r"(lo), "=r"(hi) : "l"(v));
    return make_float2(__uint_as_float(lo), __uint_as_float(hi));
}
__device__ __forceinline__ float gelu_exact(float v) {
    return 0.5f * v * (1.0f + erff(v * 0.70710678118654752f));
}
__device__ __forceinline__ void mma16816(float* c, const u32* a, u32 b0, u32 b1) {
    asm volatile(
        "mma.sync.aligned.m16n8k16.row.col.f32.bf16.bf16.f32 "
        "{%0,%1,%2,%3},{%4,%5,%6,%7},{%8,%9},{%0,%1,%2,%3};"
        : "+f"(c[0]), "+f"(c[1]), "+f"(c[2]), "+f"(c[3])
        : "r"(a[0]), "r"(a[1]), "r"(a[2]), "r"(a[3]), "r"(b0), "r"(b1));
}
__device__ __forceinline__ void ldsm4(u32& d0, u32& d1, u32& d2, u32& d3, u32 a) {
    asm volatile("ldmatrix.sync.aligned.m8n8.x4.shared.b16 {%0,%1,%2,%3},[%4];"
                 : "=r"(d0), "=r"(d1), "=r"(d2), "=r"(d3) : "r"(a));
}
__device__ __forceinline__ void ldsm4t(u32& d0, u32& d1, u32& d2, u32& d3, u32 a) {
    asm volatile("ldmatrix.sync.aligned.m8n8.x4.trans.shared.b16 {%0,%1,%2,%3},[%4];"
                 : "=r"(d0), "=r"(d1), "=r"(d2), "=r"(d3) : "r"(a));
}
__device__ __forceinline__ void split_bf16(float v, bf16& h, bf16& l) {
    h = __float2bfloat16(v);
    l = __float2bfloat16(v - __bfloat162float(h));
}
__device__ __forceinline__ void cpasync16(u32 smem_addr, const void* gptr) {
    asm volatile("cp.async.ca.shared.global [%0], [%1], 16;"
                 :: "r"(smem_addr), "l"(gptr) : "memory");
}
#define CP_COMMIT() asm volatile("cp.async.commit_group;" ::: "memory")
#define CP_WAIT0()  asm volatile("cp.async.wait_group 0;" ::: "memory")

// ======================= kernel 0: weight pre-split ========================
__global__ __launch_bounds__(256)
void k0_prep(const float* __restrict__ w1, const float* __restrict__ w2,
             const float* __restrict__ qkvw, const float* __restrict__ pw)
{
    int i = blockIdx.x * 256 + threadIdx.x;
    bf16 h, l;
    if (i < 65536) {
        split_bf16(w1[i], h, l);
        g_w1h[i] = h; g_w1l[i] = l;
    } else if (i < 131072) {
        int j = i - 65536;
        split_bf16(w2[j], h, l);
        g_w2h[j] = h; g_w2l[j] = l;
    } else if (i < 180224) {
        int j = i - 131072;
        split_bf16(qkvw[j], h, l);
        g_qkvh[j] = h; g_qkvl[j] = l;
    } else {
        int j = i - 180224;
        split_bf16(pw[j], h, l);
        g_pwh[j] = h; g_pwl[j] = l;
    }
}

// ======================= kernel 1: attention block, 512 thr ================
// smem byte layout (212224 total):
//   Af f32[128][68] @0 | Xh bf16[128][72] @34816 | Xl @53248
//   Wh bf16[64][136] @71680 (aliases Sf[2]) | Wl @89088
//   Qf f32[128][68] @106496 | Kf @141312 | Vf @176128
//   Sf[2] f32[64][68] each @71680 (+hb*17408)
//   L0 @210944 | MU @211200 | RS @211456 | DEN[128] @211712
#define SM1_BYTES 212224

__global__ __launch_bounds__(512, 1)
void k1_attn(const float* __restrict__ x, const float* __restrict__ l0,
             const float* __restrict__ n1w, const float* __restrict__ n1b,
             const float* __restrict__ gw, const float* __restrict__ gb,
             const float* __restrict__ pb, float* __restrict__ outp)
{
    extern __shared__ float sm[];
    char* smcc = (char*)sm;
    float* Af = sm;
    bf16* Xh = (bf16*)(smcc + 34816);
    bf16* Xl = (bf16*)(smcc + 53248);
    bf16* Wh = (bf16*)(smcc + 71680);
    bf16* Wl = (bf16*)(smcc + 89088);
    float* Qf = sm + 26624;
    float* Kf = sm + 35328;
    float* Vf = sm + 44032;
    float* Sf = sm + 17920;          // two buffers of 4352 floats
    float* L0v = sm + 52736;
    float* MUv = sm + 52800;
    float* RSv = sm + 52864;
    float* DENv = sm + 52928;        // 128 floats

    const int tid = threadIdx.x;
    const int wi = blockIdx.x;
    const int b  = wi >> 10;
    const int hi = (wi >> 5) & 31;
    const int wj = wi & 31;
    const int base_pix = (hi * 8) * NPLANE + wj * 8;
    const float* xb = x + (size_t)b * 128 * HW;

    #pragma unroll
    for (int it = 0; it < 16; ++it) {
        int idx = tid + it * 512;
        int c = idx >> 6, p = idx & 63;
        Af[c * 68 + p] = xb[c * HW + base_pix + (p >> 3) * NPLANE + (p & 7)];
    }
    if (tid < 64) {
        int p = tid;
        L0v[p] = l0[(size_t)b * HW + base_pix + (p >> 3) * NPLANE + (p & 7)];
    }
    __syncthreads();

    {   // LN1 stats: 8 threads/pixel
        int p = tid >> 3, part = tid & 7;
        float s = 0.f, sq = 0.f;
        #pragma unroll
        for (int c = part * 16; c < part * 16 + 16; ++c) {
            float v = Af[c * 68 + p];
            s += v; sq += v * v;
        }
        s  += __shfl_xor_sync(0xffffffffu, s, 1);
        sq += __shfl_xor_sync(0xffffffffu, sq, 1);
        s  += __shfl_xor_sync(0xffffffffu, s, 2);
        sq += __shfl_xor_sync(0xffffffffu, sq, 2);
        s  += __shfl_xor_sync(0xffffffffu, s, 4);
        sq += __shfl_xor_sync(0xffffffffu, sq, 4);
        if (part == 0) {
            float mu = s * (1.f / 128.f);
            float var = sq * (1.f / 128.f) - mu * mu;
            MUv[p] = mu;
            RSv[p] = rsqrtf(var + 1e-6f);
        }
    }
    __syncthreads();
    #pragma unroll
    for (int it = 0; it < 16; ++it) {
        int idx = tid + it * 512;
        int c = idx >> 6, p = idx & 63;
        float xn = n1w[c] * (Af[c * 68 + p] - MUv[p]) * RSv[p] + n1b[c];
        bf16 h, l;
        split_bf16(xn, h, l);
        Xh[c * 72 + p] = h;
        Xl[c * 72 + p] = l;
    }

    const int lane = tid & 31;
    const int warp = tid >> 5;              // 0..15
    const int g = lane >> 2, tg = lane & 3;
    const int mwarp = warp >> 2;            // 0..3 : 16 rows
    const int nwarp = warp & 3;             // 0..3 : 16 px cols
    const int laneW = (lane & 15) * 272 + ((lane >> 4) << 4);
    const int laneX = (lane & 15) * 144 + ((lane >> 4) << 4);

    const u32 smXh = (u32)__cvta_generic_to_shared(Xh);
    const u32 smXl = (u32)__cvta_generic_to_shared(Xl);
    const u32 smWh = (u32)__cvta_generic_to_shared(Wh);
    const u32 smWl = (u32)__cvta_generic_to_shared(Wl);

    // ---- QKV: 6 chunks, register-prefetched weights ----
    u32 wph[8], wpl[8];
    {
        const u32* wh = (const u32*)g_qkvh;
        const u32* wl = (const u32*)g_qkvl;
        #pragma unroll
        for (int it = 0; it < 8; ++it) {
            wph[it] = wh[tid + it * 512];
            wpl[it] = wl[tid + it * 512];
        }
    }

    for (int ch = 0; ch < 6; ++ch) {
        __syncthreads();
        {
            u32* dWh = (u32*)Wh;
            u32* dWl = (u32*)Wl;
            #pragma unroll
            for (int it = 0; it < 8; ++it) {
                int idx = tid + it * 512;
                int o = idx >> 6, kk = idx & 63;
                dWh[o * 68 + kk] = wph[it];
                dWl[o * 68 + kk] = wpl[it];
            }
        }
        __syncthreads();
        if (ch < 5) {
            const u32* wh = (const u32*)g_qkvh + (ch + 1) * 4096;
            const u32* wl = (const u32*)g_qkvl + (ch + 1) * 4096;
            #pragma unroll
            for (int it = 0; it < 8; ++it) {
                wph[it] = wh[tid + it * 512];
                wpl[it] = wl[tid + it * 512];
            }
        }

        float acc[2][4];
        #pragma unroll
        for (int nt = 0; nt < 2; ++nt)
            #pragma unroll
            for (int q = 0; q < 4; ++q) acc[nt][q] = 0.f;

        #pragma unroll
        for (int ks = 0; ks < 8; ++ks) {
            u32 ah[4], al[4];
            ldsm4(ah[0], ah[1], ah[2], ah[3], smWh + laneW + mwarp * 16 * 272 + ks * 32);
            ldsm4(al[0], al[1], al[2], al[3], smWl + laneW + mwarp * 16 * 272 + ks * 32);
            int n0 = nwarp * 16;
            u32 bh[4], bl[4];
            ldsm4t(bh[0], bh[1], bh[2], bh[3], smXh + laneX + ks * 16 * 144 + n0 * 2);
            ldsm4t(bl[0], bl[1], bl[2], bl[3], smXl + laneX + ks * 16 * 144 + n0 * 2);
            mma16816(acc[0], ah, bh[0], bh[1]);
            mma16816(acc[1], ah, bh[2], bh[3]);
            mma16816(acc[0], ah, bl[0], bl[1]);
            mma16816(acc[1], ah, bl[2], bl[3]);
            mma16816(acc[0], al, bh[0], bh[1]);
            mma16816(acc[1], al, bh[2], bh[3]);
        }

        float* dst = (ch < 2) ? Qf : (ch < 4) ? Kf : Vf;
        int rloc = (ch & 1) * 64 + mwarp * 16;
        int r0 = rloc + g, r1 = rloc + g + 8;
        if (ch < 2) {
            float gw0 = gw[r0], gb0 = gb[r0];
            float gw1 = gw[r1], gb1 = gb[r1];
            #pragma unroll
            for (int nt = 0; nt < 2; ++nt) {
                int col = nwarp * 16 + nt * 8 + tg * 2;
                float la = L0v[col], lb = L0v[col + 1];
                float s00 = 1.f / (1.f + __expf(-(la * gw0 + gb0)));
                float s01 = 1.f / (1.f + __expf(-(lb * gw0 + gb0)));
                float s10 = 1.f / (1.f + __expf(-(la * gw1 + gb1)));
                float s11 = 1.f / (1.f + __expf(-(lb * gw1 + gb1)));
                *(float2*)&dst[r0 * 68 + col] = make_float2(acc[nt][0] * s00, acc[nt][1] * s01);
                *(float2*)&dst[r1 * 68 + col] = make_float2(acc[nt][2] * s10, acc[nt][3] * s11);
            }
        } else {
            #pragma unroll
            for (int nt = 0; nt < 2; ++nt) {
                int col = nwarp * 16 + nt * 8 + tg * 2;
                *(float2*)&dst[r0 * 68 + col] = make_float2(acc[nt][0], acc[nt][1]);
                *(float2*)&dst[r1 * 68 + col] = make_float2(acc[nt][2], acc[nt][3]);
            }
        }
    }
    __syncthreads();

    // ---- window attention (FFMA2), 2 heads concurrent ----
    const int hb = tid >> 8;        // 0 or 1
    const int t = tid & 255;
    float* Sfh = Sf + hb * 4352;
    for (int hp = 0; hp < 4; ++hp) {
        const int cb = (2 * hp + hb) * 16;
        {
            const int tx = t & 15, ty = t >> 4;
            u64 acc2[2][4];
            #pragma unroll
            for (int i = 0; i < 2; ++i)
                #pragma unroll
                for (int j = 0; j < 4; ++j) acc2[i][j] = 0ull;
            #pragma unroll
            for (int d = 0; d < 16; ++d) {
                ulonglong2 qv = *(const ulonglong2*)&Qf[(cb + d) * 68 + 4 * tx];
                #pragma unroll
                for (int j = 0; j < 4; ++j) {
                    float kvs = Kf[(cb + d) * 68 + 4 * ty + j];
                    u64 kp;
                    asm("mov.b64 %0, {%1, %1};" : "=l"(kp) : "r"(__float_as_uint(kvs)));
                    acc2[0][j] = ffma2(qv.x, kp, acc2[0][j]);
                    acc2[1][j] = ffma2(qv.y, kp, acc2[1][j]);
                }
            }
            #pragma unroll
            for (int a = 0; a < 2; ++a)
                #pragma unroll
                for (int j = 0; j < 4; ++j) {
                    float2 f = unpack2(acc2[a][j]);
                    Sfh[(4 * tx + 2 * a) * 68 + 4 * ty + j] = f.x * 0.25f;
                    Sfh[(4 * tx + 2 * a + 1) * 68 + 4 * ty + j] = f.y * 0.25f;
                }
        }
        __syncthreads();
        {
            int r = t >> 2, part = t & 3;
            float m = -1e30f;
            #pragma unroll
            for (int kk = part * 16; kk < part * 16 + 16; ++kk)
                m = fmaxf(m, Sfh[r * 68 + kk]);
            m = fmaxf(m, __shfl_xor_sync(0xffffffffu, m, 1));
            m = fmaxf(m, __shfl_xor_sync(0xffffffffu, m, 2));
            float s = 0.f;
            #pragma unroll
            for (int kk = part * 16; kk < part * 16 + 16; ++kk) {
                float e = __expf(Sfh[r * 68 + kk] - m);
                Sfh[r * 68 + kk] = e;
                s += e;
            }
            s += __shfl_xor_sync(0xffffffffu, s, 1);
            s += __shfl_xor_sync(0xffffffffu, s, 2);
            if (part == 0) DENv[hb * 64 + r] = 1.f / s;
        }
        __syncthreads();
        {
            int pq = t >> 2, dg = t & 3;
            const u64* Srow = (const u64*)&Sfh[pq * 68];
            const u64* V0 = (const u64*)&Vf[(cb + 4 * dg + 0) * 68];
            const u64* V1 = (const u64*)&Vf[(cb + 4 * dg + 1) * 68];
            const u64* V2 = (const u64*)&Vf[(cb + 4 * dg + 2) * 68];
            const u64* V3 = (const u64*)&Vf[(cb + 4 * dg + 3) * 68];
            u64 a0 = 0ull, a1 = 0ull, a2 = 0ull, a3 = 0ull;
            #pragma unroll 8
            for (int kk = 0; kk < 32; ++kk) {
                u64 prp = Srow[kk];
                a0 = ffma2(prp, V0[kk], a0);
                a1 = ffma2(prp, V1[kk], a1);
                a2 = ffma2(prp, V2[kk], a2);
                a3 = ffma2(prp, V3[kk], a3);
            }
            float dn = DENv[hb * 64 + pq];
            float2 f0 = unpack2(a0), f1 = unpack2(a1), f2 = unpack2(a2), f3 = unpack2(a3);
            bf16 h_, l_;
            split_bf16((f0.x + f0.y) * dn, h_, l_);
            Xh[(cb + 4 * dg + 0) * 72 + pq] = h_; Xl[(cb + 4 * dg + 0) * 72 + pq] = l_;
            split_bf16((f1.x + f1.y) * dn, h_, l_);
            Xh[(cb + 4 * dg + 1) * 72 + pq] = h_; Xl[(cb + 4 * dg + 1) * 72 + pq] = l_;
            split_bf16((f2.x + f2.y) * dn, h_, l_);
            Xh[(cb + 4 * dg + 2) * 72 + pq] = h_; Xl[(cb + 4 * dg + 2) * 72 + pq] = l_;
            split_bf16((f3.x + f3.y) * dn, h_, l_);
            Xh[(cb + 4 * dg + 3) * 72 + pq] = h_; Xl[(cb + 4 * dg + 3) * 72 + pq] = l_;
        }
        __syncthreads();
    }

    // ---- proj (MMA) + bias + residual, direct store ----
    {
        const u32* wh = (const u32*)g_pwh;
        const u32* wl = (const u32*)g_pwl;
        #pragma unroll
        for (int it = 0; it < 8; ++it) {
            wph[it] = wh[tid + it * 512];
            wpl[it] = wl[tid + it * 512];
        }
    }
    for (int ch = 0; ch < 2; ++ch) {
        __syncthreads();
        {
            u32* dWh = (u32*)Wh;
            u32* dWl = (u32*)Wl;
            #pragma unroll
            for (int it = 0; it < 8; ++it) {
                int idx = tid + it * 512;
                int o = idx >> 6, kk = idx & 63;
                dWh[o * 68 + kk] = wph[it];
                dWl[o * 68 + kk] = wpl[it];
            }
        }
        __syncthreads();
        if (ch == 0) {
            const u32* wh = (const u32*)g_pwh + 4096;
            const u32* wl = (const u32*)g_pwl + 4096;
            #pragma unroll
            for (int it = 0; it < 8; ++it) {
                wph[it] = wh[tid + it * 512];
                wpl[it] = wl[tid + it * 512];
            }
        }

        float acc[2][4];
        #pragma unroll
        for (int nt = 0; nt < 2; ++nt)
            #pragma unroll
            for (int q = 0; q < 4; ++q) acc[nt][q] = 0.f;

        #pragma unroll
        for (int ks = 0; ks < 8; ++ks) {
            u32 ah[4], al[4];
            ldsm4(ah[0], ah[1], ah[2], ah[3], smWh + laneW + mwarp * 16 * 272 + ks * 32);
            ldsm4(al[0], al[1], al[2], al[3], smWl + laneW + mwarp * 16 * 272 + ks * 32);
            int n0 = nwarp * 16;
            u32 bh[4], bl[4];
            ldsm4t(bh[0], bh[1], bh[2], bh[3], smXh + laneX + ks * 16 * 144 + n0 * 2);
            ldsm4t(bl[0], bl[1], bl[2], bl[3], smXl + laneX + ks * 16 * 144 + n0 * 2);
            mma16816(acc[0], ah, bh[0], bh[1]);
            mma16816(acc[1], ah, bh[2], bh[3]);
            mma16816(acc[0], ah, bl[0], bl[1]);
            mma16816(acc[1], ah, bl[2], bl[3]);
            mma16816(acc[0], al, bh[0], bh[1]);
            mma16816(acc[1], al, bh[2], bh[3]);
        }

        int r0 = mwarp * 16 + g, r1 = r0 + 8;
        int o0 = ch * 64 + r0, o1 = ch * 64 + r1;
        float pb0 = pb[o0], pb1 = pb[o1];
        float* op0 = outp + (size_t)(b * 128 + o0) * HW + base_pix;
        float* op1 = outp + (size_t)(b * 128 + o1) * HW + base_pix;
        #pragma unroll
        for (int nt = 0; nt < 2; ++nt) {
            int col = nwarp * 16 + nt * 8 + tg * 2;
            int goff = ((col >> 3) * NPLANE) + (col & 7);
            float2 v0 = make_float2(acc[nt][0] + pb0 + Af[o0 * 68 + col],
                                    acc[nt][1] + pb0 + Af[o0 * 68 + col + 1]);
            float2 v1 = make_float2(acc[nt][2] + pb1 + Af[o1 * 68 + col],
                                    acc[nt][3] + pb1 + Af[o1 * 68 + col + 1]);
            *(float2*)&op0[goff] = v0;
            *(float2*)&op1[goff] = v1;
        }
    }
}

// ======================= kernel 2: LN2 + W1 + GELU, 512 thr ================
// smem: Xh@0 Xl@34816 | W0h@69632 W0l@104448 | W1h@139264 W1l@174080
//       Xf f32[128][132] aliases @69632 ; MU@208896 RS@209408
#define SM2_BYTES 209920

__global__ __launch_bounds__(512, 1)
void k2_ffn1(const float* __restrict__ inp, const float* __restrict__ n2w,
             const float* __restrict__ n2b, const float* __restrict__ b1)
{
    extern __shared__ char smc[];
    bf16* Xh = (bf16*)smc;
    bf16* Xl = (bf16*)(smc + 34816);
    float* Xf = (float*)(smc + 69632);
    float* MU = (float*)(smc + 208896);
    float* RS = (float*)(smc + 209408);
    const u32 smbase = (u32)__cvta_generic_to_shared(smc);
    const u32 smW[2] = {smbase + 69632, smbase + 139264};

    const int tid = threadIdx.x;
    const int pg = blockIdx.x * 128;
    const int b = pg >> 16;
    const int pix = pg & 65535;
    const float* ib = inp + (size_t)b * 128 * HW + pix;

    #pragma unroll
    for (int it = 0; it < 32; ++it) {
        int idx = tid + it * 512;
        int c = idx >> 7, p = idx & 127;
        Xf[c * 132 + p] = ib[c * HW + p];
    }
    __syncthreads();
    {   // LN stats: 4 threads/pixel
        int p = tid >> 2, part = tid & 3;
        float s = 0.f, sq = 0.f;
        #pragma unroll
        for (int c = part * 32; c < part * 32 + 32; ++c) {
            float v = Xf[c * 132 + p];
            s += v; sq += v * v;
        }
        s  += __shfl_xor_sync(0xffffffffu, s, 1);
        sq += __shfl_xor_sync(0xffffffffu, sq, 1);
        s  += __shfl_xor_sync(0xffffffffu, s, 2);
        sq += __shfl_xor_sync(0xffffffffu, sq, 2);
        if (part == 0) {
            float mu = s * (1.f / 128.f);
            float var = sq * (1.f / 128.f) - mu * mu;
            MU[p] = mu;
            RS[p] = rsqrtf(var + 1e-6f);
        }
    }
    __syncthreads();
    #pragma unroll
    for (int it = 0; it < 32; ++it) {
        int idx = tid + it * 512;
        int c = idx >> 7, p = idx & 127;
        float xn = n2w[c] * (Xf[c * 132 + p] - MU[p]) * RS[p] + n2b[c];
        bf16 h, l;
        split_bf16(xn, h, l);
        Xh[c * 136 + p] = h;
        Xl[c * 136 + p] = l;
    }
    __syncthreads();

    const int c16 = tid & 15;
    const int orow = tid >> 4;          // 0..31
    {
        const char* srcH = (const char*)g_w1h;
        const char* srcL = (const char*)g_w1l;
        #pragma unroll
        for (int it = 0; it < 4; ++it) {
            int o = orow + it * 32;
            cpasync16(smW[0] + o * 272 + c16 * 16, srcH + o * 256 + c16 * 16);
            cpasync16(smW[0] + 34816 + o * 272 + c16 * 16, srcL + o * 256 + c16 * 16);
        }
        CP_COMMIT();
    }

    const int lane = tid & 31;
    const int warp = tid >> 5;           // 0..15
    const int g = lane >> 2, tg = lane & 3;
    const int mbase = (warp >> 2) * 32;
    const int nbase = (warp & 3) * 32;
    const int laneoff = (lane & 15) * 272 + ((lane >> 4) << 4);
    const u32 smXh = smbase;
    const u32 smXl = smbase + 34816;

    for (int och = 0; och < 4; ++och) {
        CP_WAIT0();
        __syncthreads();
        if (och < 3) {
            const char* srcH = (const char*)g_w1h + (size_t)(och + 1) * 128 * 256;
            const char* srcL = (const char*)g_w1l + (size_t)(och + 1) * 128 * 256;
            u32 dstW = smW[(och + 1) & 1];
            #pragma unroll
            for (int it = 0; it < 4; ++it) {
                int o = orow + it * 32;
                cpasync16(dstW + o * 272 + c16 * 16, srcH + o * 256 + c16 * 16);
                cpasync16(dstW + 34816 + o * 272 + c16 * 16, srcL + o * 256 + c16 * 16);
            }
            CP_COMMIT();
        }
        const u32 smWh = smW[och & 1];
        const u32 smWl = smWh + 34816;

        float acc[2][4][4];
        #pragma unroll
        for (int mt = 0; mt < 2; ++mt)
            #pragma unroll
            for (int nt = 0; nt < 4; ++nt)
                #pragma unroll
                for (int q = 0; q < 4; ++q) acc[mt][nt][q] = 0.f;

        #pragma unroll
        for (int ks = 0; ks < 8; ++ks) {
            u32 ah[2][4], al[2][4];
            ldsm4(ah[0][0], ah[0][1], ah[0][2], ah[0][3],
                  smWh + laneoff + mbase * 272 + ks * 32);
            ldsm4(ah[1][0], ah[1][1], ah[1][2], ah[1][3],
                  smWh + laneoff + (mbase + 16) * 272 + ks * 32);
            ldsm4(al[0][0], al[0][1], al[0][2], al[0][3],
                  smWl + laneoff + mbase * 272 + ks * 32);
            ldsm4(al[1][0], al[1][1], al[1][2], al[1][3],
                  smWl + laneoff + (mbase + 16) * 272 + ks * 32);
            #pragma unroll
            for (int ntp = 0; ntp < 2; ++ntp) {
                int n0 = nbase + ntp * 16;
                u32 bh[4], bl[4];
                ldsm4t(bh[0], bh[1], bh[2], bh[3],
                       smXh + laneoff + ks * 16 * 272 + n0 * 2);
                ldsm4t(bl[0], bl[1], bl[2], bl[3],
                       smXl + laneoff + ks * 16 * 272 + n0 * 2);
                #pragma unroll
                for (int mt = 0; mt < 2; ++mt) {
                    mma16816(acc[mt][2 * ntp],     ah[mt], bh[0], bh[1]);
                    mma16816(acc[mt][2 * ntp + 1], ah[mt], bh[2], bh[3]);
                    mma16816(acc[mt][2 * ntp],     ah[mt], bl[0], bl[1]);
                    mma16816(acc[mt][2 * ntp + 1], ah[mt], bl[2], bl[3]);
                    mma16816(acc[mt][2 * ntp],     al[mt], bh[0], bh[1]);
                    mma16816(acc[mt][2 * ntp + 1], al[mt], bh[2], bh[3]);
                }
            }
        }

        #pragma unroll
        for (int mt = 0; mt < 2; ++mt) {
            int r = mbase + mt * 16 + g;
            int o0 = och * 128 + r, o1 = o0 + 8;
            float bv0 = b1[o0], bv1 = b1[o1];
            float* p0 = &g_h1[(size_t)(b * 512 + o0) * HW + pix];
            float* p1 = &g_h1[(size_t)(b * 512 + o1) * HW + pix];
            #pragma unroll
            for (int nt = 0; nt < 4; ++nt) {
                int col = nbase + nt * 8 + tg * 2;
                float2 v0 = make_float2(gelu_exact(acc[mt][nt][0] + bv0),
                                        gelu_exact(acc[mt][nt][1] + bv0));
                float2 v1 = make_float2(gelu_exact(acc[mt][nt][2] + bv1),
                                        gelu_exact(acc[mt][nt][3] + bv1));
                *(float2*)&p0[col] = v0;
                *(float2*)&p1[col] = v1;
            }
        }
    }
}

// ======================= kernel 3: dw3x3 + GELU ============================
__global__ __launch_bounds__(256)
void k3_dw(const float* __restrict__ dw, const float* __restrict__ dwb)
{
    const int blk = blockIdx.x;
    const int plane = blk >> 6;
    const int ch = plane & 511;
    const int rg = blk & 63;
    const int tid = threadIdx.x;
    const int y = rg * 4 + (tid >> 6);
    const int xc = (tid & 63) * 4;
    const float* ip = g_h1 + (size_t)plane * HW;

    float w[9];
    #pragma unroll
    for (int i = 0; i < 9; ++i) w[i] = dw[ch * 9 + i];
    const float bias = dwb[ch];

    float v[3][6];
    #pragma unroll
    for (int dy = 0; dy < 3; ++dy) {
        int yy = y + dy - 1;
        if (yy >= 0 && yy < 256) {
            const float* row = ip + yy * NPLANE + xc;
            float4 m = *(const float4*)row;
            v[dy][1] = m.x; v[dy][2] = m.y; v[dy][3] = m.z; v[dy][4] = m.w;
            v[dy][0] = (xc > 0) ? row[-1] : 0.f;
            v[dy][5] = (xc < 252) ? row[4] : 0.f;
        } else {
            #pragma unroll
            for (int i = 0; i < 6; ++i) v[dy][i] = 0.f;
        }
    }

    bf16 hh[4], ll[4];
    #pragma unroll
    for (int p = 0; p < 4; ++p) {
        float s = bias;
        #pragma unroll
        for (int dy = 0; dy < 3; ++dy)
            s += w[dy * 3 + 0] * v[dy][p] + w[dy * 3 + 1] * v[dy][p + 1]
               + w[dy * 3 + 2] * v[dy][p + 2];
        float r = gelu_exact(s);
        split_bf16(r, hh[p], ll[p]);
    }

    uint2 ph, pl;
    ph.x = (u32)__bfloat16_as_ushort(hh[0]) | ((u32)__bfloat16_as_ushort(hh[1]) << 16);
    ph.y = (u32)__bfloat16_as_ushort(hh[2]) | ((u32)__bfloat16_as_ushort(hh[3]) << 16);
    pl.x = (u32)__bfloat16_as_ushort(ll[0]) | ((u32)__bfloat16_as_ushort(ll[1]) << 16);
    pl.y = (u32)__bfloat16_as_ushort(ll[2]) | ((u32)__bfloat16_as_ushort(ll[3]) << 16);
    size_t off = (size_t)plane * HW + y * NPLANE + xc;
    *(uint2*)&g_h2h[off] = ph;
    *(uint2*)&g_h2l[off] = pl;
}

// ======================= kernel 4: W2 + residual, 512 thr ==================
// smem: X0h@0 X0l@34816 | X1h@69632 X1l@104448 | Wh@139264 Wl@174080
#define SM4_BYTES 208896

__global__ __launch_bounds__(512, 1)
void k4_ffn2(const float* __restrict__ b2, float* __restrict__ io)
{
    extern __shared__ char smc[];
    const u32 smbase = (u32)__cvta_generic_to_shared(smc);
    const u32 smX[2] = {smbase, smbase + 69632};
    const u32 smWh = smbase + 139264;
    const u32 smWl = smbase + 174080;

    const int tid = threadIdx.x;
    const int pg = blockIdx.x * 128;
    const int b = pg >> 16;
    const int pix = pg & 65535;

    const int c16 = tid & 15;
    const int xrow = tid >> 4;          // 0..31

    auto copyX = [&](int kc, int sel) {
        const char* srcH = (const char*)g_h2h +
            ((size_t)(b * 512 + kc * 128)) * (HW * 2) + (size_t)pix * 2;
        const char* srcL = (const char*)g_h2l +
            ((size_t)(b * 512 + kc * 128)) * (HW * 2) + (size_t)pix * 2;
        u32 dst = smX[sel];
        #pragma unroll
        for (int it = 0; it < 4; ++it) {
            int k = xrow + it * 32;
            cpasync16(dst + k * 272 + c16 * 16,
                      srcH + (size_t)k * (HW * 2) + c16 * 16);
            cpasync16(dst + 34816 + k * 272 + c16 * 16,
                      srcL + (size_t)k * (HW * 2) + c16 * 16);
        }
        CP_COMMIT();
    };

    copyX(0, 0);

    const int lane = tid & 31;
    const int warp = tid >> 5;           // 0..15
    const int g = lane >> 2, tg = lane & 3;
    const int mbase = (warp >> 2) * 32;
    const int nbase = (warp & 3) * 32;
    const int laneoff = (lane & 15) * 272 + ((lane >> 4) << 4);

    float acc[2][4][4];
    #pragma unroll
    for (int mt = 0; mt < 2; ++mt)
        #pragma unroll
        for (int nt = 0; nt < 4; ++nt)
            #pragma unroll
            for (int q = 0; q < 4; ++q) acc[mt][nt][q] = 0.f;

    for (int kc = 0; kc < 4; ++kc) {
        CP_WAIT0();
        __syncthreads();
        if (kc < 3) copyX(kc + 1, (kc + 1) & 1);
        {
            const u32* wh = (const u32*)&g_w2h[kc * 128];
            const u32* wl = (const u32*)&g_w2l[kc * 128];
            u32* dWh = (u32*)(smc + 139264);
            u32* dWl = (u32*)(smc + 174080);
            #pragma unroll
            for (int it = 0; it < 16; ++it) {
                int idx = tid + it * 512;
                int o = idx >> 6, kk = idx & 63;
                dWh[o * 68 + kk] = wh[o * 256 + kk];
                dWl[o * 68 + kk] = wl[o * 256 + kk];
            }
        }
        __syncthreads();

        const u32 smXh = smX[kc & 1];
        const u32 smXl = smXh + 34816;

        #pragma unroll
        for (int ks = 0; ks < 8; ++ks) {
            u32 ah[2][4], al[2][4];
            ldsm4(ah[0][0], ah[0][1], ah[0][2], ah[0][3],
                  smWh + laneoff + mbase * 272 + ks * 32);
            ldsm4(ah[1][0], ah[1][1], ah[1][2], ah[1][3],
                  smWh + laneoff + (mbase + 16) * 272 + ks * 32);
            ldsm4(al[0][0], al[0][1], al[0][2], al[0][3],
                  smWl + laneoff + mbase * 272 + ks * 32);
            ldsm4(al[1][0], al[1][1], al[1][2], al[1][3],
                  smWl + laneoff + (mbase + 16) * 272 + ks * 32);
            #pragma unroll
            for (int ntp = 0; ntp < 2; ++ntp) {
                int n0 = nbase + ntp * 16;
                u32 bh[4], bl[4];
                ldsm4t(bh[0], bh[1], bh[2], bh[3],
                       smXh + laneoff + ks * 16 * 272 + n0 * 2);
                ldsm4t(bl[0], bl[1], bl[2], bl[3],
                       smXl + laneoff + ks * 16 * 272 + n0 * 2);
                #pragma unroll
                for (int mt = 0; mt < 2; ++mt) {
                    mma16816(acc[mt][2 * ntp],     ah[mt], bh[0], bh[1]);
                    mma16816(acc[mt][2 * ntp + 1], ah[mt], bh[2], bh[3]);
                    mma16816(acc[mt][2 * ntp],     ah[mt], bl[0], bl[1]);
                    mma16816(acc[mt][2 * ntp + 1], ah[mt], bl[2], bl[3]);
                    mma16816(acc[mt][2 * ntp],     al[mt], bh[0], bh[1]);
                    mma16816(acc[mt][2 * ntp + 1], al[mt], bh[2], bh[3]);
                }
            }
        }
    }

    #pragma unroll
    for (int mt = 0; mt < 2; ++mt) {
        int r = mbase + mt * 16 + g;
        int o0 = r, o1 = r + 8;
        float bv0 = b2[o0], bv1 = b2[o1];
        float* p0 = &io[(size_t)(b * 128 + o0) * HW + pix];
        float* p1 = &io[(size_t)(b * 128 + o1) * HW + pix];
        #pragma unroll
        for (int nt = 0; nt < 4; ++nt) {
            int col = nbase + nt * 8 + tg * 2;
            float2 v0 = *(float2*)&p0[col];
            float2 v1 = *(float2*)&p1[col];
            v0.x += acc[mt][nt][0] + bv0;
            v0.y += acc[mt][nt][1] + bv0;
            v1.x += acc[mt][nt][2] + bv1;
            v1.y += acc[mt][nt][3] + bv1;
            *(float2*)&p0[col] = v0;
            *(float2*)&p1[col] = v1;
        }
    }
}

// ---------------------------------------------------------------------------
extern "C" void kernel_launch(void* const* d_in, const int* in_sizes, int n_in,
                              void* d_out, int out_size)
{
    const float* x    = (const float*)d_in[0];
    const float* l0   = (const float*)d_in[1];
    const float* n1w  = (const float*)d_in[2];
    const float* n1b  = (const float*)d_in[3];
    const float* n2w  = (const float*)d_in[4];
    const float* n2b  = (const float*)d_in[5];
    const float* qkvw = (const float*)d_in[6];
    const float* gw   = (const float*)d_in[7];
    const float* gb   = (const float*)d_in[8];
    const float* pw   = (const float*)d_in[9];
    const float* pb   = (const float*)d_in[10];
    const float* w1   = (const float*)d_in[11];
    const float* b1   = (const float*)d_in[12];
    const float* dw   = (const float*)d_in[13];
    const float* dwb  = (const float*)d_in[14];
    const float* w2   = (const float*)d_in[15];
    const float* b2   = (const float*)d_in[16];
    float* out = (float*)d_out;

    cudaFuncSetAttribute(k1_attn, cudaFuncAttributeMaxDynamicSharedMemorySize, SM1_BYTES);
    cudaFuncSetAttribute(k2_ffn1, cudaFuncAttributeMaxDynamicSharedMemorySize, SM2_BYTES);
    cudaFuncSetAttribute(k4_ffn2, cudaFuncAttributeMaxDynamicSharedMemorySize, SM4_BYTES);

    k0_prep<<<768, 256>>>(w1, w2, qkvw, pw);
    k1_attn<<<4096, 512, SM1_BYTES>>>(x, l0, n1w, n1b, gw, gb, pb, out);
    k2_ffn1<<<2048, 512, SM2_BYTES>>>(out, n2w, n2b, b1);
    k3_dw<<<131072, 256>>>(dw, dwb);
    k4_ffn2<<<2048, 512, SM4_BYTES>>>(b2, out);
}